// round 1
// baseline (speedup 1.0000x reference)
#include <cuda_runtime.h>
#include <math.h>

#define BB 4
#define SS 4096
#define DD 2048
#define HH 16
#define HDIM 128
#define NKEYS 128   // 8 tiles * 16

// ---------------- scratch (static device arrays: allocation-free) ----------------
__device__ float g_q  [(size_t)BB * SS * DD];        // Q projection, (b,s,h,hd)
__device__ float g_att[(size_t)BB * SS * DD];        // attention out, (b,s,h,hd)
__device__ float g_ksp[64 * NKEYS * HDIM];           // gathered K per (b,h)
__device__ float g_vsp[64 * NKEYS * HDIM];           // gathered V per (b,h)

// ---------------- sparse K/V projection ----------------
// Only project x at the 128 gathered tokens per (b,h), for head h's 128-col
// slice of Wk/Wv. grid = (64 bh, 2 {K,V}), 256 threads, 8x8 per thread.
__global__ __launch_bounds__(256, 2) void sparse_kv_kernel(
    const float* __restrict__ x, const int* __restrict__ anchors,
    const float* __restrict__ Wk, const float* __restrict__ Wv)
{
    int bh = blockIdx.x;
    int b = bh >> 4, h = bh & 15;
    const float* W = blockIdx.y ? Wv : Wk;
    float* out     = blockIdx.y ? g_vsp : g_ksp;

    __shared__ int   tok[128];
    __shared__ float xs[128][17];   // padded vs 32-bank conflicts
    __shared__ float ws[16][128];

    int tid = threadIdx.x;
    if (tid < 128) {
        int ti = tid >> 4;
        int tile = (ti == 7) ? 255 : anchors[(bh << 3) + ti];  // last slot -> current tile
        tok[tid] = tile * 16 + (tid & 15);
    }
    __syncthreads();

    int tx = tid & 15, ty = tid >> 4;
    float acc[8][8];
#pragma unroll
    for (int i = 0; i < 8; i++)
#pragma unroll
        for (int j = 0; j < 8; j++) acc[i][j] = 0.f;

    for (int kt = 0; kt < DD; kt += 16) {
#pragma unroll
        for (int t = 0; t < 8; t++) {
            int j = t * 256 + tid;
            int row = j >> 4, kk = j & 15;
            xs[row][kk] = x[((size_t)b * SS + tok[row]) * DD + kt + kk];
        }
#pragma unroll
        for (int t = 0; t < 8; t++) {
            int j = t * 256 + tid;
            int kk = j >> 7, col = j & 127;
            ws[kk][col] = W[(size_t)(kt + kk) * DD + h * HDIM + col];
        }
        __syncthreads();
#pragma unroll
        for (int kk = 0; kk < 16; kk++) {
            float av[8], bv[8];
#pragma unroll
            for (int i = 0; i < 4; i++) {
                av[i]     = xs[ty * 4 + i][kk];
                av[4 + i] = xs[64 + ty * 4 + i][kk];
                bv[i]     = ws[kk][tx * 4 + i];
                bv[4 + i] = ws[kk][64 + tx * 4 + i];
            }
#pragma unroll
            for (int i = 0; i < 8; i++)
#pragma unroll
                for (int j = 0; j < 8; j++) acc[i][j] += av[i] * bv[j];
        }
        __syncthreads();
    }

#pragma unroll
    for (int i = 0; i < 8; i++) {
        int m = (i < 4) ? (ty * 4 + i) : (64 + ty * 4 + (i - 4));
        size_t base = (size_t)bh * NKEYS * HDIM + (size_t)m * HDIM;
#pragma unroll
        for (int j = 0; j < 4; j++) {
            out[base + tx * 4 + j]      = acc[i][j];
            out[base + 64 + tx * 4 + j] = acc[i][4 + j];
        }
    }
}

// ---------------- SGEMM: C[M,2048] = A[M,2048] @ B[2048,2048] ----------------
// 128x128 tile, BK=8, 256 threads, 8x8/thread (4+64 split), float4 everywhere.
__global__ __launch_bounds__(256, 2) void sgemm_2048(
    const float* __restrict__ A, const float* __restrict__ B, float* __restrict__ C)
{
    const int K = 2048, N = 2048;
    __shared__ float As[8][128];
    __shared__ float Bs[8][128];

    int tid = threadIdx.x;
    int m0 = blockIdx.y * 128;
    int n0 = blockIdx.x * 128;
    int tx = tid & 15, ty = tid >> 4;

    int arow = tid >> 1;          // 0..127
    int acol = (tid & 1) * 4;     // 0 or 4
    int brow = tid >> 5;          // 0..7
    int bcol = (tid & 31) * 4;    // 0..124

    const float* Aptr = A + (size_t)(m0 + arow) * K + acol;
    const float* Bptr = B + (size_t)brow * N + n0 + bcol;

    float acc[8][8];
#pragma unroll
    for (int i = 0; i < 8; i++)
#pragma unroll
        for (int j = 0; j < 8; j++) acc[i][j] = 0.f;

    for (int kt = 0; kt < K; kt += 8) {
        float4 a4 = *(const float4*)(Aptr + kt);
        float4 b4 = *(const float4*)(Bptr + (size_t)kt * N);
        As[acol + 0][arow] = a4.x;
        As[acol + 1][arow] = a4.y;
        As[acol + 2][arow] = a4.z;
        As[acol + 3][arow] = a4.w;
        *(float4*)&Bs[brow][bcol] = b4;
        __syncthreads();
#pragma unroll
        for (int k = 0; k < 8; k++) {
            float4 a0 = *(const float4*)&As[k][ty * 4];
            float4 a1 = *(const float4*)&As[k][64 + ty * 4];
            float4 b0 = *(const float4*)&Bs[k][tx * 4];
            float4 b1 = *(const float4*)&Bs[k][64 + tx * 4];
            float av[8] = {a0.x, a0.y, a0.z, a0.w, a1.x, a1.y, a1.z, a1.w};
            float bv[8] = {b0.x, b0.y, b0.z, b0.w, b1.x, b1.y, b1.z, b1.w};
#pragma unroll
            for (int i = 0; i < 8; i++)
#pragma unroll
                for (int j = 0; j < 8; j++) acc[i][j] += av[i] * bv[j];
        }
        __syncthreads();
    }

#pragma unroll
    for (int i = 0; i < 8; i++) {
        int m = (i < 4) ? (m0 + ty * 4 + i) : (m0 + 64 + ty * 4 + (i - 4));
        float4 c0 = make_float4(acc[i][0], acc[i][1], acc[i][2], acc[i][3]);
        float4 c1 = make_float4(acc[i][4], acc[i][5], acc[i][6], acc[i][7]);
        *(float4*)&C[(size_t)m * N + n0 + tx * 4]      = c0;
        *(float4*)&C[(size_t)m * N + n0 + 64 + tx * 4] = c1;
    }
}

// ---------------- attention over 128 gathered keys ----------------
// grid = (32 query-chunks of 128, 64 bh). 512 threads: 4 queries in flight,
// thread = (qsub 0..3, key/d 0..127). K stored transposed (pad 129) in smem.
__global__ __launch_bounds__(512, 1) void attn_kernel(
    const int* __restrict__ anchors, float* __restrict__ attout)
{
    extern __shared__ float sm[];
    float* Kst  = sm;                    // 128*129 (Kst[d*129 + k])
    float* Vs   = Kst + 128 * 129;       // 128*128 (Vs[k*128 + d])
    float* qs   = Vs + 128 * 128;        // 4*128
    float* wsb  = qs + 512;              // 4*128
    float* redm = wsb + 512;             // 16
    float* reds = redm + 16;             // 16
    int*   tok  = (int*)(reds + 16);     // 128

    int tid = threadIdx.x;
    int bh = blockIdx.y;
    int b = bh >> 4, h = bh & 15;
    int q0 = blockIdx.x * 128;

    if (tid < 128) {
        int ti = tid >> 4;
        int tile = (ti == 7) ? 255 : anchors[(bh << 3) + ti];
        tok[tid] = tile * 16 + (tid & 15);
    }
    for (int i = tid; i < 128 * 128; i += 512) {
        int k = i >> 7, d = i & 127;
        Kst[d * 129 + k] = g_ksp[(size_t)bh * 16384 + i];
        Vs[i]            = g_vsp[(size_t)bh * 16384 + i];
    }
    __syncthreads();

    int qsub = tid >> 7;             // 0..3
    int lane = tid & 31;
    int key  = tid & 127;            // doubles as output dim d
    int wIn  = (tid & 127) >> 5;     // warp index within 128-thread group

    const float scale = 0.0883883476483184f;  // 1/sqrt(128)

    for (int it = 0; it < 32; it++) {
        int qpos = q0 + it * 4 + qsub;
        qs[qsub * 128 + key] = g_q[((size_t)b * SS + qpos) * DD + h * HDIM + key];
        __syncthreads();

        // logits: q . K[key]
        float accv = 0.f;
#pragma unroll
        for (int d = 0; d < 128; d++)
            accv += qs[qsub * 128 + d] * Kst[d * 129 + key];
        float logit = accv * scale;
        if (tok[key] > qpos) logit = -1e10f;   // causal mask on gathered positions

        // softmax over the 128 keys (4 warps per query)
        float m = logit;
#pragma unroll
        for (int o = 16; o > 0; o >>= 1) m = fmaxf(m, __shfl_xor_sync(0xffffffffu, m, o));
        if (lane == 0) redm[qsub * 4 + wIn] = m;
        __syncthreads();
        float M = fmaxf(fmaxf(redm[qsub * 4 + 0], redm[qsub * 4 + 1]),
                        fmaxf(redm[qsub * 4 + 2], redm[qsub * 4 + 3]));
        float p = __expf(logit - M);
        float s = p;
#pragma unroll
        for (int o = 16; o > 0; o >>= 1) s += __shfl_xor_sync(0xffffffffu, s, o);
        if (lane == 0) reds[qsub * 4 + wIn] = s;
        __syncthreads();
        float S = reds[qsub * 4 + 0] + reds[qsub * 4 + 1] +
                  reds[qsub * 4 + 2] + reds[qsub * 4 + 3];
        wsb[qsub * 128 + key] = p / S;
        __syncthreads();

        // out[d] = sum_k w_k * V[k][d]  (thread's key index now acts as d)
        float o = 0.f;
#pragma unroll
        for (int k = 0; k < 128; k++)
            o += wsb[qsub * 128 + k] * Vs[k * 128 + key];
        attout[((size_t)b * SS + qpos) * DD + h * HDIM + key] = o;
    }
}

// ---------------- launch ----------------
extern "C" void kernel_launch(void* const* d_in, const int* in_sizes, int n_in,
                              void* d_out, int out_size)
{
    const float* x       = (const float*)d_in[0];
    const int*   anchors = (const int*)  d_in[1];
    const float* Wq      = (const float*)d_in[2];
    const float* Wk      = (const float*)d_in[3];
    const float* Wv      = (const float*)d_in[4];
    const float* Wo      = (const float*)d_in[5];
    float* out = (float*)d_out;

    float *qp, *attp;
    cudaGetSymbolAddress((void**)&qp,   g_q);
    cudaGetSymbolAddress((void**)&attp, g_att);

    const int attn_smem = (128 * 129 + 128 * 128 + 512 + 512 + 32) * 4 + 128 * 4;
    cudaFuncSetAttribute(attn_kernel, cudaFuncAttributeMaxDynamicSharedMemorySize, attn_smem);

    sparse_kv_kernel<<<dim3(64, 2), 256>>>(x, anchors, Wk, Wv);
    sgemm_2048<<<dim3(16, 128), 256>>>(x, Wq, qp);
    attn_kernel<<<dim3(32, 64), 512, attn_smem>>>(anchors, attp);
    sgemm_2048<<<dim3(16, 128), 256>>>(attp, Wo, out);
}

// round 4
// speedup vs baseline: 1.8067x; 1.8067x over previous
#include <cuda_runtime.h>
#include <cstdint>
#include <math.h>

#define BB 4
#define SS 4096
#define DD 2048
#define HH 16
#define HDIM 128
#define NKEYS 128

// ---------------- scratch ----------------
__device__ float g_q  [(size_t)BB * SS * DD];
__device__ float g_att[(size_t)BB * SS * DD];
__device__ float g_xr [(size_t)BB * SS * DD];
__device__ float g_wqt[2048 * 2048];
__device__ float g_wot[2048 * 2048];
__device__ float g_ksp[64 * NKEYS * HDIM];
__device__ float g_vsp[64 * NKEYS * HDIM];

// ---------------- helpers ----------------
__device__ __forceinline__ uint32_t smem_u32(const void* p) {
    uint32_t a;
    asm("{ .reg .u64 t; cvta.to.shared.u64 t, %1; cvt.u32.u64 %0, t; }" : "=r"(a) : "l"(p));
    return a;
}
__device__ __forceinline__ float tf32r(float x) {
    uint32_t u;
    asm("cvt.rna.tf32.f32 %0, %1;" : "=r"(u) : "f"(x));
    return __uint_as_float(u);
}
#define CP_ASYNC16(dst, src) \
    asm volatile("cp.async.cg.shared.global [%0], [%1], 16;" :: "r"(dst), "l"(src) : "memory")
#define CP_COMMIT() asm volatile("cp.async.commit_group;" ::: "memory")
#define CP_WAIT(n)  asm volatile("cp.async.wait_group %0;" :: "n"(n) : "memory")

__device__ __forceinline__ void mma_tf32_16x8x8(
    float& c0, float& c1, float& c2, float& c3,
    uint32_t a0, uint32_t a1, uint32_t a2, uint32_t a3,
    uint32_t b0, uint32_t b1)
{
    asm volatile(
        "mma.sync.aligned.m16n8k8.row.col.f32.tf32.tf32.f32 "
        "{%0,%1,%2,%3}, {%4,%5,%6,%7}, {%8,%9}, {%0,%1,%2,%3};"
        : "+f"(c0), "+f"(c1), "+f"(c2), "+f"(c3)
        : "r"(a0), "r"(a1), "r"(a2), "r"(a3), "r"(b0), "r"(b1));
}

// ---------------- prep kernels ----------------
__global__ void round_tf32_kernel(const float4* __restrict__ in, float4* __restrict__ out) {
    int i = blockIdx.x * 256 + threadIdx.x;
    float4 v = in[i];
    v.x = tf32r(v.x); v.y = tf32r(v.y); v.z = tf32r(v.z); v.w = tf32r(v.w);
    out[i] = v;
}

__global__ void transpose_tf32_kernel(const float* __restrict__ W, float* __restrict__ WT) {
    __shared__ float t[32][33];
    int n0 = blockIdx.x * 32, k0 = blockIdx.y * 32;
    int tx = threadIdx.x, ty = threadIdx.y;
#pragma unroll
    for (int j = 0; j < 32; j += 8)
        t[ty + j][tx] = W[(size_t)(k0 + ty + j) * 2048 + n0 + tx];
    __syncthreads();
#pragma unroll
    for (int j = 0; j < 32; j += 8)
        WT[(size_t)(n0 + ty + j) * 2048 + k0 + tx] = tf32r(t[tx][ty + j]);
}

// ---------------- tf32 mma.sync GEMM: C[16384,2048] = A @ BW^T ----------------
// A [M,2048] K-contig rows; BW [2048 n][2048 k] K-contig rows (pre-transposed).
// CTA 128x128, BK=16, 256 threads, 8 warps in 2(M)x4(N), warp tile 64x32.
#define BK 16
#define APAD 20   // row stride in floats (conflict-free: r*20 mod 32 distinct for r=0..7)

__global__ __launch_bounds__(256) void gemm_tf32_kernel(
    const float* __restrict__ A, const float* __restrict__ BW, float* __restrict__ C)
{
    __shared__ float As[2][128][APAD];
    __shared__ float Bs[2][128][APAD];

    int tid = threadIdx.x;
    int wid = tid >> 5, lane = tid & 31;
    int wm = wid >> 2, wn = wid & 3;            // warp coords: 2 x 4
    int n0 = blockIdx.x * 128, m0 = blockIdx.y * 128;

    int gq = lane >> 2;                          // group id 0..7
    int kc = lane & 3;

    // loader mapping: idx in [0,512): row = idx>>2, quad = idx&3 (16B each)
    int lr0 = tid >> 1;                          // not used; use generic loop below

    const float* Ag = A + (size_t)m0 * 2048;
    const float* Bg = BW + (size_t)n0 * 2048;

    float acc[4][4][4];
#pragma unroll
    for (int i = 0; i < 4; i++)
#pragma unroll
        for (int j = 0; j < 4; j++)
#pragma unroll
            for (int r = 0; r < 4; r++) acc[i][j][r] = 0.f;

    uint32_t sAbase = smem_u32(&As[0][0][0]);
    uint32_t sBbase = smem_u32(&Bs[0][0][0]);
    const uint32_t stageBytes = 128 * APAD * 4;

    // ---- load stage 0 ----
    {
        int k0 = 0;
#pragma unroll
        for (int v = 0; v < 2; v++) {
            int idx = v * 256 + tid;
            int row = idx >> 2, q = idx & 3;
            uint32_t off = (uint32_t)(row * APAD + q * 4) * 4u;
            CP_ASYNC16(sAbase + off, Ag + (size_t)row * 2048 + k0 + q * 4);
            CP_ASYNC16(sBbase + off, Bg + (size_t)row * 2048 + k0 + q * 4);
        }
        CP_COMMIT();
    }

    for (int kt = 0; kt < 128; kt++) {
        if (kt + 1 < 128) {
            int k0 = (kt + 1) * BK;
            uint32_t so = ((kt + 1) & 1) * stageBytes;
#pragma unroll
            for (int v = 0; v < 2; v++) {
                int idx = v * 256 + tid;
                int row = idx >> 2, q = idx & 3;
                uint32_t off = (uint32_t)(row * APAD + q * 4) * 4u;
                CP_ASYNC16(sAbase + so + off, Ag + (size_t)row * 2048 + k0 + q * 4);
                CP_ASYNC16(sBbase + so + off, Bg + (size_t)row * 2048 + k0 + q * 4);
            }
            CP_COMMIT();
            CP_WAIT(1);
        } else {
            CP_WAIT(0);
        }
        __syncthreads();

        int buf = kt & 1;
#pragma unroll
        for (int k8 = 0; k8 < 2; k8++) {
            int k = k8 * 8;
            uint32_t af[4][4], bf[4][2];
#pragma unroll
            for (int mf = 0; mf < 4; mf++) {
                int r = wm * 64 + mf * 16 + gq;
                af[mf][0] = __float_as_uint(As[buf][r][k + kc]);
                af[mf][1] = __float_as_uint(As[buf][r + 8][k + kc]);
                af[mf][2] = __float_as_uint(As[buf][r][k + kc + 4]);
                af[mf][3] = __float_as_uint(As[buf][r + 8][k + kc + 4]);
            }
#pragma unroll
            for (int nf = 0; nf < 4; nf++) {
                int nr = wn * 32 + nf * 8 + gq;
                bf[nf][0] = __float_as_uint(Bs[buf][nr][k + kc]);
                bf[nf][1] = __float_as_uint(Bs[buf][nr][k + kc + 4]);
            }
#pragma unroll
            for (int mf = 0; mf < 4; mf++)
#pragma unroll
                for (int nf = 0; nf < 4; nf++)
                    mma_tf32_16x8x8(acc[mf][nf][0], acc[mf][nf][1],
                                    acc[mf][nf][2], acc[mf][nf][3],
                                    af[mf][0], af[mf][1], af[mf][2], af[mf][3],
                                    bf[nf][0], bf[nf][1]);
        }
        __syncthreads();
    }

    // ---- epilogue ----
#pragma unroll
    for (int mf = 0; mf < 4; mf++) {
        int r0 = m0 + wm * 64 + mf * 16 + gq;
#pragma unroll
        for (int nf = 0; nf < 4; nf++) {
            int col = n0 + wn * 32 + nf * 8 + kc * 2;
            *(float2*)&C[(size_t)r0 * 2048 + col]       = make_float2(acc[mf][nf][0], acc[mf][nf][1]);
            *(float2*)&C[(size_t)(r0 + 8) * 2048 + col] = make_float2(acc[mf][nf][2], acc[mf][nf][3]);
        }
    }
}

// ---------------- sparse K/V projection (fp32) ----------------
__global__ __launch_bounds__(256, 2) void sparse_kv_kernel(
    const float* __restrict__ x, const int* __restrict__ anchors,
    const float* __restrict__ Wk, const float* __restrict__ Wv)
{
    int bh = blockIdx.x;
    int b = bh >> 4, h = bh & 15;
    const float* W = blockIdx.y ? Wv : Wk;
    float* out     = blockIdx.y ? g_vsp : g_ksp;

    __shared__ int   tok[128];
    __shared__ float xs[128][17];
    __shared__ float ws[16][128];

    int tid = threadIdx.x;
    if (tid < 128) {
        int ti = tid >> 4;
        int tile = (ti == 7) ? 255 : anchors[(bh << 3) + ti];
        tok[tid] = tile * 16 + (tid & 15);
    }
    __syncthreads();

    int tx = tid & 15, ty = tid >> 4;
    float acc[8][8];
#pragma unroll
    for (int i = 0; i < 8; i++)
#pragma unroll
        for (int j = 0; j < 8; j++) acc[i][j] = 0.f;

    for (int kt = 0; kt < DD; kt += 16) {
#pragma unroll
        for (int t = 0; t < 8; t++) {
            int j = t * 256 + tid;
            int row = j >> 4, kk = j & 15;
            xs[row][kk] = x[((size_t)b * SS + tok[row]) * DD + kt + kk];
        }
#pragma unroll
        for (int t = 0; t < 8; t++) {
            int j = t * 256 + tid;
            int kk = j >> 7, col = j & 127;
            ws[kk][col] = W[(size_t)(kt + kk) * DD + h * HDIM + col];
        }
        __syncthreads();
#pragma unroll
        for (int kk = 0; kk < 16; kk++) {
            float av[8], bv[8];
#pragma unroll
            for (int i = 0; i < 4; i++) {
                av[i]     = xs[ty * 4 + i][kk];
                av[4 + i] = xs[64 + ty * 4 + i][kk];
                bv[i]     = ws[kk][tx * 4 + i];
                bv[4 + i] = ws[kk][64 + tx * 4 + i];
            }
#pragma unroll
            for (int i = 0; i < 8; i++)
#pragma unroll
                for (int j = 0; j < 8; j++) acc[i][j] += av[i] * bv[j];
        }
        __syncthreads();
    }

#pragma unroll
    for (int i = 0; i < 8; i++) {
        int m = (i < 4) ? (ty * 4 + i) : (64 + ty * 4 + (i - 4));
        size_t base = (size_t)bh * NKEYS * HDIM + (size_t)m * HDIM;
#pragma unroll
        for (int j = 0; j < 4; j++) {
            out[base + tx * 4 + j]      = acc[i][j];
            out[base + 64 + tx * 4 + j] = acc[i][4 + j];
        }
    }
}

// ---------------- attention over 128 gathered keys ----------------
__global__ __launch_bounds__(512, 1) void attn_kernel(
    const int* __restrict__ anchors, float* __restrict__ attout)
{
    extern __shared__ float sm[];
    float* Kst  = sm;                    // 128*129
    float* Vs   = Kst + 128 * 129;       // 128*128
    float* qs   = Vs + 128 * 128;        // 4*128
    float* wsb  = qs + 512;              // 4*128
    float* redm = wsb + 512;             // 16
    float* reds = redm + 16;             // 16
    int*   tok  = (int*)(reds + 16);     // 128

    int tid = threadIdx.x;
    int bh = blockIdx.y;
    int b = bh >> 4, h = bh & 15;
    int q0 = blockIdx.x * 128;

    if (tid < 128) {
        int ti = tid >> 4;
        int tile = (ti == 7) ? 255 : anchors[(bh << 3) + ti];
        tok[tid] = tile * 16 + (tid & 15);
    }
    for (int i = tid; i < 128 * 128; i += 512) {
        int k = i >> 7, d = i & 127;
        Kst[d * 129 + k] = g_ksp[(size_t)bh * 16384 + i];
        Vs[i]            = g_vsp[(size_t)bh * 16384 + i];
    }
    __syncthreads();

    int qsub = tid >> 7;
    int lane = tid & 31;
    int key  = tid & 127;
    int wIn  = (tid & 127) >> 5;

    const float scale = 0.0883883476483184f;

    for (int it = 0; it < 32; it++) {
        int qpos = q0 + it * 4 + qsub;
        qs[qsub * 128 + key] = g_q[((size_t)b * SS + qpos) * DD + h * HDIM + key];
        __syncthreads();

        float accv = 0.f;
#pragma unroll
        for (int d = 0; d < 128; d++)
            accv += qs[qsub * 128 + d] * Kst[d * 129 + key];
        float logit = accv * scale;
        if (tok[key] > qpos) logit = -1e10f;

        float m = logit;
#pragma unroll
        for (int o = 16; o > 0; o >>= 1) m = fmaxf(m, __shfl_xor_sync(0xffffffffu, m, o));
        if (lane == 0) redm[qsub * 4 + wIn] = m;
        __syncthreads();
        float M = fmaxf(fmaxf(redm[qsub * 4 + 0], redm[qsub * 4 + 1]),
                        fmaxf(redm[qsub * 4 + 2], redm[qsub * 4 + 3]));
        float p = __expf(logit - M);
        float s = p;
#pragma unroll
        for (int o = 16; o > 0; o >>= 1) s += __shfl_xor_sync(0xffffffffu, s, o);
        if (lane == 0) reds[qsub * 4 + wIn] = s;
        __syncthreads();
        float S = reds[qsub * 4 + 0] + reds[qsub * 4 + 1] +
                  reds[qsub * 4 + 2] + reds[qsub * 4 + 3];
        wsb[qsub * 128 + key] = p / S;
        __syncthreads();

        float o = 0.f;
#pragma unroll
        for (int k = 0; k < 128; k++)
            o += wsb[qsub * 128 + k] * Vs[k * 128 + key];
        // round to tf32 so GEMM2's A operand is exactly representable
        attout[((size_t)b * SS + qpos) * DD + h * HDIM + key] = tf32r(o);
    }
}

// ---------------- launch ----------------
extern "C" void kernel_launch(void* const* d_in, const int* in_sizes, int n_in,
                              void* d_out, int out_size)
{
    const float* x       = (const float*)d_in[0];
    const int*   anchors = (const int*)  d_in[1];
    const float* Wq      = (const float*)d_in[2];
    const float* Wk      = (const float*)d_in[3];
    const float* Wv      = (const float*)d_in[4];
    const float* Wo      = (const float*)d_in[5];
    float* out = (float*)d_out;

    float *qp, *attp, *xrp, *wqtp, *wotp;
    cudaGetSymbolAddress((void**)&qp,   g_q);
    cudaGetSymbolAddress((void**)&attp, g_att);
    cudaGetSymbolAddress((void**)&xrp,  g_xr);
    cudaGetSymbolAddress((void**)&wqtp, g_wqt);
    cudaGetSymbolAddress((void**)&wotp, g_wot);

    const int attn_smem = (128 * 129 + 128 * 128 + 512 + 512 + 32) * 4 + 128 * 4;
    cudaFuncSetAttribute(attn_kernel, cudaFuncAttributeMaxDynamicSharedMemorySize, attn_smem);

    // prep: tf32-round x, transpose+round weights; sparse KV (fp32)
    round_tf32_kernel<<<(BB * SS * DD / 4) / 256, 256>>>((const float4*)x, (float4*)xrp);
    transpose_tf32_kernel<<<dim3(64, 64), dim3(32, 8)>>>(Wq, wqtp);
    transpose_tf32_kernel<<<dim3(64, 64), dim3(32, 8)>>>(Wo, wotp);
    sparse_kv_kernel<<<dim3(64, 2), 256>>>(x, anchors, Wk, Wv);

    // Q = x @ Wq  (tf32 mma.sync)
    gemm_tf32_kernel<<<dim3(16, 128), 256>>>(xrp, wqtp, qp);
    // attention
    attn_kernel<<<dim3(32, 64), 512, attn_smem>>>(anchors, attp);
    // out = att @ Wo  (tf32 mma.sync)
    gemm_tf32_kernel<<<dim3(16, 128), 256>>>(attp, wotp, out);
}

// round 5
// speedup vs baseline: 2.8676x; 1.5872x over previous
#include <cuda_runtime.h>
#include <cstdint>
#include <math.h>

#define BB 4
#define SS 4096
#define DD 2048
#define HH 16
#define HDIM 128
#define NKEYS 128
#define KSPLIT 4

// ---------------- scratch ----------------
__device__ float g_q  [(size_t)BB * SS * DD];
__device__ float g_att[(size_t)BB * SS * DD];
__device__ float g_xr [(size_t)BB * SS * DD];
__device__ float g_wqt[2048 * 2048];
__device__ float g_wot[2048 * 2048];
__device__ float g_ksp[64 * NKEYS * HDIM];
__device__ float g_vsp[64 * NKEYS * HDIM];
__device__ float g_kvpart[(size_t)KSPLIT * 2 * 64 * NKEYS * HDIM];

// ---------------- helpers ----------------
__device__ __forceinline__ uint32_t smem_u32(const void* p) {
    uint32_t a;
    asm("{ .reg .u64 t; cvta.to.shared.u64 t, %1; cvt.u32.u64 %0, t; }" : "=r"(a) : "l"(p));
    return a;
}
__device__ __forceinline__ float tf32r(float x) {
    uint32_t u;
    asm("cvt.rna.tf32.f32 %0, %1;" : "=r"(u) : "f"(x));
    return __uint_as_float(u);
}
#define CP_ASYNC16(dst, src) \
    asm volatile("cp.async.cg.shared.global [%0], [%1], 16;" :: "r"(dst), "l"(src) : "memory")
#define CP_COMMIT() asm volatile("cp.async.commit_group;" ::: "memory")
#define CP_WAIT(n)  asm volatile("cp.async.wait_group %0;" :: "n"(n) : "memory")

__device__ __forceinline__ void mma_tf32_16x8x8(
    float& c0, float& c1, float& c2, float& c3,
    uint32_t a0, uint32_t a1, uint32_t a2, uint32_t a3,
    uint32_t b0, uint32_t b1)
{
    asm volatile(
        "mma.sync.aligned.m16n8k8.row.col.f32.tf32.tf32.f32 "
        "{%0,%1,%2,%3}, {%4,%5,%6,%7}, {%8,%9}, {%0,%1,%2,%3};"
        : "+f"(c0), "+f"(c1), "+f"(c2), "+f"(c3)
        : "r"(a0), "r"(a1), "r"(a2), "r"(a3), "r"(b0), "r"(b1));
}

// ---------------- prep kernels ----------------
__global__ void round_tf32_kernel(const float4* __restrict__ in, float4* __restrict__ out) {
    int i = blockIdx.x * 256 + threadIdx.x;
    float4 v = in[i];
    v.x = tf32r(v.x); v.y = tf32r(v.y); v.z = tf32r(v.z); v.w = tf32r(v.w);
    out[i] = v;
}

__global__ void transpose_tf32_kernel(const float* __restrict__ W, float* __restrict__ WT) {
    __shared__ float t[32][33];
    int n0 = blockIdx.x * 32, k0 = blockIdx.y * 32;
    int tx = threadIdx.x, ty = threadIdx.y;
#pragma unroll
    for (int j = 0; j < 32; j += 8)
        t[ty + j][tx] = W[(size_t)(k0 + ty + j) * 2048 + n0 + tx];
    __syncthreads();
#pragma unroll
    for (int j = 0; j < 32; j += 8)
        WT[(size_t)(n0 + ty + j) * 2048 + k0 + tx] = tf32r(t[tx][ty + j]);
}

// ---------------- tf32 mma.sync GEMM: C[16384,2048] = A @ BW^T ----------------
#define BK 16
#define APAD 20

__global__ __launch_bounds__(256) void gemm_tf32_kernel(
    const float* __restrict__ A, const float* __restrict__ BW, float* __restrict__ C)
{
    __shared__ float As[2][128][APAD];
    __shared__ float Bs[2][128][APAD];

    int tid = threadIdx.x;
    int wid = tid >> 5, lane = tid & 31;
    int wm = wid >> 2, wn = wid & 3;
    int n0 = blockIdx.x * 128, m0 = blockIdx.y * 128;

    int gq = lane >> 2;
    int kc = lane & 3;

    const float* Ag = A + (size_t)m0 * 2048;
    const float* Bg = BW + (size_t)n0 * 2048;

    float acc[4][4][4];
#pragma unroll
    for (int i = 0; i < 4; i++)
#pragma unroll
        for (int j = 0; j < 4; j++)
#pragma unroll
            for (int r = 0; r < 4; r++) acc[i][j][r] = 0.f;

    uint32_t sAbase = smem_u32(&As[0][0][0]);
    uint32_t sBbase = smem_u32(&Bs[0][0][0]);
    const uint32_t stageBytes = 128 * APAD * 4;

    {
#pragma unroll
        for (int v = 0; v < 2; v++) {
            int idx = v * 256 + tid;
            int row = idx >> 2, q = idx & 3;
            uint32_t off = (uint32_t)(row * APAD + q * 4) * 4u;
            CP_ASYNC16(sAbase + off, Ag + (size_t)row * 2048 + q * 4);
            CP_ASYNC16(sBbase + off, Bg + (size_t)row * 2048 + q * 4);
        }
        CP_COMMIT();
    }

    for (int kt = 0; kt < 128; kt++) {
        if (kt + 1 < 128) {
            int k0 = (kt + 1) * BK;
            uint32_t so = ((kt + 1) & 1) * stageBytes;
#pragma unroll
            for (int v = 0; v < 2; v++) {
                int idx = v * 256 + tid;
                int row = idx >> 2, q = idx & 3;
                uint32_t off = (uint32_t)(row * APAD + q * 4) * 4u;
                CP_ASYNC16(sAbase + so + off, Ag + (size_t)row * 2048 + k0 + q * 4);
                CP_ASYNC16(sBbase + so + off, Bg + (size_t)row * 2048 + k0 + q * 4);
            }
            CP_COMMIT();
            CP_WAIT(1);
        } else {
            CP_WAIT(0);
        }
        __syncthreads();

        int buf = kt & 1;
#pragma unroll
        for (int k8 = 0; k8 < 2; k8++) {
            int k = k8 * 8;
            uint32_t af[4][4], bf[4][2];
#pragma unroll
            for (int mf = 0; mf < 4; mf++) {
                int r = wm * 64 + mf * 16 + gq;
                af[mf][0] = __float_as_uint(As[buf][r][k + kc]);
                af[mf][1] = __float_as_uint(As[buf][r + 8][k + kc]);
                af[mf][2] = __float_as_uint(As[buf][r][k + kc + 4]);
                af[mf][3] = __float_as_uint(As[buf][r + 8][k + kc + 4]);
            }
#pragma unroll
            for (int nf = 0; nf < 4; nf++) {
                int nr = wn * 32 + nf * 8 + gq;
                bf[nf][0] = __float_as_uint(Bs[buf][nr][k + kc]);
                bf[nf][1] = __float_as_uint(Bs[buf][nr][k + kc + 4]);
            }
#pragma unroll
            for (int mf = 0; mf < 4; mf++)
#pragma unroll
                for (int nf = 0; nf < 4; nf++)
                    mma_tf32_16x8x8(acc[mf][nf][0], acc[mf][nf][1],
                                    acc[mf][nf][2], acc[mf][nf][3],
                                    af[mf][0], af[mf][1], af[mf][2], af[mf][3],
                                    bf[nf][0], bf[nf][1]);
        }
        __syncthreads();
    }

#pragma unroll
    for (int mf = 0; mf < 4; mf++) {
        int r0 = m0 + wm * 64 + mf * 16 + gq;
#pragma unroll
        for (int nf = 0; nf < 4; nf++) {
            int col = n0 + wn * 32 + nf * 8 + kc * 2;
            *(float2*)&C[(size_t)r0 * 2048 + col]       = make_float2(acc[mf][nf][0], acc[mf][nf][1]);
            *(float2*)&C[(size_t)(r0 + 8) * 2048 + col] = make_float2(acc[mf][nf][2], acc[mf][nf][3]);
        }
    }
}

// ---------------- sparse K/V projection, split-K x4 (deterministic) ----------------
__global__ __launch_bounds__(256, 2) void sparse_kv_part_kernel(
    const float* __restrict__ x, const int* __restrict__ anchors,
    const float* __restrict__ Wk, const float* __restrict__ Wv)
{
    int bh = blockIdx.x;
    int b = bh >> 4, h = bh & 15;
    int kvsel = blockIdx.y;
    int kz = blockIdx.z;
    const float* W = kvsel ? Wv : Wk;
    float* out = g_kvpart + (size_t)kz * (2 * 64 * NKEYS * HDIM)
                          + (size_t)kvsel * (64 * NKEYS * HDIM)
                          + (size_t)bh * NKEYS * HDIM;

    __shared__ int   tok[128];
    __shared__ float xs[128][17];
    __shared__ float ws[16][128];

    int tid = threadIdx.x;
    if (tid < 128) {
        int ti = tid >> 4;
        int tile = (ti == 7) ? 255 : anchors[(bh << 3) + ti];
        tok[tid] = tile * 16 + (tid & 15);
    }
    __syncthreads();

    int tx = tid & 15, ty = tid >> 4;
    float acc[8][8];
#pragma unroll
    for (int i = 0; i < 8; i++)
#pragma unroll
        for (int j = 0; j < 8; j++) acc[i][j] = 0.f;

    int kbeg = kz * (DD / KSPLIT), kend = kbeg + DD / KSPLIT;
    for (int kt = kbeg; kt < kend; kt += 16) {
#pragma unroll
        for (int t = 0; t < 8; t++) {
            int j = t * 256 + tid;
            int row = j >> 4, kk = j & 15;
            xs[row][kk] = x[((size_t)b * SS + tok[row]) * DD + kt + kk];
        }
#pragma unroll
        for (int t = 0; t < 8; t++) {
            int j = t * 256 + tid;
            int kk = j >> 7, col = j & 127;
            ws[kk][col] = W[(size_t)(kt + kk) * DD + h * HDIM + col];
        }
        __syncthreads();
#pragma unroll
        for (int kk = 0; kk < 16; kk++) {
            float av[8], bv[8];
#pragma unroll
            for (int i = 0; i < 4; i++) {
                av[i]     = xs[ty * 4 + i][kk];
                av[4 + i] = xs[64 + ty * 4 + i][kk];
                bv[i]     = ws[kk][tx * 4 + i];
                bv[4 + i] = ws[kk][64 + tx * 4 + i];
            }
#pragma unroll
            for (int i = 0; i < 8; i++)
#pragma unroll
                for (int j = 0; j < 8; j++) acc[i][j] += av[i] * bv[j];
        }
        __syncthreads();
    }

#pragma unroll
    for (int i = 0; i < 8; i++) {
        int m = (i < 4) ? (ty * 4 + i) : (64 + ty * 4 + (i - 4));
        size_t base = (size_t)m * HDIM;
#pragma unroll
        for (int j = 0; j < 4; j++) {
            out[base + tx * 4 + j]      = acc[i][j];
            out[base + 64 + tx * 4 + j] = acc[i][4 + j];
        }
    }
}

__global__ void kv_reduce_kernel(float4* __restrict__ k4, float4* __restrict__ v4) {
    const size_t stride4 = (size_t)2 * 64 * NKEYS * HDIM / 4;   // per split, in float4
    size_t i = (size_t)blockIdx.x * 256 + threadIdx.x;           // [0, 2*64*4096)
    const float4* p = (const float4*)g_kvpart;
    float4 s = p[i];
#pragma unroll
    for (int z = 1; z < KSPLIT; z++) {
        float4 t = p[i + z * stride4];
        s.x += t.x; s.y += t.y; s.z += t.z; s.w += t.w;
    }
    const size_t half = (size_t)64 * NKEYS * HDIM / 4;
    if (i < half) k4[i] = s; else v4[i - half] = s;
}

// ---------------- attention: tf32 mma, 128 queries x 128 keys per CTA ----------------
// smem: Ksm[key][132], Vt[d][132 keys], QS[q][132] (Q then S/P), tok[128]
#define ASTR 132
#define ATTN_SMEM ((3 * 128 * ASTR) * 4 + 128 * 4)

__global__ __launch_bounds__(256) void attn_mma_kernel(
    const int* __restrict__ anchors, float* __restrict__ attout)
{
    extern __shared__ float sm[];
    float* Ksm = sm;                        // 128*132
    float* Vt  = Ksm + 128 * ASTR;          // 128*132
    float* QS  = Vt  + 128 * ASTR;          // 128*132
    int*   tok = (int*)(QS + 128 * ASTR);   // 128

    int tid = threadIdx.x;
    int bh = blockIdx.y;
    int b = bh >> 4, h = bh & 15;
    int q0 = blockIdx.x * 128;
    int wid = tid >> 5, lane = tid & 31;
    int gq = lane >> 2, kc = lane & 3;

    if (tid < 128) {
        int ti = tid >> 4;
        int tile = (ti == 7) ? 255 : anchors[(bh << 3) + ti];
        tok[tid] = tile * 16 + (tid & 15);
    }

    // K: [key][d] row-major, coalesced
    const float* kg = g_ksp + (size_t)bh * 16384;
    for (int i = tid; i < 16384; i += 256) {
        int key = i >> 7, d = i & 127;
        Ksm[key * ASTR + d] = tf32r(kg[i]);
    }
    // V transposed: Vt[d][key]
    const float* vg = g_vsp + (size_t)bh * 16384;
    for (int idx = tid; idx < 4096; idx += 256) {
        int key = idx >> 5, dq = (idx & 31) * 4;
        float4 v = *(const float4*)(vg + key * 128 + dq);
        Vt[(dq + 0) * ASTR + key] = tf32r(v.x);
        Vt[(dq + 1) * ASTR + key] = tf32r(v.y);
        Vt[(dq + 2) * ASTR + key] = tf32r(v.z);
        Vt[(dq + 3) * ASTR + key] = tf32r(v.w);
    }
    // Q: [q][d]
    for (int i = tid; i < 16384; i += 256) {
        int q = i >> 7, d = i & 127;
        QS[q * ASTR + d] = tf32r(g_q[((size_t)b * SS + q0 + q) * DD + h * HDIM + d]);
    }
    __syncthreads();

    // ---- S = Q @ K^T : warp w owns queries [w*16, w*16+16) ----
    float acc[16][4];
#pragma unroll
    for (int nf = 0; nf < 16; nf++)
#pragma unroll
        for (int r = 0; r < 4; r++) acc[nf][r] = 0.f;

    int r = wid * 16 + gq;
#pragma unroll
    for (int kt = 0; kt < 16; kt++) {
        int k8 = kt * 8;
        uint32_t a0 = __float_as_uint(QS[r * ASTR + k8 + kc]);
        uint32_t a1 = __float_as_uint(QS[(r + 8) * ASTR + k8 + kc]);
        uint32_t a2 = __float_as_uint(QS[r * ASTR + k8 + kc + 4]);
        uint32_t a3 = __float_as_uint(QS[(r + 8) * ASTR + k8 + kc + 4]);
#pragma unroll
        for (int nf = 0; nf < 16; nf++) {
            int nr = nf * 8 + gq;
            uint32_t b0 = __float_as_uint(Ksm[nr * ASTR + k8 + kc]);
            uint32_t b1 = __float_as_uint(Ksm[nr * ASTR + k8 + kc + 4]);
            mma_tf32_16x8x8(acc[nf][0], acc[nf][1], acc[nf][2], acc[nf][3],
                            a0, a1, a2, a3, b0, b1);
        }
    }
    __syncthreads();   // all warps done reading Q
#pragma unroll
    for (int nf = 0; nf < 16; nf++) {
        int col = nf * 8 + kc * 2;
        QS[r * ASTR + col]           = acc[nf][0];
        QS[r * ASTR + col + 1]       = acc[nf][1];
        QS[(r + 8) * ASTR + col]     = acc[nf][2];
        QS[(r + 8) * ASTR + col + 1] = acc[nf][3];
    }
    __syncthreads();

    // ---- softmax: 2 threads per row ----
    {
        const float scale = 0.0883883476483184f;
        int row = tid >> 1, hc = (tid & 1) * 64;
        int qpos = q0 + row;
        float* S = QS + row * ASTR + hc;
        float mx = -3.0e38f;
#pragma unroll 16
        for (int c = 0; c < 64; c++) {
            float v = S[c] * scale;
            if (tok[hc + c] > qpos) v = -1e10f;
            mx = fmaxf(mx, v);
        }
        mx = fmaxf(mx, __shfl_xor_sync(0xffffffffu, mx, 1));
        float sum = 0.f;
#pragma unroll 16
        for (int c = 0; c < 64; c++) {
            float v = S[c] * scale;
            if (tok[hc + c] > qpos) v = -1e10f;
            float e = __expf(v - mx);
            sum += e;
            S[c] = e;
        }
        sum += __shfl_xor_sync(0xffffffffu, sum, 1);
        float inv = 1.f / sum;
#pragma unroll 16
        for (int c = 0; c < 64; c++)
            S[c] = tf32r(S[c] * inv);
    }
    __syncthreads();

    // ---- O = P @ V : same warp rows, B = Vt ----
    float acc2[16][4];
#pragma unroll
    for (int nf = 0; nf < 16; nf++)
#pragma unroll
        for (int rr = 0; rr < 4; rr++) acc2[nf][rr] = 0.f;

#pragma unroll
    for (int kt = 0; kt < 16; kt++) {
        int k8 = kt * 8;
        uint32_t a0 = __float_as_uint(QS[r * ASTR + k8 + kc]);
        uint32_t a1 = __float_as_uint(QS[(r + 8) * ASTR + k8 + kc]);
        uint32_t a2 = __float_as_uint(QS[r * ASTR + k8 + kc + 4]);
        uint32_t a3 = __float_as_uint(QS[(r + 8) * ASTR + k8 + kc + 4]);
#pragma unroll
        for (int nf = 0; nf < 16; nf++) {
            int nr = nf * 8 + gq;
            uint32_t b0 = __float_as_uint(Vt[nr * ASTR + k8 + kc]);
            uint32_t b1 = __float_as_uint(Vt[nr * ASTR + k8 + kc + 4]);
            mma_tf32_16x8x8(acc2[nf][0], acc2[nf][1], acc2[nf][2], acc2[nf][3],
                            a0, a1, a2, a3, b0, b1);
        }
    }

    // ---- store O (tf32-rounded: feeds GEMM2's A operand) ----
    float* o0 = attout + ((size_t)b * SS + q0 + r) * DD + h * HDIM;
    float* o1 = attout + ((size_t)b * SS + q0 + r + 8) * DD + h * HDIM;
#pragma unroll
    for (int nf = 0; nf < 16; nf++) {
        int col = nf * 8 + kc * 2;
        *(float2*)(o0 + col) = make_float2(tf32r(acc2[nf][0]), tf32r(acc2[nf][1]));
        *(float2*)(o1 + col) = make_float2(tf32r(acc2[nf][2]), tf32r(acc2[nf][3]));
    }
}

// ---------------- launch ----------------
extern "C" void kernel_launch(void* const* d_in, const int* in_sizes, int n_in,
                              void* d_out, int out_size)
{
    const float* x       = (const float*)d_in[0];
    const int*   anchors = (const int*)  d_in[1];
    const float* Wq      = (const float*)d_in[2];
    const float* Wk      = (const float*)d_in[3];
    const float* Wv      = (const float*)d_in[4];
    const float* Wo      = (const float*)d_in[5];
    float* out = (float*)d_out;

    float *qp, *attp, *xrp, *wqtp, *wotp, *kspp, *vspp;
    cudaGetSymbolAddress((void**)&qp,   g_q);
    cudaGetSymbolAddress((void**)&attp, g_att);
    cudaGetSymbolAddress((void**)&xrp,  g_xr);
    cudaGetSymbolAddress((void**)&wqtp, g_wqt);
    cudaGetSymbolAddress((void**)&wotp, g_wot);
    cudaGetSymbolAddress((void**)&kspp, g_ksp);
    cudaGetSymbolAddress((void**)&vspp, g_vsp);

    cudaFuncSetAttribute(attn_mma_kernel, cudaFuncAttributeMaxDynamicSharedMemorySize, ATTN_SMEM);

    // prep
    round_tf32_kernel<<<(BB * SS * DD / 4) / 256, 256>>>((const float4*)x, (float4*)xrp);
    transpose_tf32_kernel<<<dim3(64, 64), dim3(32, 8)>>>(Wq, wqtp);
    transpose_tf32_kernel<<<dim3(64, 64), dim3(32, 8)>>>(Wo, wotp);

    // sparse KV (split-K x4 + deterministic reduce)
    sparse_kv_part_kernel<<<dim3(64, 2, KSPLIT), 256>>>(x, anchors, Wk, Wv);
    kv_reduce_kernel<<<(2 * 64 * NKEYS * HDIM / 4) / 256, 256>>>((float4*)kspp, (float4*)vspp);

    // Q = x @ Wq
    gemm_tf32_kernel<<<dim3(16, 128), 256>>>(xrp, wqtp, qp);
    // attention (tf32 mma)
    attn_mma_kernel<<<dim3(32, 64), 256, ATTN_SMEM>>>(anchors, attp);
    // out = att @ Wo
    gemm_tf32_kernel<<<dim3(16, 128), 256>>>(attp, wotp, out);
}

// round 6
// speedup vs baseline: 3.0679x; 1.0698x over previous
#include <cuda_runtime.h>
#include <cstdint>
#include <math.h>

#define BB 4
#define SS 4096
#define DD 2048
#define HH 16
#define HDIM 128
#define NKEYS 128

// ---------------- scratch ----------------
__device__ float g_q  [(size_t)BB * SS * DD];
__device__ float g_att[(size_t)BB * SS * DD];
__device__ float g_xr [(size_t)BB * SS * DD];
__device__ float g_wqt[2048 * 2048];
__device__ float g_wot[2048 * 2048];
__device__ float g_wkt[2048 * 2048];
__device__ float g_wvt[2048 * 2048];
__device__ float g_ksp[64 * NKEYS * HDIM];
__device__ float g_vsp[64 * NKEYS * HDIM];

// ---------------- helpers ----------------
__device__ __forceinline__ uint32_t smem_u32(const void* p) {
    uint32_t a;
    asm("{ .reg .u64 t; cvta.to.shared.u64 t, %1; cvt.u32.u64 %0, t; }" : "=r"(a) : "l"(p));
    return a;
}
__device__ __forceinline__ float tf32r(float x) {
    uint32_t u;
    asm("cvt.rna.tf32.f32 %0, %1;" : "=r"(u) : "f"(x));
    return __uint_as_float(u);
}
#define CP_ASYNC16(dst, src) \
    asm volatile("cp.async.cg.shared.global [%0], [%1], 16;" :: "r"(dst), "l"(src) : "memory")
#define CP_COMMIT() asm volatile("cp.async.commit_group;" ::: "memory")
#define CP_WAIT(n)  asm volatile("cp.async.wait_group %0;" :: "n"(n) : "memory")

__device__ __forceinline__ void mma_tf32_16x8x8(
    float& c0, float& c1, float& c2, float& c3,
    uint32_t a0, uint32_t a1, uint32_t a2, uint32_t a3,
    uint32_t b0, uint32_t b1)
{
    asm volatile(
        "mma.sync.aligned.m16n8k8.row.col.f32.tf32.tf32.f32 "
        "{%0,%1,%2,%3}, {%4,%5,%6,%7}, {%8,%9}, {%0,%1,%2,%3};"
        : "+f"(c0), "+f"(c1), "+f"(c2), "+f"(c3)
        : "r"(a0), "r"(a1), "r"(a2), "r"(a3), "r"(b0), "r"(b1));
}

// ---------------- prep kernels ----------------
__global__ void round_tf32_kernel(const float4* __restrict__ in, float4* __restrict__ out) {
    int i = blockIdx.x * 256 + threadIdx.x;
    float4 v = in[i];
    v.x = tf32r(v.x); v.y = tf32r(v.y); v.z = tf32r(v.z); v.w = tf32r(v.w);
    out[i] = v;
}

__global__ void transpose_tf32_kernel(const float* __restrict__ W, float* __restrict__ WT) {
    __shared__ float t[32][33];
    int n0 = blockIdx.x * 32, k0 = blockIdx.y * 32;
    int tx = threadIdx.x, ty = threadIdx.y;
#pragma unroll
    for (int j = 0; j < 32; j += 8)
        t[ty + j][tx] = W[(size_t)(k0 + ty + j) * 2048 + n0 + tx];
    __syncthreads();
#pragma unroll
    for (int j = 0; j < 32; j += 8)
        WT[(size_t)(n0 + ty + j) * 2048 + k0 + tx] = tf32r(t[tx][ty + j]);
}

// ---------------- tf32 GEMM, 128(M)x256(N) tile, 4-stage, 512 threads ----------------
// A [16384,2048] K-contig; BW [2048 n][2048 k] K-contig. C row-major [16384,2048].
#define PAD 20
#define GSW ((128 + 256) * PAD)            // words per stage
#define GEMM_SMEM (4 * GSW * 4)

__global__ __launch_bounds__(512, 1) void gemm256_kernel(
    const float* __restrict__ A, const float* __restrict__ BW, float* __restrict__ C)
{
    extern __shared__ float sh[];
    int tid = threadIdx.x;
    int wid = tid >> 5, lane = tid & 31;
    int wm = wid >> 2, wn = wid & 3;        // 4x4 warps, warp tile 32(M)x64(N)
    int gq = lane >> 2, kc = lane & 3;
    int n0 = blockIdx.x * 256, m0 = blockIdx.y * 128;

    int lrow = tid >> 2, lq = tid & 3;      // loader: row 0..127, 16B quad
    const float* Ag  = A  + (size_t)(m0 + lrow) * 2048 + lq * 4;
    const float* Bg0 = BW + (size_t)(n0 + lrow) * 2048 + lq * 4;
    const float* Bg1 = Bg0 + (size_t)128 * 2048;

    uint32_t sA = smem_u32(sh) + (uint32_t)(lrow * PAD + lq * 4) * 4u;
    uint32_t sB = smem_u32(sh) + (uint32_t)((128 + lrow) * PAD + lq * 4) * 4u;
    const uint32_t stB = GSW * 4;

    float acc[2][8][4];
#pragma unroll
    for (int i = 0; i < 2; i++)
#pragma unroll
        for (int j = 0; j < 8; j++)
#pragma unroll
            for (int r = 0; r < 4; r++) acc[i][j][r] = 0.f;

    // prefill stages 0..2
#pragma unroll
    for (int s = 0; s < 3; s++) {
        int k0 = s * 16;
        CP_ASYNC16(sA + s * stB, Ag + k0);
        CP_ASYNC16(sB + s * stB, Bg0 + k0);
        CP_ASYNC16(sB + s * stB + 128 * PAD * 4, Bg1 + k0);
        CP_COMMIT();
    }

    for (int kt = 0; kt < 128; kt++) {
        CP_WAIT(2);
        __syncthreads();
        if (kt + 3 < 128) {
            int s = (kt + 3) & 3, k0 = (kt + 3) * 16;
            CP_ASYNC16(sA + s * stB, Ag + k0);
            CP_ASYNC16(sB + s * stB, Bg0 + k0);
            CP_ASYNC16(sB + s * stB + 128 * PAD * 4, Bg1 + k0);
        }
        CP_COMMIT();

        const float* As = sh + (kt & 3) * GSW;
        const float* Bs = As + 128 * PAD;
#pragma unroll
        for (int k8 = 0; k8 < 2; k8++) {
            int k = k8 * 8;
            uint32_t af[2][4], bf[8][2];
#pragma unroll
            for (int mf = 0; mf < 2; mf++) {
                int r = wm * 32 + mf * 16 + gq;
                af[mf][0] = __float_as_uint(As[r * PAD + k + kc]);
                af[mf][1] = __float_as_uint(As[(r + 8) * PAD + k + kc]);
                af[mf][2] = __float_as_uint(As[r * PAD + k + kc + 4]);
                af[mf][3] = __float_as_uint(As[(r + 8) * PAD + k + kc + 4]);
            }
#pragma unroll
            for (int nf = 0; nf < 8; nf++) {
                int nr = wn * 64 + nf * 8 + gq;
                bf[nf][0] = __float_as_uint(Bs[nr * PAD + k + kc]);
                bf[nf][1] = __float_as_uint(Bs[nr * PAD + k + kc + 4]);
            }
#pragma unroll
            for (int mf = 0; mf < 2; mf++)
#pragma unroll
                for (int nf = 0; nf < 8; nf++)
                    mma_tf32_16x8x8(acc[mf][nf][0], acc[mf][nf][1],
                                    acc[mf][nf][2], acc[mf][nf][3],
                                    af[mf][0], af[mf][1], af[mf][2], af[mf][3],
                                    bf[nf][0], bf[nf][1]);
        }
    }

#pragma unroll
    for (int mf = 0; mf < 2; mf++) {
        int r0 = m0 + wm * 32 + mf * 16 + gq;
#pragma unroll
        for (int nf = 0; nf < 8; nf++) {
            int col = n0 + wn * 64 + nf * 8 + kc * 2;
            *(float2*)&C[(size_t)r0 * 2048 + col]       = make_float2(acc[mf][nf][0], acc[mf][nf][1]);
            *(float2*)&C[(size_t)(r0 + 8) * 2048 + col] = make_float2(acc[mf][nf][2], acc[mf][nf][3]);
        }
    }
}

// ---------------- sparse K/V projection via tf32 mma ----------------
// grid (64 bh, 2 {K,V}); CTA: 128 gathered tokens x 128 head cols x 2048 K.
#define KSW ((128 + 128) * PAD)
#define KV_SMEM (4 * KSW * 4 + 128 * 4)

__global__ __launch_bounds__(256, 1) void sparse_kv_mma_kernel(
    const int* __restrict__ anchors)
{
    extern __shared__ float sh[];
    int*  tok = (int*)(sh + 4 * KSW);

    int tid = threadIdx.x;
    int bh = blockIdx.x;
    int h = bh & 15, b = bh >> 4;
    const float* WT = blockIdx.y ? g_wvt : g_wkt;
    float* out      = (blockIdx.y ? g_vsp : g_ksp) + (size_t)bh * NKEYS * HDIM;

    if (tid < 128) {
        int ti = tid >> 4;
        int tile = (ti == 7) ? 255 : anchors[(bh << 3) + ti];
        tok[tid] = tile * 16 + (tid & 15);
    }
    __syncthreads();

    int wid = tid >> 5, lane = tid & 31;
    int wm = wid >> 2, wn = wid & 3;        // 2x4 warps, warp tile 64x32
    int gq = lane >> 2, kc = lane & 3;

    int lrow = tid >> 2, lq = tid & 3;      // loader rows: lrow, 64+lrow
    const float* Ag0 = g_xr + ((size_t)b * SS + tok[lrow])      * 2048 + lq * 4;
    const float* Ag1 = g_xr + ((size_t)b * SS + tok[64 + lrow]) * 2048 + lq * 4;
    const float* Bg0 = WT + (size_t)(h * 128 + lrow) * 2048 + lq * 4;
    const float* Bg1 = Bg0 + (size_t)64 * 2048;

    uint32_t sA0 = smem_u32(sh) + (uint32_t)(lrow * PAD + lq * 4) * 4u;
    uint32_t sA1 = sA0 + 64 * PAD * 4;
    uint32_t sB0 = smem_u32(sh) + (uint32_t)((128 + lrow) * PAD + lq * 4) * 4u;
    uint32_t sB1 = sB0 + 64 * PAD * 4;
    const uint32_t stB = KSW * 4;

    float acc[4][4][4];
#pragma unroll
    for (int i = 0; i < 4; i++)
#pragma unroll
        for (int j = 0; j < 4; j++)
#pragma unroll
            for (int r = 0; r < 4; r++) acc[i][j][r] = 0.f;

#pragma unroll
    for (int s = 0; s < 3; s++) {
        int k0 = s * 16;
        CP_ASYNC16(sA0 + s * stB, Ag0 + k0);
        CP_ASYNC16(sA1 + s * stB, Ag1 + k0);
        CP_ASYNC16(sB0 + s * stB, Bg0 + k0);
        CP_ASYNC16(sB1 + s * stB, Bg1 + k0);
        CP_COMMIT();
    }

    for (int kt = 0; kt < 128; kt++) {
        CP_WAIT(2);
        __syncthreads();
        if (kt + 3 < 128) {
            int s = (kt + 3) & 3, k0 = (kt + 3) * 16;
            CP_ASYNC16(sA0 + s * stB, Ag0 + k0);
            CP_ASYNC16(sA1 + s * stB, Ag1 + k0);
            CP_ASYNC16(sB0 + s * stB, Bg0 + k0);
            CP_ASYNC16(sB1 + s * stB, Bg1 + k0);
        }
        CP_COMMIT();

        const float* As = sh + (kt & 3) * KSW;
        const float* Bs = As + 128 * PAD;
#pragma unroll
        for (int k8 = 0; k8 < 2; k8++) {
            int k = k8 * 8;
            uint32_t af[4][4], bf[4][2];
#pragma unroll
            for (int mf = 0; mf < 4; mf++) {
                int r = wm * 64 + mf * 16 + gq;
                af[mf][0] = __float_as_uint(As[r * PAD + k + kc]);
                af[mf][1] = __float_as_uint(As[(r + 8) * PAD + k + kc]);
                af[mf][2] = __float_as_uint(As[r * PAD + k + kc + 4]);
                af[mf][3] = __float_as_uint(As[(r + 8) * PAD + k + kc + 4]);
            }
#pragma unroll
            for (int nf = 0; nf < 4; nf++) {
                int nr = wn * 32 + nf * 8 + gq;
                bf[nf][0] = __float_as_uint(Bs[nr * PAD + k + kc]);
                bf[nf][1] = __float_as_uint(Bs[nr * PAD + k + kc + 4]);
            }
#pragma unroll
            for (int mf = 0; mf < 4; mf++)
#pragma unroll
                for (int nf = 0; nf < 4; nf++)
                    mma_tf32_16x8x8(acc[mf][nf][0], acc[mf][nf][1],
                                    acc[mf][nf][2], acc[mf][nf][3],
                                    af[mf][0], af[mf][1], af[mf][2], af[mf][3],
                                    bf[nf][0], bf[nf][1]);
        }
    }

#pragma unroll
    for (int mf = 0; mf < 4; mf++) {
        int r0 = wm * 64 + mf * 16 + gq;
#pragma unroll
        for (int nf = 0; nf < 4; nf++) {
            int col = wn * 32 + nf * 8 + kc * 2;
            *(float2*)&out[(size_t)r0 * 128 + col]       = make_float2(acc[mf][nf][0], acc[mf][nf][1]);
            *(float2*)&out[(size_t)(r0 + 8) * 128 + col] = make_float2(acc[mf][nf][2], acc[mf][nf][3]);
        }
    }
}

// ---------------- attention: tf32 mma, 128 queries x 128 keys per CTA ----------------
#define ASTR 132
#define ATTN_SMEM ((3 * 128 * ASTR) * 4 + 128 * 4)

__global__ __launch_bounds__(256) void attn_mma_kernel(
    const int* __restrict__ anchors, float* __restrict__ attout)
{
    extern __shared__ float sm[];
    float* Ksm = sm;
    float* Vt  = Ksm + 128 * ASTR;
    float* QS  = Vt  + 128 * ASTR;
    int*   tok = (int*)(QS + 128 * ASTR);

    int tid = threadIdx.x;
    int bh = blockIdx.y;
    int b = bh >> 4, h = bh & 15;
    int q0 = blockIdx.x * 128;
    int wid = tid >> 5, lane = tid & 31;
    int gq = lane >> 2, kc = lane & 3;

    if (tid < 128) {
        int ti = tid >> 4;
        int tile = (ti == 7) ? 255 : anchors[(bh << 3) + ti];
        tok[tid] = tile * 16 + (tid & 15);
    }

    const float* kg = g_ksp + (size_t)bh * 16384;
    for (int i = tid; i < 16384; i += 256) {
        int key = i >> 7, d = i & 127;
        Ksm[key * ASTR + d] = tf32r(kg[i]);
    }
    const float* vg = g_vsp + (size_t)bh * 16384;
    for (int idx = tid; idx < 4096; idx += 256) {
        int key = idx >> 5, dq = (idx & 31) * 4;
        float4 v = *(const float4*)(vg + key * 128 + dq);
        Vt[(dq + 0) * ASTR + key] = tf32r(v.x);
        Vt[(dq + 1) * ASTR + key] = tf32r(v.y);
        Vt[(dq + 2) * ASTR + key] = tf32r(v.z);
        Vt[(dq + 3) * ASTR + key] = tf32r(v.w);
    }
    for (int i = tid; i < 16384; i += 256) {
        int q = i >> 7, d = i & 127;
        QS[q * ASTR + d] = tf32r(g_q[((size_t)b * SS + q0 + q) * DD + h * HDIM + d]);
    }
    __syncthreads();

    float acc[16][4];
#pragma unroll
    for (int nf = 0; nf < 16; nf++)
#pragma unroll
        for (int r = 0; r < 4; r++) acc[nf][r] = 0.f;

    int r = wid * 16 + gq;
#pragma unroll
    for (int kt = 0; kt < 16; kt++) {
        int k8 = kt * 8;
        uint32_t a0 = __float_as_uint(QS[r * ASTR + k8 + kc]);
        uint32_t a1 = __float_as_uint(QS[(r + 8) * ASTR + k8 + kc]);
        uint32_t a2 = __float_as_uint(QS[r * ASTR + k8 + kc + 4]);
        uint32_t a3 = __float_as_uint(QS[(r + 8) * ASTR + k8 + kc + 4]);
#pragma unroll
        for (int nf = 0; nf < 16; nf++) {
            int nr = nf * 8 + gq;
            uint32_t b0 = __float_as_uint(Ksm[nr * ASTR + k8 + kc]);
            uint32_t b1 = __float_as_uint(Ksm[nr * ASTR + k8 + kc + 4]);
            mma_tf32_16x8x8(acc[nf][0], acc[nf][1], acc[nf][2], acc[nf][3],
                            a0, a1, a2, a3, b0, b1);
        }
    }
    __syncthreads();
#pragma unroll
    for (int nf = 0; nf < 16; nf++) {
        int col = nf * 8 + kc * 2;
        QS[r * ASTR + col]           = acc[nf][0];
        QS[r * ASTR + col + 1]       = acc[nf][1];
        QS[(r + 8) * ASTR + col]     = acc[nf][2];
        QS[(r + 8) * ASTR + col + 1] = acc[nf][3];
    }
    __syncthreads();

    {
        const float scale = 0.0883883476483184f;
        int row = tid >> 1, hc = (tid & 1) * 64;
        int qpos = q0 + row;
        float* S = QS + row * ASTR + hc;
        float mx = -3.0e38f;
#pragma unroll 16
        for (int c = 0; c < 64; c++) {
            float v = S[c] * scale;
            if (tok[hc + c] > qpos) v = -1e10f;
            mx = fmaxf(mx, v);
        }
        mx = fmaxf(mx, __shfl_xor_sync(0xffffffffu, mx, 1));
        float sum = 0.f;
#pragma unroll 16
        for (int c = 0; c < 64; c++) {
            float v = S[c] * scale;
            if (tok[hc + c] > qpos) v = -1e10f;
            float e = __expf(v - mx);
            sum += e;
            S[c] = e;
        }
        sum += __shfl_xor_sync(0xffffffffu, sum, 1);
        float inv = 1.f / sum;
#pragma unroll 16
        for (int c = 0; c < 64; c++)
            S[c] = tf32r(S[c] * inv);
    }
    __syncthreads();

    float acc2[16][4];
#pragma unroll
    for (int nf = 0; nf < 16; nf++)
#pragma unroll
        for (int rr = 0; rr < 4; rr++) acc2[nf][rr] = 0.f;

#pragma unroll
    for (int kt = 0; kt < 16; kt++) {
        int k8 = kt * 8;
        uint32_t a0 = __float_as_uint(QS[r * ASTR + k8 + kc]);
        uint32_t a1 = __float_as_uint(QS[(r + 8) * ASTR + k8 + kc]);
        uint32_t a2 = __float_as_uint(QS[r * ASTR + k8 + kc + 4]);
        uint32_t a3 = __float_as_uint(QS[(r + 8) * ASTR + k8 + kc + 4]);
#pragma unroll
        for (int nf = 0; nf < 16; nf++) {
            int nr = nf * 8 + gq;
            uint32_t b0 = __float_as_uint(Vt[nr * ASTR + k8 + kc]);
            uint32_t b1 = __float_as_uint(Vt[nr * ASTR + k8 + kc + 4]);
            mma_tf32_16x8x8(acc2[nf][0], acc2[nf][1], acc2[nf][2], acc2[nf][3],
                            a0, a1, a2, a3, b0, b1);
        }
    }

    float* o0 = attout + ((size_t)b * SS + q0 + r) * DD + h * HDIM;
    float* o1 = attout + ((size_t)b * SS + q0 + r + 8) * DD + h * HDIM;
#pragma unroll
    for (int nf = 0; nf < 16; nf++) {
        int col = nf * 8 + kc * 2;
        *(float2*)(o0 + col) = make_float2(tf32r(acc2[nf][0]), tf32r(acc2[nf][1]));
        *(float2*)(o1 + col) = make_float2(tf32r(acc2[nf][2]), tf32r(acc2[nf][3]));
    }
}

// ---------------- launch ----------------
extern "C" void kernel_launch(void* const* d_in, const int* in_sizes, int n_in,
                              void* d_out, int out_size)
{
    const float* x       = (const float*)d_in[0];
    const int*   anchors = (const int*)  d_in[1];
    const float* Wq      = (const float*)d_in[2];
    const float* Wk      = (const float*)d_in[3];
    const float* Wv      = (const float*)d_in[4];
    const float* Wo      = (const float*)d_in[5];
    float* out = (float*)d_out;

    float *qp, *attp, *xrp, *wqtp, *wotp, *wktp, *wvtp;
    cudaGetSymbolAddress((void**)&qp,   g_q);
    cudaGetSymbolAddress((void**)&attp, g_att);
    cudaGetSymbolAddress((void**)&xrp,  g_xr);
    cudaGetSymbolAddress((void**)&wqtp, g_wqt);
    cudaGetSymbolAddress((void**)&wotp, g_wot);
    cudaGetSymbolAddress((void**)&wktp, g_wkt);
    cudaGetSymbolAddress((void**)&wvtp, g_wvt);

    cudaFuncSetAttribute(attn_mma_kernel, cudaFuncAttributeMaxDynamicSharedMemorySize, ATTN_SMEM);
    cudaFuncSetAttribute(gemm256_kernel, cudaFuncAttributeMaxDynamicSharedMemorySize, GEMM_SMEM);
    cudaFuncSetAttribute(sparse_kv_mma_kernel, cudaFuncAttributeMaxDynamicSharedMemorySize, KV_SMEM);

    // prep
    round_tf32_kernel<<<(BB * SS * DD / 4) / 256, 256>>>((const float4*)x, (float4*)xrp);
    transpose_tf32_kernel<<<dim3(64, 64), dim3(32, 8)>>>(Wq, wqtp);
    transpose_tf32_kernel<<<dim3(64, 64), dim3(32, 8)>>>(Wo, wotp);
    transpose_tf32_kernel<<<dim3(64, 64), dim3(32, 8)>>>(Wk, wktp);
    transpose_tf32_kernel<<<dim3(64, 64), dim3(32, 8)>>>(Wv, wvtp);

    // sparse KV (tf32 mma)
    sparse_kv_mma_kernel<<<dim3(64, 2), 256, KV_SMEM>>>(anchors);

    // Q = x @ Wq
    gemm256_kernel<<<dim3(8, 128), 512, GEMM_SMEM>>>(xrp, wqtp, qp);
    // attention
    attn_mma_kernel<<<dim3(32, 64), 256, ATTN_SMEM>>>(anchors, attp);
    // out = att @ Wo
    gemm256_kernel<<<dim3(8, 128), 512, GEMM_SMEM>>>(attp, wotp, out);
}

// round 7
// speedup vs baseline: 3.0775x; 1.0031x over previous
#include <cuda_runtime.h>
#include <cstdint>
#include <math.h>

#define BB 4
#define SS 4096
#define DD 2048
#define HH 16
#define HDIM 128
#define NKEYS 128

// ---------------- scratch ----------------
// Tiled-swizzled operand layout: matrix [R,2048] stored as blocks of 128 rows x 32 cols.
// block(mblk,kblk) base = (mblk*64 + kblk)*4096 floats. Within block, element (r,kcol):
//   off = r*32 + (((kcol>>2) ^ (r&7))<<2) + (kcol&3)
__device__ float g_q  [(size_t)BB * SS * DD];   // normal row-major (attn reads it)
__device__ float g_att[(size_t)BB * SS * DD];   // TILED (GEMM2 A operand)
__device__ float g_xr [(size_t)BB * SS * DD];   // TILED (GEMM1 + sparse_kv A operand)
__device__ float g_wqt[2048 * 2048];            // TILED  [n][k]
__device__ float g_wot[2048 * 2048];            // TILED
__device__ float g_wkt[2048 * 2048];            // TILED
__device__ float g_wvt[2048 * 2048];            // TILED
__device__ float g_ksp[64 * NKEYS * HDIM];      // normal
__device__ float g_vsp[64 * NKEYS * HDIM];      // normal

// ---------------- helpers ----------------
__device__ __forceinline__ uint32_t smem_u32(const void* p) {
    uint32_t a;
    asm("{ .reg .u64 t; cvta.to.shared.u64 t, %1; cvt.u32.u64 %0, t; }" : "=r"(a) : "l"(p));
    return a;
}
__device__ __forceinline__ float tf32r(float x) {
    uint32_t u;
    asm("cvt.rna.tf32.f32 %0, %1;" : "=r"(u) : "f"(x));
    return __uint_as_float(u);
}
__device__ __forceinline__ int swidx(int row, int kcol) {
    return row * 32 + ((((kcol >> 2) ^ (row & 7)) << 2) | (kcol & 3));
}
#define CP_ASYNC16(dst, src) \
    asm volatile("cp.async.cg.shared.global [%0], [%1], 16;" :: "r"(dst), "l"(src) : "memory")
#define CP_COMMIT() asm volatile("cp.async.commit_group;" ::: "memory")
#define CP_WAIT(n)  asm volatile("cp.async.wait_group %0;" :: "n"(n) : "memory")
#define CP_BULK(dst, src, bytes, mbar) \
    asm volatile("cp.async.bulk.shared::cluster.global.mbarrier::complete_tx::bytes [%0], [%1], %2, [%3];" \
        :: "r"(dst), "l"(src), "r"(bytes), "r"(mbar) : "memory")
#define MBARRIER_INIT(addr, cnt) \
    asm volatile("mbarrier.init.shared.b64 [%0], %1;" :: "r"(addr), "r"(cnt) : "memory")
#define MBARRIER_EXPECT_TX(addr, tx) \
    asm volatile("mbarrier.arrive.expect_tx.shared.b64 _, [%0], %1;" :: "r"(addr), "r"(tx) : "memory")
#define MBARRIER_WAIT_PARITY(addr, ph) do { \
    uint32_t _m = (addr), _p = (ph), _d; \
    asm volatile("{\n\t.reg .pred p;\n\t" \
        "mbarrier.try_wait.parity.acquire.cta.shared::cta.b64 p, [%1], %2;\n\t" \
        "selp.b32 %0, 1, 0, p;\n\t}" : "=r"(_d) : "r"(_m), "r"(_p) : "memory"); \
    if (!_d) { \
        asm volatile("{\n\t.reg .pred P1;\n\tWL_%=:\n\t" \
            "mbarrier.try_wait.parity.acquire.cta.shared::cta.b64 P1, [%0], %1, 0x989680;\n\t" \
            "@P1 bra.uni WD_%=;\n\tbra.uni WL_%=;\n\tWD_%=:\n\t}" \
            :: "r"(_m), "r"(_p) : "memory"); \
    } } while (0)

__device__ __forceinline__ void mma_tf32_16x8x8(
    float& c0, float& c1, float& c2, float& c3,
    uint32_t a0, uint32_t a1, uint32_t a2, uint32_t a3,
    uint32_t b0, uint32_t b1)
{
    asm volatile(
        "mma.sync.aligned.m16n8k8.row.col.f32.tf32.tf32.f32 "
        "{%0,%1,%2,%3}, {%4,%5,%6,%7}, {%8,%9}, {%0,%1,%2,%3};"
        : "+f"(c0), "+f"(c1), "+f"(c2), "+f"(c3)
        : "r"(a0), "r"(a1), "r"(a2), "r"(a3), "r"(b0), "r"(b1));
}

// ---------------- prep: round x to tf32, write TILED layout ----------------
__global__ void round_tf32_kernel(const float4* __restrict__ in, float4* __restrict__ out) {
    int i = blockIdx.x * 256 + threadIdx.x;      // float4 index; 512 float4 per row
    float4 v = in[i];
    v.x = tf32r(v.x); v.y = tf32r(v.y); v.z = tf32r(v.z); v.w = tf32r(v.w);
    int m = i >> 9;
    int c4 = i & 511;                             // float4 col; dcol = c4*4
    int kblk = c4 >> 3;
    int chunk = c4 & 7;
    int r = m & 127, mblk = m >> 7;
    out[(size_t)(mblk * 64 + kblk) * 1024 + r * 8 + (chunk ^ (r & 7))] = v;
}

// ---------------- prep: transpose W -> TILED [n][k] tf32 ----------------
__global__ void transpose_tf32_kernel(const float* __restrict__ W, float* __restrict__ WT) {
    __shared__ float t[32][33];
    int n0 = blockIdx.x * 32, k0 = blockIdx.y * 32;
    int tx = threadIdx.x, ty = threadIdx.y;
#pragma unroll
    for (int j = 0; j < 32; j += 8)
        t[ty + j][tx] = W[(size_t)(k0 + ty + j) * 2048 + n0 + tx];
    __syncthreads();
    int kblk = k0 >> 5;
#pragma unroll
    for (int j = 0; j < 32; j += 8) {
        int n = n0 + ty + j;
        int kcol = tx;                            // k = k0 + tx
        int r = n & 127, nblk = n >> 7;
        size_t off = (size_t)(nblk * 64 + kblk) * 4096 +
                     r * 32 + ((((kcol >> 2) ^ (r & 7)) << 2) | (kcol & 3));
        WT[off] = tf32r(t[tx][ty + j]);
    }
}

// ---------------- tf32 GEMM via cp.async.bulk: C[16384,2048] = A @ BW^T ----------------
// A TILED [M,2048]; BW TILED [2048 n][2048 k]; C normal row-major.
// CTA 128(M)x256(N), BK=32, 512 threads (16 warps 4x4, warp 32x64), 4 bulk stages.
#define GSTAGEF 12288                 // floats/stage: (128+256)*32
#define GEMM_SMEM (4 * 49152 + 64)

__global__ __launch_bounds__(512, 1) void gemm256_kernel(
    const float* __restrict__ A, const float* __restrict__ BW, float* __restrict__ C)
{
    extern __shared__ float sh[];
    uint32_t sb = smem_u32(sh);
    uint32_t mb = sb + 4 * 49152;

    int tid = threadIdx.x;
    int wid = tid >> 5, lane = tid & 31;
    int wm = wid >> 2, wn = wid & 3;
    int gq = lane >> 2, kc = lane & 3;
    int n0 = blockIdx.x * 256, m0 = blockIdx.y * 128;

    if (tid == 0) {
#pragma unroll
        for (int s = 0; s < 4; s++) MBARRIER_INIT(mb + 8 * s, 1);
    }
    __syncthreads();

    const float* Ab = A  + (size_t)(m0 >> 7) * 64 * 4096;
    const float* B0 = BW + (size_t)(n0 >> 7) * 64 * 4096;
    const float* B1 = BW + (size_t)((n0 >> 7) + 1) * 64 * 4096;

    if (tid == 0) {
#pragma unroll
        for (int s = 0; s < 3; s++) {
            MBARRIER_EXPECT_TX(mb + 8 * s, 49152);
            CP_BULK(sb + s * 49152,         Ab + (size_t)s * 4096, 16384, mb + 8 * s);
            CP_BULK(sb + s * 49152 + 16384, B0 + (size_t)s * 4096, 16384, mb + 8 * s);
            CP_BULK(sb + s * 49152 + 32768, B1 + (size_t)s * 4096, 16384, mb + 8 * s);
        }
    }

    float acc[2][8][4];
#pragma unroll
    for (int i = 0; i < 2; i++)
#pragma unroll
        for (int j = 0; j < 8; j++)
#pragma unroll
            for (int r = 0; r < 4; r++) acc[i][j][r] = 0.f;

    for (int kt = 0; kt < 64; kt++) {
        int s = kt & 3;
        MBARRIER_WAIT_PARITY(mb + 8 * s, (kt >> 2) & 1);
        const float* As = sh + s * GSTAGEF;
        const float* Bs = As + 4096;
#pragma unroll
        for (int k8 = 0; k8 < 4; k8++) {
            int kb = k8 * 8;
            uint32_t af[2][4], bf[8][2];
#pragma unroll
            for (int mf = 0; mf < 2; mf++) {
                int r = wm * 32 + mf * 16 + gq;
                af[mf][0] = __float_as_uint(As[swidx(r,     kb + kc)]);
                af[mf][1] = __float_as_uint(As[swidx(r + 8, kb + kc)]);
                af[mf][2] = __float_as_uint(As[swidx(r,     kb + kc + 4)]);
                af[mf][3] = __float_as_uint(As[swidx(r + 8, kb + kc + 4)]);
            }
#pragma unroll
            for (int nf = 0; nf < 8; nf++) {
                int nr = wn * 64 + nf * 8 + gq;
                bf[nf][0] = __float_as_uint(Bs[swidx(nr, kb + kc)]);
                bf[nf][1] = __float_as_uint(Bs[swidx(nr, kb + kc + 4)]);
            }
#pragma unroll
            for (int mf = 0; mf < 2; mf++)
#pragma unroll
                for (int nf = 0; nf < 8; nf++)
                    mma_tf32_16x8x8(acc[mf][nf][0], acc[mf][nf][1],
                                    acc[mf][nf][2], acc[mf][nf][3],
                                    af[mf][0], af[mf][1], af[mf][2], af[mf][3],
                                    bf[nf][0], bf[nf][1]);
        }
        __syncthreads();
        if (tid == 0 && kt + 3 < 64) {
            int s2 = (kt + 3) & 3;
            MBARRIER_EXPECT_TX(mb + 8 * s2, 49152);
            CP_BULK(sb + s2 * 49152,         Ab + (size_t)(kt + 3) * 4096, 16384, mb + 8 * s2);
            CP_BULK(sb + s2 * 49152 + 16384, B0 + (size_t)(kt + 3) * 4096, 16384, mb + 8 * s2);
            CP_BULK(sb + s2 * 49152 + 32768, B1 + (size_t)(kt + 3) * 4096, 16384, mb + 8 * s2);
        }
    }

#pragma unroll
    for (int mf = 0; mf < 2; mf++) {
        int r0 = m0 + wm * 32 + mf * 16 + gq;
#pragma unroll
        for (int nf = 0; nf < 8; nf++) {
            int col = n0 + wn * 64 + nf * 8 + kc * 2;
            *(float2*)&C[(size_t)r0 * 2048 + col]       = make_float2(acc[mf][nf][0], acc[mf][nf][1]);
            *(float2*)&C[(size_t)(r0 + 8) * 2048 + col] = make_float2(acc[mf][nf][2], acc[mf][nf][3]);
        }
    }
}

// ---------------- sparse K/V projection via tf32 mma, tiled-gmem reads ----------------
// grid (64 bh, 2 {K,V}); 256 threads (8 warps 2x4, warp 64x32), BK=32, 4 cp.async stages.
#define KVSTAGEF 8192                  // (128+128)*32
#define KV_SMEM (4 * 32768 + 128 * 4)

__global__ __launch_bounds__(256, 1) void sparse_kv_mma_kernel(
    const int* __restrict__ anchors)
{
    extern __shared__ float sh[];
    int* tok = (int*)(sh + 4 * KVSTAGEF);

    int tid = threadIdx.x;
    int bh = blockIdx.x;
    int h = bh & 15, b = bh >> 4;
    const float* WT = blockIdx.y ? g_wvt : g_wkt;
    float* out      = (blockIdx.y ? g_vsp : g_ksp) + (size_t)bh * NKEYS * HDIM;

    if (tid < 128) {
        int ti = tid >> 4;
        int tile = (ti == 7) ? 255 : anchors[(bh << 3) + ti];
        tok[tid] = tile * 16 + (tid & 15);
    }
    __syncthreads();

    int wid = tid >> 5, lane = tid & 31;
    int wm = wid >> 2, wn = wid & 3;
    int gq = lane >> 2, kc = lane & 3;

    uint32_t sb = smem_u32(sh);
    const float* Bb = WT + (size_t)h * 64 * 4096;

    // loader: 1024 16B-chunks per stage (A 1024? A:128x8 + B:128x8 = 2048 chunks / 256 thr = 8)
    // chunk-linear: cidx = i*256+tid, i<4 for A, i<4 for B
    float acc[4][4][4];
#pragma unroll
    for (int i = 0; i < 4; i++)
#pragma unroll
        for (int j = 0; j < 4; j++)
#pragma unroll
            for (int r = 0; r < 4; r++) acc[i][j][r] = 0.f;

#pragma unroll
    for (int s = 0; s < 3; s++) {
        uint32_t so = sb + s * 32768;
#pragma unroll
        for (int i = 0; i < 4; i++) {
            int cidx = i * 256 + tid;
            int rs = cidx >> 3, c = cidx & 7;
            int grow = b * SS + tok[rs];
            const float* srcA = g_xr + (size_t)((grow >> 7) * 64 + s) * 4096
                              + (grow & 127) * 32 + ((c ^ (grow & 7)) << 2);
            CP_ASYNC16(so + (uint32_t)(rs * 32 + ((c ^ (rs & 7)) << 2)) * 4u, srcA);
            const float* srcB = Bb + (size_t)s * 4096 + rs * 32 + ((c ^ (rs & 7)) << 2);
            CP_ASYNC16(so + (uint32_t)(4096 + rs * 32 + ((c ^ (rs & 7)) << 2)) * 4u, srcB);
        }
        CP_COMMIT();
    }

    for (int kt = 0; kt < 64; kt++) {
        CP_WAIT(2);
        __syncthreads();
        if (kt + 3 < 64) {
            int sl = kt + 3;
            uint32_t so = sb + (uint32_t)(sl & 3) * 32768;
#pragma unroll
            for (int i = 0; i < 4; i++) {
                int cidx = i * 256 + tid;
                int rs = cidx >> 3, c = cidx & 7;
                int grow = b * SS + tok[rs];
                const float* srcA = g_xr + (size_t)((grow >> 7) * 64 + sl) * 4096
                                  + (grow & 127) * 32 + ((c ^ (grow & 7)) << 2);
                CP_ASYNC16(so + (uint32_t)(rs * 32 + ((c ^ (rs & 7)) << 2)) * 4u, srcA);
                const float* srcB = Bb + (size_t)sl * 4096 + rs * 32 + ((c ^ (rs & 7)) << 2);
                CP_ASYNC16(so + (uint32_t)(4096 + rs * 32 + ((c ^ (rs & 7)) << 2)) * 4u, srcB);
            }
        }
        CP_COMMIT();

        const float* As = sh + (kt & 3) * KVSTAGEF;
        const float* Bs = As + 4096;
#pragma unroll
        for (int k8 = 0; k8 < 4; k8++) {
            int kb = k8 * 8;
            uint32_t af[4][4], bf[4][2];
#pragma unroll
            for (int mf = 0; mf < 4; mf++) {
                int r = wm * 64 + mf * 16 + gq;
                af[mf][0] = __float_as_uint(As[swidx(r,     kb + kc)]);
                af[mf][1] = __float_as_uint(As[swidx(r + 8, kb + kc)]);
                af[mf][2] = __float_as_uint(As[swidx(r,     kb + kc + 4)]);
                af[mf][3] = __float_as_uint(As[swidx(r + 8, kb + kc + 4)]);
            }
#pragma unroll
            for (int nf = 0; nf < 4; nf++) {
                int nr = wn * 32 + nf * 8 + gq;
                bf[nf][0] = __float_as_uint(Bs[swidx(nr, kb + kc)]);
                bf[nf][1] = __float_as_uint(Bs[swidx(nr, kb + kc + 4)]);
            }
#pragma unroll
            for (int mf = 0; mf < 4; mf++)
#pragma unroll
                for (int nf = 0; nf < 4; nf++)
                    mma_tf32_16x8x8(acc[mf][nf][0], acc[mf][nf][1],
                                    acc[mf][nf][2], acc[mf][nf][3],
                                    af[mf][0], af[mf][1], af[mf][2], af[mf][3],
                                    bf[nf][0], bf[nf][1]);
        }
    }

#pragma unroll
    for (int mf = 0; mf < 4; mf++) {
        int r0 = wm * 64 + mf * 16 + gq;
#pragma unroll
        for (int nf = 0; nf < 4; nf++) {
            int col = wn * 32 + nf * 8 + kc * 2;
            *(float2*)&out[(size_t)r0 * 128 + col]       = make_float2(acc[mf][nf][0], acc[mf][nf][1]);
            *(float2*)&out[(size_t)(r0 + 8) * 128 + col] = make_float2(acc[mf][nf][2], acc[mf][nf][3]);
        }
    }
}

// ---------------- attention: tf32 mma, O written in TILED layout ----------------
#define ASTR 132
#define ATTN_SMEM ((3 * 128 * ASTR) * 4 + 128 * 4)

__global__ __launch_bounds__(256) void attn_mma_kernel(
    const int* __restrict__ anchors, float* __restrict__ attout)
{
    extern __shared__ float sm[];
    float* Ksm = sm;
    float* Vt  = Ksm + 128 * ASTR;
    float* QS  = Vt  + 128 * ASTR;
    int*   tok = (int*)(QS + 128 * ASTR);

    int tid = threadIdx.x;
    int bh = blockIdx.y;
    int b = bh >> 4, h = bh & 15;
    int q0 = blockIdx.x * 128;
    int wid = tid >> 5, lane = tid & 31;
    int gq = lane >> 2, kc = lane & 3;

    if (tid < 128) {
        int ti = tid >> 4;
        int tile = (ti == 7) ? 255 : anchors[(bh << 3) + ti];
        tok[tid] = tile * 16 + (tid & 15);
    }

    const float* kg = g_ksp + (size_t)bh * 16384;
    for (int i = tid; i < 16384; i += 256) {
        int key = i >> 7, d = i & 127;
        Ksm[key * ASTR + d] = tf32r(kg[i]);
    }
    const float* vg = g_vsp + (size_t)bh * 16384;
    for (int idx = tid; idx < 4096; idx += 256) {
        int key = idx >> 5, dq = (idx & 31) * 4;
        float4 v = *(const float4*)(vg + key * 128 + dq);
        Vt[(dq + 0) * ASTR + key] = tf32r(v.x);
        Vt[(dq + 1) * ASTR + key] = tf32r(v.y);
        Vt[(dq + 2) * ASTR + key] = tf32r(v.z);
        Vt[(dq + 3) * ASTR + key] = tf32r(v.w);
    }
    for (int i = tid; i < 16384; i += 256) {
        int q = i >> 7, d = i & 127;
        QS[q * ASTR + d] = tf32r(g_q[((size_t)b * SS + q0 + q) * DD + h * HDIM + d]);
    }
    __syncthreads();

    float acc[16][4];
#pragma unroll
    for (int nf = 0; nf < 16; nf++)
#pragma unroll
        for (int r = 0; r < 4; r++) acc[nf][r] = 0.f;

    int r = wid * 16 + gq;
#pragma unroll
    for (int kt = 0; kt < 16; kt++) {
        int k8 = kt * 8;
        uint32_t a0 = __float_as_uint(QS[r * ASTR + k8 + kc]);
        uint32_t a1 = __float_as_uint(QS[(r + 8) * ASTR + k8 + kc]);
        uint32_t a2 = __float_as_uint(QS[r * ASTR + k8 + kc + 4]);
        uint32_t a3 = __float_as_uint(QS[(r + 8) * ASTR + k8 + kc + 4]);
#pragma unroll
        for (int nf = 0; nf < 16; nf++) {
            int nr = nf * 8 + gq;
            uint32_t b0 = __float_as_uint(Ksm[nr * ASTR + k8 + kc]);
            uint32_t b1 = __float_as_uint(Ksm[nr * ASTR + k8 + kc + 4]);
            mma_tf32_16x8x8(acc[nf][0], acc[nf][1], acc[nf][2], acc[nf][3],
                            a0, a1, a2, a3, b0, b1);
        }
    }
    __syncthreads();
#pragma unroll
    for (int nf = 0; nf < 16; nf++) {
        int col = nf * 8 + kc * 2;
        QS[r * ASTR + col]           = acc[nf][0];
        QS[r * ASTR + col + 1]       = acc[nf][1];
        QS[(r + 8) * ASTR + col]     = acc[nf][2];
        QS[(r + 8) * ASTR + col + 1] = acc[nf][3];
    }
    __syncthreads();

    {
        const float scale = 0.0883883476483184f;
        int row = tid >> 1, hc = (tid & 1) * 64;
        int qpos = q0 + row;
        float* S = QS + row * ASTR + hc;
        float mx = -3.0e38f;
#pragma unroll 16
        for (int c = 0; c < 64; c++) {
            float v = S[c] * scale;
            if (tok[hc + c] > qpos) v = -1e10f;
            mx = fmaxf(mx, v);
        }
        mx = fmaxf(mx, __shfl_xor_sync(0xffffffffu, mx, 1));
        float sum = 0.f;
#pragma unroll 16
        for (int c = 0; c < 64; c++) {
            float v = S[c] * scale;
            if (tok[hc + c] > qpos) v = -1e10f;
            float e = __expf(v - mx);
            sum += e;
            S[c] = e;
        }
        sum += __shfl_xor_sync(0xffffffffu, sum, 1);
        float inv = 1.f / sum;
#pragma unroll 16
        for (int c = 0; c < 64; c++)
            S[c] = tf32r(S[c] * inv);
    }
    __syncthreads();

    float acc2[16][4];
#pragma unroll
    for (int nf = 0; nf < 16; nf++)
#pragma unroll
        for (int rr = 0; rr < 4; rr++) acc2[nf][rr] = 0.f;

#pragma unroll
    for (int kt = 0; kt < 16; kt++) {
        int k8 = kt * 8;
        uint32_t a0 = __float_as_uint(QS[r * ASTR + k8 + kc]);
        uint32_t a1 = __float_as_uint(QS[(r + 8) * ASTR + k8 + kc]);
        uint32_t a2 = __float_as_uint(QS[r * ASTR + k8 + kc + 4]);
        uint32_t a3 = __float_as_uint(QS[(r + 8) * ASTR + k8 + kc + 4]);
#pragma unroll
        for (int nf = 0; nf < 16; nf++) {
            int nr = nf * 8 + gq;
            uint32_t b0 = __float_as_uint(Vt[nr * ASTR + k8 + kc]);
            uint32_t b1 = __float_as_uint(Vt[nr * ASTR + k8 + kc + 4]);
            mma_tf32_16x8x8(acc2[nf][0], acc2[nf][1], acc2[nf][2], acc2[nf][3],
                            a0, a1, a2, a3, b0, b1);
        }
    }

    // store O in TILED layout (GEMM2 A operand), tf32-rounded
    {
        int mblk = (b * SS + q0) >> 7;              // q0, b*SS multiples of 128
        float* abase = attout + (size_t)mblk * 64 * 4096;
#pragma unroll
        for (int nf = 0; nf < 16; nf++) {
            int col = h * HDIM + nf * 8 + kc * 2;
            int kblk = col >> 5, kcol = col & 31;
            int chunk = kcol >> 2;
            int pc = (chunk ^ gq) << 2;             // r&7 == (r+8)&7 == gq
            size_t o0 = (size_t)kblk * 4096 + r * 32 + pc + (kcol & 3);
            size_t o1 = (size_t)kblk * 4096 + (r + 8) * 32 + pc + (kcol & 3);
            *(float2*)(abase + o0) = make_float2(tf32r(acc2[nf][0]), tf32r(acc2[nf][1]));
            *(float2*)(abase + o1) = make_float2(tf32r(acc2[nf][2]), tf32r(acc2[nf][3]));
        }
    }
}

// ---------------- launch ----------------
extern "C" void kernel_launch(void* const* d_in, const int* in_sizes, int n_in,
                              void* d_out, int out_size)
{
    const float* x       = (const float*)d_in[0];
    const int*   anchors = (const int*)  d_in[1];
    const float* Wq      = (const float*)d_in[2];
    const float* Wk      = (const float*)d_in[3];
    const float* Wv      = (const float*)d_in[4];
    const float* Wo      = (const float*)d_in[5];
    float* out = (float*)d_out;

    float *qp, *attp, *xrp, *wqtp, *wotp, *wktp, *wvtp;
    cudaGetSymbolAddress((void**)&qp,   g_q);
    cudaGetSymbolAddress((void**)&attp, g_att);
    cudaGetSymbolAddress((void**)&xrp,  g_xr);
    cudaGetSymbolAddress((void**)&wqtp, g_wqt);
    cudaGetSymbolAddress((void**)&wotp, g_wot);
    cudaGetSymbolAddress((void**)&wktp, g_wkt);
    cudaGetSymbolAddress((void**)&wvtp, g_wvt);

    cudaFuncSetAttribute(attn_mma_kernel, cudaFuncAttributeMaxDynamicSharedMemorySize, ATTN_SMEM);
    cudaFuncSetAttribute(gemm256_kernel, cudaFuncAttributeMaxDynamicSharedMemorySize, GEMM_SMEM);
    cudaFuncSetAttribute(sparse_kv_mma_kernel, cudaFuncAttributeMaxDynamicSharedMemorySize, KV_SMEM);

    // prep (tiled-swizzled operands)
    round_tf32_kernel<<<(BB * SS * DD / 4) / 256, 256>>>((const float4*)x, (float4*)xrp);
    transpose_tf32_kernel<<<dim3(64, 64), dim3(32, 8)>>>(Wq, wqtp);
    transpose_tf32_kernel<<<dim3(64, 64), dim3(32, 8)>>>(Wo, wotp);
    transpose_tf32_kernel<<<dim3(64, 64), dim3(32, 8)>>>(Wk, wktp);
    transpose_tf32_kernel<<<dim3(64, 64), dim3(32, 8)>>>(Wv, wvtp);

    // sparse KV (tf32 mma)
    sparse_kv_mma_kernel<<<dim3(64, 2), 256, KV_SMEM>>>(anchors);

    // Q = x @ Wq  (bulk-fed tf32 mma)
    gemm256_kernel<<<dim3(8, 128), 512, GEMM_SMEM>>>(xrp, wqtp, qp);
    // attention
    attn_mma_kernel<<<dim3(32, 64), 256, ATTN_SMEM>>>(anchors, attp);
    // out = att @ Wo
    gemm256_kernel<<<dim3(8, 128), 512, GEMM_SMEM>>>(attp, wotp, out);
}

// round 8
// speedup vs baseline: 5.3232x; 1.7297x over previous
#include <cuda_runtime.h>
#include <cuda_fp16.h>
#include <cstdint>
#include <math.h>

#define BB 4
#define SS 4096
#define DD 2048
#define HH 16
#define HDIM 128
#define NKEYS 128

// ---------------- scratch ----------------
// Half tiled layout for [R,2048]: blocks of 128 rows x 32 kcols (4096 halves = 8KB).
// element (row,kcol): mblk=row>>7, r=row&127, kblk=kcol>>5, c=kcol&31,
//   g=c>>1, phys=g^(((r>>1)&3)<<2), off = (mblk*64+kblk)*4096 + r*32 + phys*2 + (c&1)
__device__ float  g_q  [(size_t)BB * SS * DD];   // fp32 row-major (attn reads)
__device__ __half g_att[(size_t)BB * SS * DD];   // half TILED (GEMM2 A)
__device__ __half g_xh [(size_t)BB * SS * DD];   // half TILED (GEMM1 + kv A)
__device__ __half g_wqt[2048 * 2048];            // half TILED [n][k]
__device__ __half g_wot[2048 * 2048];
__device__ __half g_wkt[2048 * 2048];
__device__ __half g_wvt[2048 * 2048];
__device__ float  g_ksp[64 * NKEYS * HDIM];      // fp32
__device__ float  g_vsp[64 * NKEYS * HDIM];      // fp32

// ---------------- helpers ----------------
__device__ __forceinline__ uint32_t smem_u32(const void* p) {
    uint32_t a;
    asm("{ .reg .u64 t; cvta.to.shared.u64 t, %1; cvt.u32.u64 %0, t; }" : "=r"(a) : "l"(p));
    return a;
}
__device__ __forceinline__ float tf32r(float x) {
    uint32_t u;
    asm("cvt.rna.tf32.f32 %0, %1;" : "=r"(u) : "f"(x));
    return __uint_as_float(u);
}
// half2 (one b32) at logical granule g of row r inside a half-tiled block image
__device__ __forceinline__ uint32_t ldh2(const __half* blk, int r, int g) {
    int phys = g ^ (((r >> 1) & 3) << 2);
    return *(const uint32_t*)(blk + r * 32 + phys * 2);
}
#define CP_ASYNC16(dst, src) \
    asm volatile("cp.async.cg.shared.global [%0], [%1], 16;" :: "r"(dst), "l"(src) : "memory")
#define CP_COMMIT() asm volatile("cp.async.commit_group;" ::: "memory")
#define CP_WAIT(n)  asm volatile("cp.async.wait_group %0;" :: "n"(n) : "memory")
#define CP_BULK(dst, src, bytes, mbar) \
    asm volatile("cp.async.bulk.shared::cluster.global.mbarrier::complete_tx::bytes [%0], [%1], %2, [%3];" \
        :: "r"(dst), "l"(src), "r"(bytes), "r"(mbar) : "memory")
#define MBARRIER_INIT(addr, cnt) \
    asm volatile("mbarrier.init.shared.b64 [%0], %1;" :: "r"(addr), "r"(cnt) : "memory")
#define MBARRIER_EXPECT_TX(addr, tx) \
    asm volatile("mbarrier.arrive.expect_tx.shared.b64 _, [%0], %1;" :: "r"(addr), "r"(tx) : "memory")
#define MBARRIER_WAIT_PARITY(addr, ph) do { \
    uint32_t _m = (addr), _p = (ph), _d; \
    asm volatile("{\n\t.reg .pred p;\n\t" \
        "mbarrier.try_wait.parity.acquire.cta.shared::cta.b64 p, [%1], %2;\n\t" \
        "selp.b32 %0, 1, 0, p;\n\t}" : "=r"(_d) : "r"(_m), "r"(_p) : "memory"); \
    if (!_d) { \
        asm volatile("{\n\t.reg .pred P1;\n\tWL_%=:\n\t" \
            "mbarrier.try_wait.parity.acquire.cta.shared::cta.b64 P1, [%0], %1, 0x989680;\n\t" \
            "@P1 bra.uni WD_%=;\n\tbra.uni WL_%=;\n\tWD_%=:\n\t}" \
            :: "r"(_m), "r"(_p) : "memory"); \
    } } while (0)

__device__ __forceinline__ void mma_f16_16x8x16(
    float& c0, float& c1, float& c2, float& c3,
    uint32_t a0, uint32_t a1, uint32_t a2, uint32_t a3,
    uint32_t b0, uint32_t b1)
{
    asm volatile(
        "mma.sync.aligned.m16n8k16.row.col.f32.f16.f16.f32 "
        "{%0,%1,%2,%3}, {%4,%5,%6,%7}, {%8,%9}, {%0,%1,%2,%3};"
        : "+f"(c0), "+f"(c1), "+f"(c2), "+f"(c3)
        : "r"(a0), "r"(a1), "r"(a2), "r"(a3), "r"(b0), "r"(b1));
}
__device__ __forceinline__ void mma_tf32_16x8x8(
    float& c0, float& c1, float& c2, float& c3,
    uint32_t a0, uint32_t a1, uint32_t a2, uint32_t a3,
    uint32_t b0, uint32_t b1)
{
    asm volatile(
        "mma.sync.aligned.m16n8k8.row.col.f32.tf32.tf32.f32 "
        "{%0,%1,%2,%3}, {%4,%5,%6,%7}, {%8,%9}, {%0,%1,%2,%3};"
        : "+f"(c0), "+f"(c1), "+f"(c2), "+f"(c3)
        : "r"(a0), "r"(a1), "r"(a2), "r"(a3), "r"(b0), "r"(b1));
}

// ---------------- prep: x -> half TILED ----------------
__global__ void round_half_kernel(const float4* __restrict__ in, __half* __restrict__ out) {
    int i = blockIdx.x * 256 + threadIdx.x;       // float4 index
    float4 v = in[i];
    int m = i >> 9, c4 = i & 511;
    int kblk = c4 >> 3;
    int g0 = (c4 & 7) * 2;                        // even logical granule
    int r = m & 127, mblk = m >> 7;
    int phys = g0 ^ (((r >> 1) & 3) << 2);
    __half2* dst = (__half2*)(out + ((size_t)(mblk * 64 + kblk) * 4096 + r * 32 + phys * 2));
    dst[0] = __floats2half2_rn(v.x, v.y);
    dst[1] = __floats2half2_rn(v.z, v.w);
}

// ---------------- prep: W -> half TILED [n][k] ----------------
__global__ void transpose_half_kernel(const float* __restrict__ W, __half* __restrict__ WT) {
    __shared__ float t[32][33];
    int n0 = blockIdx.x * 32, k0 = blockIdx.y * 32;
    int tx = threadIdx.x, ty = threadIdx.y;
#pragma unroll
    for (int j = 0; j < 32; j += 8)
        t[ty + j][tx] = W[(size_t)(k0 + ty + j) * 2048 + n0 + tx];
    __syncthreads();
    int kblk = k0 >> 5;
#pragma unroll
    for (int j = 0; j < 32; j += 8) {
        int n = n0 + ty + j;
        int kcol = tx;
        int r = n & 127, nblk = n >> 7;
        int g = kcol >> 1, phys = g ^ (((r >> 1) & 3) << 2);
        WT[(size_t)(nblk * 64 + kblk) * 4096 + r * 32 + phys * 2 + (kcol & 1)] =
            __float2half_rn(t[tx][ty + j]);
    }
}

// ---------------- fp16 GEMM via cp.async.bulk: C[16384,2048] = A @ BW^T ----------------
// CTA 128(M)x256(N), BK=32, 512 threads (16 warps 4x4, warp 32x64), 4 bulk stages.
#define GSTAGE_B 24576                // bytes/stage: (128+256)*32*2
#define GSTAGE_H 12288
#define GEMM_SMEM (4 * GSTAGE_B + 64)

__global__ __launch_bounds__(512, 1) void gemm256_kernel(
    const __half* __restrict__ A, const __half* __restrict__ BW, float* __restrict__ C)
{
    extern __shared__ __half shh[];
    uint32_t sb = smem_u32(shh);
    uint32_t mb = sb + 4 * GSTAGE_B;

    int tid = threadIdx.x;
    int wid = tid >> 5, lane = tid & 31;
    int wm = wid >> 2, wn = wid & 3;
    int gq = lane >> 2, kc = lane & 3;
    int n0 = blockIdx.x * 256, m0 = blockIdx.y * 128;

    if (tid == 0) {
#pragma unroll
        for (int s = 0; s < 4; s++) MBARRIER_INIT(mb + 8 * s, 1);
    }
    __syncthreads();

    const __half* Ab = A  + (size_t)(m0 >> 7) * 64 * 4096;
    const __half* B0 = BW + (size_t)(n0 >> 7) * 64 * 4096;
    const __half* B1 = BW + (size_t)((n0 >> 7) + 1) * 64 * 4096;

    if (tid == 0) {
#pragma unroll
        for (int s = 0; s < 3; s++) {
            MBARRIER_EXPECT_TX(mb + 8 * s, GSTAGE_B);
            CP_BULK(sb + s * GSTAGE_B,         Ab + (size_t)s * 4096, 8192, mb + 8 * s);
            CP_BULK(sb + s * GSTAGE_B + 8192,  B0 + (size_t)s * 4096, 8192, mb + 8 * s);
            CP_BULK(sb + s * GSTAGE_B + 16384, B1 + (size_t)s * 4096, 8192, mb + 8 * s);
        }
    }

    float acc[2][8][4];
#pragma unroll
    for (int i = 0; i < 2; i++)
#pragma unroll
        for (int j = 0; j < 8; j++)
#pragma unroll
            for (int r = 0; r < 4; r++) acc[i][j][r] = 0.f;

    for (int kt = 0; kt < 64; kt++) {
        int s = kt & 3;
        MBARRIER_WAIT_PARITY(mb + 8 * s, (kt >> 2) & 1);
        const __half* As = shh + (size_t)s * GSTAGE_H;
        const __half* Bs = As + 4096;     // rows 0..255 contiguous across B0|B1
#pragma unroll
        for (int t = 0; t < 2; t++) {
            int gb = t * 8;
            uint32_t af[2][4], bf[8][2];
#pragma unroll
            for (int mf = 0; mf < 2; mf++) {
                int r = wm * 32 + mf * 16 + gq;
                af[mf][0] = ldh2(As, r,     gb + kc);
                af[mf][1] = ldh2(As, r + 8, gb + kc);
                af[mf][2] = ldh2(As, r,     gb + kc + 4);
                af[mf][3] = ldh2(As, r + 8, gb + kc + 4);
            }
#pragma unroll
            for (int nf = 0; nf < 8; nf++) {
                int nr = wn * 64 + nf * 8 + gq;
                bf[nf][0] = ldh2(Bs, nr, gb + kc);
                bf[nf][1] = ldh2(Bs, nr, gb + kc + 4);
            }
#pragma unroll
            for (int mf = 0; mf < 2; mf++)
#pragma unroll
                for (int nf = 0; nf < 8; nf++)
                    mma_f16_16x8x16(acc[mf][nf][0], acc[mf][nf][1],
                                    acc[mf][nf][2], acc[mf][nf][3],
                                    af[mf][0], af[mf][1], af[mf][2], af[mf][3],
                                    bf[nf][0], bf[nf][1]);
        }
        __syncthreads();
        if (tid == 0 && kt + 3 < 64) {
            int s2 = (kt + 3) & 3;
            MBARRIER_EXPECT_TX(mb + 8 * s2, GSTAGE_B);
            CP_BULK(sb + s2 * GSTAGE_B,         Ab + (size_t)(kt + 3) * 4096, 8192, mb + 8 * s2);
            CP_BULK(sb + s2 * GSTAGE_B + 8192,  B0 + (size_t)(kt + 3) * 4096, 8192, mb + 8 * s2);
            CP_BULK(sb + s2 * GSTAGE_B + 16384, B1 + (size_t)(kt + 3) * 4096, 8192, mb + 8 * s2);
        }
    }

#pragma unroll
    for (int mf = 0; mf < 2; mf++) {
        int r0 = m0 + wm * 32 + mf * 16 + gq;
#pragma unroll
        for (int nf = 0; nf < 8; nf++) {
            int col = n0 + wn * 64 + nf * 8 + kc * 2;
            *(float2*)&C[(size_t)r0 * 2048 + col]       = make_float2(acc[mf][nf][0], acc[mf][nf][1]);
            *(float2*)&C[(size_t)(r0 + 8) * 2048 + col] = make_float2(acc[mf][nf][2], acc[mf][nf][3]);
        }
    }
}

// ---------------- sparse K/V projection (fp16 mma, gathered tiled reads) ----------------
#define KVSTAGE_B 16384               // (128+128)*32*2
#define KVSTAGE_H 8192
#define KV_SMEM (4 * KVSTAGE_B + 128 * 4)

__global__ __launch_bounds__(256, 1) void sparse_kv_mma_kernel(
    const int* __restrict__ anchors)
{
    extern __shared__ __half shh[];
    int* tok = (int*)(shh + 4 * KVSTAGE_H);

    int tid = threadIdx.x;
    int bh = blockIdx.x;
    int h = bh & 15, b = bh >> 4;
    const __half* Bb = (blockIdx.y ? g_wvt : g_wkt) + (size_t)h * 64 * 4096;
    float* out = (blockIdx.y ? g_vsp : g_ksp) + (size_t)bh * NKEYS * HDIM;

    if (tid < 128) {
        int ti = tid >> 4;
        int tile = (ti == 7) ? 255 : anchors[(bh << 3) + ti];
        tok[tid] = tile * 16 + (tid & 15);
    }
    __syncthreads();

    int wid = tid >> 5, lane = tid & 31;
    int wm = wid >> 2, wn = wid & 3;       // 2x4 warps, warp 64x32
    int gq = lane >> 2, kc = lane & 3;

    uint32_t sb = smem_u32(shh);

    float acc[4][4][4];
#pragma unroll
    for (int i = 0; i < 4; i++)
#pragma unroll
        for (int j = 0; j < 4; j++)
#pragma unroll
            for (int r = 0; r < 4; r++) acc[i][j][r] = 0.f;

    // loader: per stage 1024 16B chunks (A 512, B 512) -> 4/thread
#pragma unroll
    for (int s = 0; s < 3; s++) {
        uint32_t so = sb + s * KVSTAGE_B;
#pragma unroll
        for (int i = 0; i < 2; i++) {
            int cidx = i * 256 + tid;
            int rs = cidx >> 2, c = cidx & 3;
            int grow = b * SS + tok[rs];
            const __half* srcA = g_xh + (size_t)((grow >> 7) * 64 + s) * 4096
                               + (grow & 127) * 32 + ((c ^ ((grow >> 1) & 3)) * 8);
            CP_ASYNC16(so + (uint32_t)(rs * 64 + (c ^ ((rs >> 1) & 3)) * 16), srcA);
            const __half* srcB = Bb + (size_t)s * 4096 + rs * 32 + ((c ^ ((rs >> 1) & 3)) * 8);
            CP_ASYNC16(so + 8192 + (uint32_t)(rs * 64 + (c ^ ((rs >> 1) & 3)) * 16), srcB);
        }
        CP_COMMIT();
    }

    for (int kt = 0; kt < 64; kt++) {
        CP_WAIT(2);
        __syncthreads();
        if (kt + 3 < 64) {
            int sl = kt + 3;
            uint32_t so = sb + (uint32_t)(sl & 3) * KVSTAGE_B;
#pragma unroll
            for (int i = 0; i < 2; i++) {
                int cidx = i * 256 + tid;
                int rs = cidx >> 2, c = cidx & 3;
                int grow = b * SS + tok[rs];
                const __half* srcA = g_xh + (size_t)((grow >> 7) * 64 + sl) * 4096
                                   + (grow & 127) * 32 + ((c ^ ((grow >> 1) & 3)) * 8);
                CP_ASYNC16(so + (uint32_t)(rs * 64 + (c ^ ((rs >> 1) & 3)) * 16), srcA);
                const __half* srcB = Bb + (size_t)sl * 4096 + rs * 32 + ((c ^ ((rs >> 1) & 3)) * 8);
                CP_ASYNC16(so + 8192 + (uint32_t)(rs * 64 + (c ^ ((rs >> 1) & 3)) * 16), srcB);
            }
        }
        CP_COMMIT();

        const __half* As = shh + (size_t)(kt & 3) * KVSTAGE_H;
        const __half* Bs = As + 4096;
#pragma unroll
        for (int t = 0; t < 2; t++) {
            int gb = t * 8;
            uint32_t af[4][4], bf[4][2];
#pragma unroll
            for (int mf = 0; mf < 4; mf++) {
                int r = wm * 64 + mf * 16 + gq;
                af[mf][0] = ldh2(As, r,     gb + kc);
                af[mf][1] = ldh2(As, r + 8, gb + kc);
                af[mf][2] = ldh2(As, r,     gb + kc + 4);
                af[mf][3] = ldh2(As, r + 8, gb + kc + 4);
            }
#pragma unroll
            for (int nf = 0; nf < 4; nf++) {
                int nr = wn * 32 + nf * 8 + gq;
                bf[nf][0] = ldh2(Bs, nr, gb + kc);
                bf[nf][1] = ldh2(Bs, nr, gb + kc + 4);
            }
#pragma unroll
            for (int mf = 0; mf < 4; mf++)
#pragma unroll
                for (int nf = 0; nf < 4; nf++)
                    mma_f16_16x8x16(acc[mf][nf][0], acc[mf][nf][1],
                                    acc[mf][nf][2], acc[mf][nf][3],
                                    af[mf][0], af[mf][1], af[mf][2], af[mf][3],
                                    bf[nf][0], bf[nf][1]);
        }
    }

#pragma unroll
    for (int mf = 0; mf < 4; mf++) {
        int r0 = wm * 64 + mf * 16 + gq;
#pragma unroll
        for (int nf = 0; nf < 4; nf++) {
            int col = wn * 32 + nf * 8 + kc * 2;
            *(float2*)&out[(size_t)r0 * 128 + col]       = make_float2(acc[mf][nf][0], acc[mf][nf][1]);
            *(float2*)&out[(size_t)(r0 + 8) * 128 + col] = make_float2(acc[mf][nf][2], acc[mf][nf][3]);
        }
    }
}

// ---------------- attention: tf32 mma internally, epilogue -> half TILED ----------------
#define ASTR 132
#define ATTN_SMEM ((3 * 128 * ASTR) * 4 + 128 * 4)

__global__ __launch_bounds__(256) void attn_mma_kernel(
    const int* __restrict__ anchors, __half* __restrict__ attout)
{
    extern __shared__ float sm[];
    float* Ksm = sm;
    float* Vt  = Ksm + 128 * ASTR;
    float* QS  = Vt  + 128 * ASTR;
    int*   tok = (int*)(QS + 128 * ASTR);

    int tid = threadIdx.x;
    int bh = blockIdx.y;
    int b = bh >> 4, h = bh & 15;
    int q0 = blockIdx.x * 128;
    int wid = tid >> 5, lane = tid & 31;
    int gq = lane >> 2, kc = lane & 3;

    if (tid < 128) {
        int ti = tid >> 4;
        int tile = (ti == 7) ? 255 : anchors[(bh << 3) + ti];
        tok[tid] = tile * 16 + (tid & 15);
    }

    const float* kg = g_ksp + (size_t)bh * 16384;
    for (int i = tid; i < 16384; i += 256) {
        int key = i >> 7, d = i & 127;
        Ksm[key * ASTR + d] = tf32r(kg[i]);
    }
    const float* vg = g_vsp + (size_t)bh * 16384;
    for (int idx = tid; idx < 4096; idx += 256) {
        int key = idx >> 5, dq = (idx & 31) * 4;
        float4 v = *(const float4*)(vg + key * 128 + dq);
        Vt[(dq + 0) * ASTR + key] = tf32r(v.x);
        Vt[(dq + 1) * ASTR + key] = tf32r(v.y);
        Vt[(dq + 2) * ASTR + key] = tf32r(v.z);
        Vt[(dq + 3) * ASTR + key] = tf32r(v.w);
    }
    for (int i = tid; i < 16384; i += 256) {
        int q = i >> 7, d = i & 127;
        QS[q * ASTR + d] = tf32r(g_q[((size_t)b * SS + q0 + q) * DD + h * HDIM + d]);
    }
    __syncthreads();

    float acc[16][4];
#pragma unroll
    for (int nf = 0; nf < 16; nf++)
#pragma unroll
        for (int r = 0; r < 4; r++) acc[nf][r] = 0.f;

    int r = wid * 16 + gq;
#pragma unroll
    for (int kt = 0; kt < 16; kt++) {
        int k8 = kt * 8;
        uint32_t a0 = __float_as_uint(QS[r * ASTR + k8 + kc]);
        uint32_t a1 = __float_as_uint(QS[(r + 8) * ASTR + k8 + kc]);
        uint32_t a2 = __float_as_uint(QS[r * ASTR + k8 + kc + 4]);
        uint32_t a3 = __float_as_uint(QS[(r + 8) * ASTR + k8 + kc + 4]);
#pragma unroll
        for (int nf = 0; nf < 16; nf++) {
            int nr = nf * 8 + gq;
            uint32_t b0 = __float_as_uint(Ksm[nr * ASTR + k8 + kc]);
            uint32_t b1 = __float_as_uint(Ksm[nr * ASTR + k8 + kc + 4]);
            mma_tf32_16x8x8(acc[nf][0], acc[nf][1], acc[nf][2], acc[nf][3],
                            a0, a1, a2, a3, b0, b1);
        }
    }
    __syncthreads();
#pragma unroll
    for (int nf = 0; nf < 16; nf++) {
        int col = nf * 8 + kc * 2;
        QS[r * ASTR + col]           = acc[nf][0];
        QS[r * ASTR + col + 1]       = acc[nf][1];
        QS[(r + 8) * ASTR + col]     = acc[nf][2];
        QS[(r + 8) * ASTR + col + 1] = acc[nf][3];
    }
    __syncthreads();

    {
        const float scale = 0.0883883476483184f;
        int row = tid >> 1, hc = (tid & 1) * 64;
        int qpos = q0 + row;
        float* S = QS + row * ASTR + hc;
        float mx = -3.0e38f;
#pragma unroll 16
        for (int c = 0; c < 64; c++) {
            float v = S[c] * scale;
            if (tok[hc + c] > qpos) v = -1e10f;
            mx = fmaxf(mx, v);
        }
        mx = fmaxf(mx, __shfl_xor_sync(0xffffffffu, mx, 1));
        float sum = 0.f;
#pragma unroll 16
        for (int c = 0; c < 64; c++) {
            float v = S[c] * scale;
            if (tok[hc + c] > qpos) v = -1e10f;
            float e = __expf(v - mx);
            sum += e;
            S[c] = e;
        }
        sum += __shfl_xor_sync(0xffffffffu, sum, 1);
        float inv = 1.f / sum;
#pragma unroll 16
        for (int c = 0; c < 64; c++)
            S[c] = tf32r(S[c] * inv);
    }
    __syncthreads();

    float acc2[16][4];
#pragma unroll
    for (int nf = 0; nf < 16; nf++)
#pragma unroll
        for (int rr = 0; rr < 4; rr++) acc2[nf][rr] = 0.f;

#pragma unroll
    for (int kt = 0; kt < 16; kt++) {
        int k8 = kt * 8;
        uint32_t a0 = __float_as_uint(QS[r * ASTR + k8 + kc]);
        uint32_t a1 = __float_as_uint(QS[(r + 8) * ASTR + k8 + kc]);
        uint32_t a2 = __float_as_uint(QS[r * ASTR + k8 + kc + 4]);
        uint32_t a3 = __float_as_uint(QS[(r + 8) * ASTR + k8 + kc + 4]);
#pragma unroll
        for (int nf = 0; nf < 16; nf++) {
            int nr = nf * 8 + gq;
            uint32_t b0 = __float_as_uint(Vt[nr * ASTR + k8 + kc]);
            uint32_t b1 = __float_as_uint(Vt[nr * ASTR + k8 + kc + 4]);
            mma_tf32_16x8x8(acc2[nf][0], acc2[nf][1], acc2[nf][2], acc2[nf][3],
                            a0, a1, a2, a3, b0, b1);
        }
    }

    // store O in half TILED layout (GEMM2 A operand)
    {
        int mblk = (b * SS + q0) >> 7;
        __half* abase = attout + (size_t)mblk * 64 * 4096;
        int sw = ((r >> 1) & 3) << 2;           // same for r and r+8
#pragma unroll
        for (int nf = 0; nf < 16; nf++) {
            int col = h * HDIM + nf * 8 + kc * 2;
            int kblk = col >> 5, kcol = col & 31;
            int phys = (kcol >> 1) ^ sw;
            *(__half2*)(abase + (size_t)kblk * 4096 + r * 32 + phys * 2) =
                __floats2half2_rn(acc2[nf][0], acc2[nf][1]);
            *(__half2*)(abase + (size_t)kblk * 4096 + (r + 8) * 32 + phys * 2) =
                __floats2half2_rn(acc2[nf][2], acc2[nf][3]);
        }
    }
}

// ---------------- launch ----------------
extern "C" void kernel_launch(void* const* d_in, const int* in_sizes, int n_in,
                              void* d_out, int out_size)
{
    const float* x       = (const float*)d_in[0];
    const int*   anchors = (const int*)  d_in[1];
    const float* Wq      = (const float*)d_in[2];
    const float* Wk      = (const float*)d_in[3];
    const float* Wv      = (const float*)d_in[4];
    const float* Wo      = (const float*)d_in[5];
    float* out = (float*)d_out;

    float *qp;
    __half *attp, *xhp, *wqtp, *wotp, *wktp, *wvtp;
    cudaGetSymbolAddress((void**)&qp,   g_q);
    cudaGetSymbolAddress((void**)&attp, g_att);
    cudaGetSymbolAddress((void**)&xhp,  g_xh);
    cudaGetSymbolAddress((void**)&wqtp, g_wqt);
    cudaGetSymbolAddress((void**)&wotp, g_wot);
    cudaGetSymbolAddress((void**)&wktp, g_wkt);
    cudaGetSymbolAddress((void**)&wvtp, g_wvt);

    cudaFuncSetAttribute(attn_mma_kernel, cudaFuncAttributeMaxDynamicSharedMemorySize, ATTN_SMEM);
    cudaFuncSetAttribute(gemm256_kernel, cudaFuncAttributeMaxDynamicSharedMemorySize, GEMM_SMEM);
    cudaFuncSetAttribute(sparse_kv_mma_kernel, cudaFuncAttributeMaxDynamicSharedMemorySize, KV_SMEM);

    // prep (half tiled operands)
    round_half_kernel<<<(BB * SS * DD / 4) / 256, 256>>>((const float4*)x, xhp);
    transpose_half_kernel<<<dim3(64, 64), dim3(32, 8)>>>(Wq, wqtp);
    transpose_half_kernel<<<dim3(64, 64), dim3(32, 8)>>>(Wo, wotp);
    transpose_half_kernel<<<dim3(64, 64), dim3(32, 8)>>>(Wk, wktp);
    transpose_half_kernel<<<dim3(64, 64), dim3(32, 8)>>>(Wv, wvtp);

    // sparse KV (fp16 mma)
    sparse_kv_mma_kernel<<<dim3(64, 2), 256, KV_SMEM>>>(anchors);

    // Q = x @ Wq  (fp16 mma, bulk-fed)
    gemm256_kernel<<<dim3(8, 128), 512, GEMM_SMEM>>>(xhp, wqtp, qp);
    // attention
    attn_mma_kernel<<<dim3(32, 64), 256, ATTN_SMEM>>>(anchors, attp);
    // out = att @ Wo
    gemm256_kernel<<<dim3(8, 128), 512, GEMM_SMEM>>>(attp, wotp, out);
}

// round 9
// speedup vs baseline: 5.9453x; 1.1169x over previous
#include <cuda_runtime.h>
#include <cuda_fp16.h>
#include <cstdint>
#include <math.h>

#define BB 4
#define SS 4096
#define DD 2048
#define HH 16
#define HDIM 128
#define NKEYS 128

// ---------------- scratch ----------------
// Half tiled layout for [R,2048]: blocks of 128 rows x 32 kcols (4096 halves).
// element (row,kcol): mblk=row>>7, r=row&127, kblk=kcol>>5, c=kcol&31,
//   g=c>>1, phys=g^(((r>>1)&3)<<2), off = (mblk*64+kblk)*4096 + r*32 + phys*2 + (c&1)
__device__ float  g_q  [(size_t)BB * SS * DD];   // fp32 row-major (attn reads)
__device__ __half g_att[(size_t)BB * SS * DD];   // half TILED (GEMM2 A)
__device__ __half g_xh [(size_t)BB * SS * DD];   // half TILED (GEMM1 + kv A)
__device__ __half g_wqt[2048 * 2048];            // half TILED [n][k]
__device__ __half g_wot[2048 * 2048];
__device__ __half g_wkt[2048 * 2048];
__device__ __half g_wvt[2048 * 2048];
__device__ float  g_ksp[64 * NKEYS * HDIM];      // fp32
__device__ float  g_vsp[64 * NKEYS * HDIM];      // fp32

// ---------------- helpers ----------------
__device__ __forceinline__ uint32_t smem_u32(const void* p) {
    uint32_t a;
    asm("{ .reg .u64 t; cvta.to.shared.u64 t, %1; cvt.u32.u64 %0, t; }" : "=r"(a) : "l"(p));
    return a;
}
// 64B-row tiled block load (GEMM smem images)
__device__ __forceinline__ uint32_t ldh2(const __half* blk, int r, int g) {
    int phys = g ^ (((r >> 1) & 3) << 2);
    return *(const uint32_t*)(blk + r * 32 + phys * 2);
}
// 256B-row swizzled load (attention smem: 128 halves/row, phys = g ^ ((r&7)<<2))
__device__ __forceinline__ uint32_t ldh2a(const __half* base, int r, int g) {
    int phys = g ^ ((r & 7) << 2);
    return *(const uint32_t*)(base + r * 128 + phys * 2);
}
#define CP_ASYNC16(dst, src) \
    asm volatile("cp.async.cg.shared.global [%0], [%1], 16;" :: "r"(dst), "l"(src) : "memory")
#define CP_COMMIT() asm volatile("cp.async.commit_group;" ::: "memory")
#define CP_WAIT(n)  asm volatile("cp.async.wait_group %0;" :: "n"(n) : "memory")
#define CP_BULK(dst, src, bytes, mbar) \
    asm volatile("cp.async.bulk.shared::cluster.global.mbarrier::complete_tx::bytes [%0], [%1], %2, [%3];" \
        :: "r"(dst), "l"(src), "r"(bytes), "r"(mbar) : "memory")
#define MBARRIER_INIT(addr, cnt) \
    asm volatile("mbarrier.init.shared.b64 [%0], %1;" :: "r"(addr), "r"(cnt) : "memory")
#define MBARRIER_EXPECT_TX(addr, tx) \
    asm volatile("mbarrier.arrive.expect_tx.shared.b64 _, [%0], %1;" :: "r"(addr), "r"(tx) : "memory")
#define MBARRIER_WAIT_PARITY(addr, ph) do { \
    uint32_t _m = (addr), _p = (ph), _d; \
    asm volatile("{\n\t.reg .pred p;\n\t" \
        "mbarrier.try_wait.parity.acquire.cta.shared::cta.b64 p, [%1], %2;\n\t" \
        "selp.b32 %0, 1, 0, p;\n\t}" : "=r"(_d) : "r"(_m), "r"(_p) : "memory"); \
    if (!_d) { \
        asm volatile("{\n\t.reg .pred P1;\n\tWL_%=:\n\t" \
            "mbarrier.try_wait.parity.acquire.cta.shared::cta.b64 P1, [%0], %1, 0x989680;\n\t" \
            "@P1 bra.uni WD_%=;\n\tbra.uni WL_%=;\n\tWD_%=:\n\t}" \
            :: "r"(_m), "r"(_p) : "memory"); \
    } } while (0)

__device__ __forceinline__ void mma_f16_16x8x16(
    float& c0, float& c1, float& c2, float& c3,
    uint32_t a0, uint32_t a1, uint32_t a2, uint32_t a3,
    uint32_t b0, uint32_t b1)
{
    asm volatile(
        "mma.sync.aligned.m16n8k16.row.col.f32.f16.f16.f32 "
        "{%0,%1,%2,%3}, {%4,%5,%6,%7}, {%8,%9}, {%0,%1,%2,%3};"
        : "+f"(c0), "+f"(c1), "+f"(c2), "+f"(c3)
        : "r"(a0), "r"(a1), "r"(a2), "r"(a3), "r"(b0), "r"(b1));
}

// ---------------- prep: x -> half TILED ----------------
__global__ void round_half_kernel(const float4* __restrict__ in, __half* __restrict__ out) {
    int i = blockIdx.x * 256 + threadIdx.x;
    float4 v = in[i];
    int m = i >> 9, c4 = i & 511;
    int kblk = c4 >> 3;
    int g0 = (c4 & 7) * 2;
    int r = m & 127, mblk = m >> 7;
    int phys = g0 ^ (((r >> 1) & 3) << 2);
    __half2* dst = (__half2*)(out + ((size_t)(mblk * 64 + kblk) * 4096 + r * 32 + phys * 2));
    dst[0] = __floats2half2_rn(v.x, v.y);
    dst[1] = __floats2half2_rn(v.z, v.w);
}

// ---------------- prep: W -> half TILED [n][k] ----------------
__global__ void transpose_half_kernel(const float* __restrict__ W, __half* __restrict__ WT) {
    __shared__ float t[32][33];
    int n0 = blockIdx.x * 32, k0 = blockIdx.y * 32;
    int tx = threadIdx.x, ty = threadIdx.y;
#pragma unroll
    for (int j = 0; j < 32; j += 8)
        t[ty + j][tx] = W[(size_t)(k0 + ty + j) * 2048 + n0 + tx];
    __syncthreads();
    int kblk = k0 >> 5;
#pragma unroll
    for (int j = 0; j < 32; j += 8) {
        int n = n0 + ty + j;
        int kcol = tx;
        int r = n & 127, nblk = n >> 7;
        int g = kcol >> 1, phys = g ^ (((r >> 1) & 3) << 2);
        WT[(size_t)(nblk * 64 + kblk) * 4096 + r * 32 + phys * 2 + (kcol & 1)] =
            __float2half_rn(t[tx][ty + j]);
    }
}

// ---------------- fp16 GEMM via cp.async.bulk ----------------
#define GSTAGE_B 24576
#define GSTAGE_H 12288
#define GEMM_SMEM (4 * GSTAGE_B + 64)

__global__ __launch_bounds__(512, 1) void gemm256_kernel(
    const __half* __restrict__ A, const __half* __restrict__ BW, float* __restrict__ C)
{
    extern __shared__ __half shh[];
    uint32_t sb = smem_u32(shh);
    uint32_t mb = sb + 4 * GSTAGE_B;

    int tid = threadIdx.x;
    int wid = tid >> 5, lane = tid & 31;
    int wm = wid >> 2, wn = wid & 3;
    int gq = lane >> 2, kc = lane & 3;
    int n0 = blockIdx.x * 256, m0 = blockIdx.y * 128;

    if (tid == 0) {
#pragma unroll
        for (int s = 0; s < 4; s++) MBARRIER_INIT(mb + 8 * s, 1);
    }
    __syncthreads();

    const __half* Ab = A  + (size_t)(m0 >> 7) * 64 * 4096;
    const __half* B0 = BW + (size_t)(n0 >> 7) * 64 * 4096;
    const __half* B1 = BW + (size_t)((n0 >> 7) + 1) * 64 * 4096;

    if (tid == 0) {
#pragma unroll
        for (int s = 0; s < 3; s++) {
            MBARRIER_EXPECT_TX(mb + 8 * s, GSTAGE_B);
            CP_BULK(sb + s * GSTAGE_B,         Ab + (size_t)s * 4096, 8192, mb + 8 * s);
            CP_BULK(sb + s * GSTAGE_B + 8192,  B0 + (size_t)s * 4096, 8192, mb + 8 * s);
            CP_BULK(sb + s * GSTAGE_B + 16384, B1 + (size_t)s * 4096, 8192, mb + 8 * s);
        }
    }

    float acc[2][8][4];
#pragma unroll
    for (int i = 0; i < 2; i++)
#pragma unroll
        for (int j = 0; j < 8; j++)
#pragma unroll
            for (int r = 0; r < 4; r++) acc[i][j][r] = 0.f;

    for (int kt = 0; kt < 64; kt++) {
        int s = kt & 3;
        MBARRIER_WAIT_PARITY(mb + 8 * s, (kt >> 2) & 1);
        const __half* As = shh + (size_t)s * GSTAGE_H;
        const __half* Bs = As + 4096;
#pragma unroll
        for (int t = 0; t < 2; t++) {
            int gb = t * 8;
            uint32_t af[2][4], bf[8][2];
#pragma unroll
            for (int mf = 0; mf < 2; mf++) {
                int r = wm * 32 + mf * 16 + gq;
                af[mf][0] = ldh2(As, r,     gb + kc);
                af[mf][1] = ldh2(As, r + 8, gb + kc);
                af[mf][2] = ldh2(As, r,     gb + kc + 4);
                af[mf][3] = ldh2(As, r + 8, gb + kc + 4);
            }
#pragma unroll
            for (int nf = 0; nf < 8; nf++) {
                int nr = wn * 64 + nf * 8 + gq;
                bf[nf][0] = ldh2(Bs, nr, gb + kc);
                bf[nf][1] = ldh2(Bs, nr, gb + kc + 4);
            }
#pragma unroll
            for (int mf = 0; mf < 2; mf++)
#pragma unroll
                for (int nf = 0; nf < 8; nf++)
                    mma_f16_16x8x16(acc[mf][nf][0], acc[mf][nf][1],
                                    acc[mf][nf][2], acc[mf][nf][3],
                                    af[mf][0], af[mf][1], af[mf][2], af[mf][3],
                                    bf[nf][0], bf[nf][1]);
        }
        __syncthreads();
        if (tid == 0 && kt + 3 < 64) {
            int s2 = (kt + 3) & 3;
            MBARRIER_EXPECT_TX(mb + 8 * s2, GSTAGE_B);
            CP_BULK(sb + s2 * GSTAGE_B,         Ab + (size_t)(kt + 3) * 4096, 8192, mb + 8 * s2);
            CP_BULK(sb + s2 * GSTAGE_B + 8192,  B0 + (size_t)(kt + 3) * 4096, 8192, mb + 8 * s2);
            CP_BULK(sb + s2 * GSTAGE_B + 16384, B1 + (size_t)(kt + 3) * 4096, 8192, mb + 8 * s2);
        }
    }

#pragma unroll
    for (int mf = 0; mf < 2; mf++) {
        int r0 = m0 + wm * 32 + mf * 16 + gq;
#pragma unroll
        for (int nf = 0; nf < 8; nf++) {
            int col = n0 + wn * 64 + nf * 8 + kc * 2;
            *(float2*)&C[(size_t)r0 * 2048 + col]       = make_float2(acc[mf][nf][0], acc[mf][nf][1]);
            *(float2*)&C[(size_t)(r0 + 8) * 2048 + col] = make_float2(acc[mf][nf][2], acc[mf][nf][3]);
        }
    }
}

// ---------------- sparse K/V projection (fp16 mma) ----------------
#define KVSTAGE_B 16384
#define KVSTAGE_H 8192
#define KV_SMEM (4 * KVSTAGE_B + 128 * 4)

__global__ __launch_bounds__(256, 1) void sparse_kv_mma_kernel(
    const int* __restrict__ anchors)
{
    extern __shared__ __half shh[];
    int* tok = (int*)(shh + 4 * KVSTAGE_H);

    int tid = threadIdx.x;
    int bh = blockIdx.x;
    int h = bh & 15, b = bh >> 4;
    const __half* Bb = (blockIdx.y ? g_wvt : g_wkt) + (size_t)h * 64 * 4096;
    float* out = (blockIdx.y ? g_vsp : g_ksp) + (size_t)bh * NKEYS * HDIM;

    if (tid < 128) {
        int ti = tid >> 4;
        int tile = (ti == 7) ? 255 : anchors[(bh << 3) + ti];
        tok[tid] = tile * 16 + (tid & 15);
    }
    __syncthreads();

    int wid = tid >> 5, lane = tid & 31;
    int wm = wid >> 2, wn = wid & 3;
    int gq = lane >> 2, kc = lane & 3;

    uint32_t sb = smem_u32(shh);

    float acc[4][4][4];
#pragma unroll
    for (int i = 0; i < 4; i++)
#pragma unroll
        for (int j = 0; j < 4; j++)
#pragma unroll
            for (int r = 0; r < 4; r++) acc[i][j][r] = 0.f;

#pragma unroll
    for (int s = 0; s < 3; s++) {
        uint32_t so = sb + s * KVSTAGE_B;
#pragma unroll
        for (int i = 0; i < 2; i++) {
            int cidx = i * 256 + tid;
            int rs = cidx >> 2, c = cidx & 3;
            int grow = b * SS + tok[rs];
            const __half* srcA = g_xh + (size_t)((grow >> 7) * 64 + s) * 4096
                               + (grow & 127) * 32 + ((c ^ ((grow >> 1) & 3)) * 8);
            CP_ASYNC16(so + (uint32_t)(rs * 64 + (c ^ ((rs >> 1) & 3)) * 16), srcA);
            const __half* srcB = Bb + (size_t)s * 4096 + rs * 32 + ((c ^ ((rs >> 1) & 3)) * 8);
            CP_ASYNC16(so + 8192 + (uint32_t)(rs * 64 + (c ^ ((rs >> 1) & 3)) * 16), srcB);
        }
        CP_COMMIT();
    }

    for (int kt = 0; kt < 64; kt++) {
        CP_WAIT(2);
        __syncthreads();
        if (kt + 3 < 64) {
            int sl = kt + 3;
            uint32_t so = sb + (uint32_t)(sl & 3) * KVSTAGE_B;
#pragma unroll
            for (int i = 0; i < 2; i++) {
                int cidx = i * 256 + tid;
                int rs = cidx >> 2, c = cidx & 3;
                int grow = b * SS + tok[rs];
                const __half* srcA = g_xh + (size_t)((grow >> 7) * 64 + sl) * 4096
                                   + (grow & 127) * 32 + ((c ^ ((grow >> 1) & 3)) * 8);
                CP_ASYNC16(so + (uint32_t)(rs * 64 + (c ^ ((rs >> 1) & 3)) * 16), srcA);
                const __half* srcB = Bb + (size_t)sl * 4096 + rs * 32 + ((c ^ ((rs >> 1) & 3)) * 8);
                CP_ASYNC16(so + 8192 + (uint32_t)(rs * 64 + (c ^ ((rs >> 1) & 3)) * 16), srcB);
            }
        }
        CP_COMMIT();

        const __half* As = shh + (size_t)(kt & 3) * KVSTAGE_H;
        const __half* Bs = As + 4096;
#pragma unroll
        for (int t = 0; t < 2; t++) {
            int gb = t * 8;
            uint32_t af[4][4], bf[4][2];
#pragma unroll
            for (int mf = 0; mf < 4; mf++) {
                int r = wm * 64 + mf * 16 + gq;
                af[mf][0] = ldh2(As, r,     gb + kc);
                af[mf][1] = ldh2(As, r + 8, gb + kc);
                af[mf][2] = ldh2(As, r,     gb + kc + 4);
                af[mf][3] = ldh2(As, r + 8, gb + kc + 4);
            }
#pragma unroll
            for (int nf = 0; nf < 4; nf++) {
                int nr = wn * 32 + nf * 8 + gq;
                bf[nf][0] = ldh2(Bs, nr, gb + kc);
                bf[nf][1] = ldh2(Bs, nr, gb + kc + 4);
            }
#pragma unroll
            for (int mf = 0; mf < 4; mf++)
#pragma unroll
                for (int nf = 0; nf < 4; nf++)
                    mma_f16_16x8x16(acc[mf][nf][0], acc[mf][nf][1],
                                    acc[mf][nf][2], acc[mf][nf][3],
                                    af[mf][0], af[mf][1], af[mf][2], af[mf][3],
                                    bf[nf][0], bf[nf][1]);
        }
    }

#pragma unroll
    for (int mf = 0; mf < 4; mf++) {
        int r0 = wm * 64 + mf * 16 + gq;
#pragma unroll
        for (int nf = 0; nf < 4; nf++) {
            int col = wn * 32 + nf * 8 + kc * 2;
            *(float2*)&out[(size_t)r0 * 128 + col]       = make_float2(acc[mf][nf][0], acc[mf][nf][1]);
            *(float2*)&out[(size_t)(r0 + 8) * 128 + col] = make_float2(acc[mf][nf][2], acc[mf][nf][3]);
        }
    }
}

// ---------------- attention: fp16 mma end-to-end ----------------
#define SAST 132
#define ATTN_SMEM (3 * 32768 + 128 * SAST * 4 + 512)

__global__ __launch_bounds__(256) void attn_mma_kernel(
    const int* __restrict__ anchors, __half* __restrict__ attout, int bhbase)
{
    extern __shared__ char smraw[];
    __half* Kh  = (__half*)smraw;              // [key][128 d]   swizzled 256B rows
    __half* Vth = Kh + 16384;                  // [d][128 key]
    __half* QPh = Vth + 16384;                 // [q][128]  Q then P
    float*  Sf  = (float*)(QPh + 16384);       // [q][132] scores
    int*    tok = (int*)(Sf + 128 * SAST);

    int tid = threadIdx.x;
    int bh = bhbase + blockIdx.y;
    int b = bh >> 4, h = bh & 15;
    int q0 = blockIdx.x * 128;
    int wid = tid >> 5, lane = tid & 31;
    int gq = lane >> 2, kc = lane & 3;

    if (tid < 128) {
        int ti = tid >> 4;
        int tile = (ti == 7) ? 255 : anchors[(bh << 3) + ti];
        tok[tid] = tile * 16 + (tid & 15);
    }

    const float* kg = g_ksp + (size_t)bh * 16384;
    for (int idx = tid; idx < 4096; idx += 256) {
        int key = idx >> 5, d4 = idx & 31;
        float4 v = *(const float4*)(kg + key * 128 + d4 * 4);
        int p0 = (d4 * 2) ^ ((key & 7) << 2);
        *(__half2*)(Kh + key * 128 + p0 * 2)       = __floats2half2_rn(v.x, v.y);
        *(__half2*)(Kh + key * 128 + (p0 + 1) * 2) = __floats2half2_rn(v.z, v.w);
    }
    const float* vg = g_vsp + (size_t)bh * 16384;
    for (int idx = tid; idx < 16384; idx += 256) {
        int key = idx >> 7, d = idx & 127;
        int phys = (key >> 1) ^ ((d & 7) << 2);
        Vth[d * 128 + phys * 2 + (key & 1)] = __float2half_rn(vg[idx]);
    }
    const float* qg = g_q + ((size_t)b * SS + q0) * 2048 + h * 128;
    for (int idx = tid; idx < 4096; idx += 256) {
        int q = idx >> 5, d4 = idx & 31;
        float4 v = *(const float4*)(qg + (size_t)q * 2048 + d4 * 4);
        int p0 = (d4 * 2) ^ ((q & 7) << 2);
        *(__half2*)(QPh + q * 128 + p0 * 2)       = __floats2half2_rn(v.x, v.y);
        *(__half2*)(QPh + q * 128 + (p0 + 1) * 2) = __floats2half2_rn(v.z, v.w);
    }
    __syncthreads();

    // ---- S = Q @ K^T (fp16, 8 k-chunks of 16) ----
    int r = wid * 16 + gq;
    float acc[16][4];
#pragma unroll
    for (int nf = 0; nf < 16; nf++)
#pragma unroll
        for (int z = 0; z < 4; z++) acc[nf][z] = 0.f;
#pragma unroll
    for (int t = 0; t < 8; t++) {
        int gb = t * 8;
        uint32_t a0 = ldh2a(QPh, r,     gb + kc);
        uint32_t a1 = ldh2a(QPh, r + 8, gb + kc);
        uint32_t a2 = ldh2a(QPh, r,     gb + kc + 4);
        uint32_t a3 = ldh2a(QPh, r + 8, gb + kc + 4);
#pragma unroll
        for (int nf = 0; nf < 16; nf++) {
            int nr = nf * 8 + gq;
            uint32_t b0 = ldh2a(Kh, nr, gb + kc);
            uint32_t b1 = ldh2a(Kh, nr, gb + kc + 4);
            mma_f16_16x8x16(acc[nf][0], acc[nf][1], acc[nf][2], acc[nf][3],
                            a0, a1, a2, a3, b0, b1);
        }
    }
#pragma unroll
    for (int nf = 0; nf < 16; nf++) {
        int col = nf * 8 + kc * 2;
        Sf[r * SAST + col]           = acc[nf][0];
        Sf[r * SAST + col + 1]       = acc[nf][1];
        Sf[(r + 8) * SAST + col]     = acc[nf][2];
        Sf[(r + 8) * SAST + col + 1] = acc[nf][3];
    }
    __syncthreads();   // scores visible; all Q reads complete

    // ---- softmax (fp32), write P as half into QPh ----
    {
        const float scale = 0.0883883476483184f;
        int row = tid >> 1, hc = (tid & 1) * 64;
        int qpos = q0 + row;
        float* S = Sf + row * SAST + hc;
        float mx = -3.0e38f;
#pragma unroll 16
        for (int c = 0; c < 64; c++) {
            float v = S[c] * scale;
            if (tok[hc + c] > qpos) v = -1e10f;
            mx = fmaxf(mx, v);
        }
        mx = fmaxf(mx, __shfl_xor_sync(0xffffffffu, mx, 1));
        float sum = 0.f;
        float e[64];
#pragma unroll 16
        for (int c = 0; c < 64; c++) {
            float v = S[c] * scale;
            if (tok[hc + c] > qpos) v = -1e10f;
            e[c] = __expf(v - mx);
            sum += e[c];
        }
        sum += __shfl_xor_sync(0xffffffffu, sum, 1);
        float inv = 1.f / sum;
        int sw = (row & 7) << 2;
#pragma unroll 16
        for (int c = 0; c < 64; c += 2) {
            int g = (hc + c) >> 1, phys = g ^ sw;
            *(__half2*)(QPh + row * 128 + phys * 2) =
                __floats2half2_rn(e[c] * inv, e[c + 1] * inv);
        }
    }
    __syncthreads();

    // ---- O = P @ V (fp16) ----
    float acc2[16][4];
#pragma unroll
    for (int nf = 0; nf < 16; nf++)
#pragma unroll
        for (int z = 0; z < 4; z++) acc2[nf][z] = 0.f;
#pragma unroll
    for (int t = 0; t < 8; t++) {
        int gb = t * 8;
        uint32_t a0 = ldh2a(QPh, r,     gb + kc);
        uint32_t a1 = ldh2a(QPh, r + 8, gb + kc);
        uint32_t a2 = ldh2a(QPh, r,     gb + kc + 4);
        uint32_t a3 = ldh2a(QPh, r + 8, gb + kc + 4);
#pragma unroll
        for (int nf = 0; nf < 16; nf++) {
            int nr = nf * 8 + gq;
            uint32_t b0 = ldh2a(Vth, nr, gb + kc);
            uint32_t b1 = ldh2a(Vth, nr, gb + kc + 4);
            mma_f16_16x8x16(acc2[nf][0], acc2[nf][1], acc2[nf][2], acc2[nf][3],
                            a0, a1, a2, a3, b0, b1);
        }
    }

    // ---- store O in half TILED layout (GEMM2 A operand) ----
    {
        int mblk = (b * SS + q0) >> 7;
        __half* abase = attout + (size_t)mblk * 64 * 4096;
        int sw = ((r >> 1) & 3) << 2;
#pragma unroll
        for (int nf = 0; nf < 16; nf++) {
            int col = h * HDIM + nf * 8 + kc * 2;
            int kblk = col >> 5, kcol = col & 31;
            int phys = (kcol >> 1) ^ sw;
            *(__half2*)(abase + (size_t)kblk * 4096 + r * 32 + phys * 2) =
                __floats2half2_rn(acc2[nf][0], acc2[nf][1]);
            *(__half2*)(abase + (size_t)kblk * 4096 + (r + 8) * 32 + phys * 2) =
                __floats2half2_rn(acc2[nf][2], acc2[nf][3]);
        }
    }
}

// ---------------- streams/events (created pre-main, before harness checkpoints) ----------------
static cudaStream_t g_s1, g_s2;
static cudaEvent_t g_e0, g_ekv, g_e1[4], g_e2[4];
static bool g_streams_ok = [](){
    cudaStreamCreateWithFlags(&g_s1, cudaStreamNonBlocking);
    cudaStreamCreateWithFlags(&g_s2, cudaStreamNonBlocking);
    cudaEventCreateWithFlags(&g_e0,  cudaEventDisableTiming);
    cudaEventCreateWithFlags(&g_ekv, cudaEventDisableTiming);
    for (int i = 0; i < 4; i++) {
        cudaEventCreateWithFlags(&g_e1[i], cudaEventDisableTiming);
        cudaEventCreateWithFlags(&g_e2[i], cudaEventDisableTiming);
    }
    return true;
}();

// ---------------- launch ----------------
extern "C" void kernel_launch(void* const* d_in, const int* in_sizes, int n_in,
                              void* d_out, int out_size)
{
    const float* x       = (const float*)d_in[0];
    const int*   anchors = (const int*)  d_in[1];
    const float* Wq      = (const float*)d_in[2];
    const float* Wk      = (const float*)d_in[3];
    const float* Wv      = (const float*)d_in[4];
    const float* Wo      = (const float*)d_in[5];
    float* out = (float*)d_out;

    float *qp;
    __half *attp, *xhp, *wqtp, *wotp, *wktp, *wvtp;
    cudaGetSymbolAddress((void**)&qp,   g_q);
    cudaGetSymbolAddress((void**)&attp, g_att);
    cudaGetSymbolAddress((void**)&xhp,  g_xh);
    cudaGetSymbolAddress((void**)&wqtp, g_wqt);
    cudaGetSymbolAddress((void**)&wotp, g_wot);
    cudaGetSymbolAddress((void**)&wktp, g_wkt);
    cudaGetSymbolAddress((void**)&wvtp, g_wvt);

    cudaFuncSetAttribute(attn_mma_kernel, cudaFuncAttributeMaxDynamicSharedMemorySize, ATTN_SMEM);
    cudaFuncSetAttribute(gemm256_kernel, cudaFuncAttributeMaxDynamicSharedMemorySize, GEMM_SMEM);
    cudaFuncSetAttribute(sparse_kv_mma_kernel, cudaFuncAttributeMaxDynamicSharedMemorySize, KV_SMEM);

    const size_t ABLK = (size_t)32 * 64 * 4096;   // half elems per batch (tiled)
    const size_t CBLK = (size_t)SS * DD;          // fp32 elems per batch

    // stream 0: prep for GEMM1, then KV prep + sparse_kv, then Wo transpose
    round_half_kernel<<<(BB * SS * DD / 4) / 256, 256>>>((const float4*)x, xhp);
    transpose_half_kernel<<<dim3(64, 64), dim3(32, 8)>>>(Wq, wqtp);
    cudaEventRecord(g_e0, 0);
    transpose_half_kernel<<<dim3(64, 64), dim3(32, 8)>>>(Wk, wktp);
    transpose_half_kernel<<<dim3(64, 64), dim3(32, 8)>>>(Wv, wvtp);
    sparse_kv_mma_kernel<<<dim3(64, 2), 256, KV_SMEM>>>(anchors);
    cudaEventRecord(g_ekv, 0);
    transpose_half_kernel<<<dim3(64, 64), dim3(32, 8)>>>(Wo, wotp);

    // s1: GEMM1 per batch
    cudaStreamWaitEvent(g_s1, g_e0, 0);
    for (int b = 0; b < 4; b++) {
        gemm256_kernel<<<dim3(8, 32), 512, GEMM_SMEM, g_s1>>>(
            xhp + b * ABLK, wqtp, qp + b * CBLK);
        cudaEventRecord(g_e1[b], g_s1);
    }
    // s2: attention per batch
    cudaStreamWaitEvent(g_s2, g_ekv, 0);
    for (int b = 0; b < 4; b++) {
        cudaStreamWaitEvent(g_s2, g_e1[b], 0);
        attn_mma_kernel<<<dim3(32, 16), 256, ATTN_SMEM, g_s2>>>(anchors, attp, b * 16);
        cudaEventRecord(g_e2[b], g_s2);
    }
    // stream 0: GEMM2 per batch (joins everything)
    for (int b = 0; b < 4; b++) {
        cudaStreamWaitEvent(0, g_e2[b], 0);
        gemm256_kernel<<<dim3(8, 32), 512, GEMM_SMEM>>>(
            attp + b * ABLK, wotp, out + b * CBLK);
    }
}

// round 10
// speedup vs baseline: 6.6843x; 1.1243x over previous
#include <cuda_runtime.h>
#include <cuda_fp16.h>
#include <cstdint>
#include <math.h>

#define BB 4
#define SS 4096
#define DD 2048
#define HH 16
#define HDIM 128
#define NKEYS 128

// ---------------- scratch ----------------
__device__ float  g_q  [(size_t)BB * SS * DD];   // fp32 row-major (attn reads)
__device__ __half g_att[(size_t)BB * SS * DD];   // half TILED (GEMM2 A)
__device__ __half g_xh [(size_t)BB * SS * DD];   // half TILED (GEMM1 + kv A)
__device__ __half g_wqt[2048 * 2048];            // half TILED [n][k]
__device__ __half g_wot[2048 * 2048];
__device__ __half g_wkt[2048 * 2048];
__device__ __half g_wvt[2048 * 2048];
__device__ float  g_ksp[64 * NKEYS * HDIM];      // fp32
__device__ float  g_vsp[64 * NKEYS * HDIM];      // fp32

// ---------------- helpers ----------------
__device__ __forceinline__ uint32_t smem_u32(const void* p) {
    uint32_t a;
    asm("{ .reg .u64 t; cvta.to.shared.u64 t, %1; cvt.u32.u64 %0, t; }" : "=r"(a) : "l"(p));
    return a;
}
__device__ __forceinline__ uint32_t ldh2(const __half* blk, int r, int g) {
    int phys = g ^ (((r >> 1) & 3) << 2);
    return *(const uint32_t*)(blk + r * 32 + phys * 2);
}
__device__ __forceinline__ uint32_t ldh2a(const __half* base, int r, int g) {
    int phys = g ^ ((r & 7) << 2);
    return *(const uint32_t*)(base + r * 128 + phys * 2);
}
#define CP_ASYNC16(dst, src) \
    asm volatile("cp.async.cg.shared.global [%0], [%1], 16;" :: "r"(dst), "l"(src) : "memory")
#define CP_COMMIT() asm volatile("cp.async.commit_group;" ::: "memory")
#define CP_WAIT(n)  asm volatile("cp.async.wait_group %0;" :: "n"(n) : "memory")
#define CP_BULK(dst, src, bytes, mbar) \
    asm volatile("cp.async.bulk.shared::cluster.global.mbarrier::complete_tx::bytes [%0], [%1], %2, [%3];" \
        :: "r"(dst), "l"(src), "r"(bytes), "r"(mbar) : "memory")
#define MBARRIER_INIT(addr, cnt) \
    asm volatile("mbarrier.init.shared.b64 [%0], %1;" :: "r"(addr), "r"(cnt) : "memory")
#define MBARRIER_EXPECT_TX(addr, tx) \
    asm volatile("mbarrier.arrive.expect_tx.shared.b64 _, [%0], %1;" :: "r"(addr), "r"(tx) : "memory")
#define MBARRIER_WAIT_PARITY(addr, ph) do { \
    uint32_t _m = (addr), _p = (ph), _d; \
    asm volatile("{\n\t.reg .pred p;\n\t" \
        "mbarrier.try_wait.parity.acquire.cta.shared::cta.b64 p, [%1], %2;\n\t" \
        "selp.b32 %0, 1, 0, p;\n\t}" : "=r"(_d) : "r"(_m), "r"(_p) : "memory"); \
    if (!_d) { \
        asm volatile("{\n\t.reg .pred P1;\n\tWL_%=:\n\t" \
            "mbarrier.try_wait.parity.acquire.cta.shared::cta.b64 P1, [%0], %1, 0x989680;\n\t" \
            "@P1 bra.uni WD_%=;\n\tbra.uni WL_%=;\n\tWD_%=:\n\t}" \
            :: "r"(_m), "r"(_p) : "memory"); \
    } } while (0)
#define LDMX4(r0, r1, r2, r3, addr) \
    asm volatile("ldmatrix.sync.aligned.m8n8.x4.shared.b16 {%0,%1,%2,%3}, [%4];" \
        : "=r"(r0), "=r"(r1), "=r"(r2), "=r"(r3) : "r"(addr))

__device__ __forceinline__ void mma_f16_16x8x16(
    float& c0, float& c1, float& c2, float& c3,
    uint32_t a0, uint32_t a1, uint32_t a2, uint32_t a3,
    uint32_t b0, uint32_t b1)
{
    asm volatile(
        "mma.sync.aligned.m16n8k16.row.col.f32.f16.f16.f32 "
        "{%0,%1,%2,%3}, {%4,%5,%6,%7}, {%8,%9}, {%0,%1,%2,%3};"
        : "+f"(c0), "+f"(c1), "+f"(c2), "+f"(c3)
        : "r"(a0), "r"(a1), "r"(a2), "r"(a3), "r"(b0), "r"(b1));
}

// ---------------- prep: x -> half TILED ----------------
__global__ void round_half_kernel(const float4* __restrict__ in, __half* __restrict__ out) {
    int i = blockIdx.x * 256 + threadIdx.x;
    float4 v = in[i];
    int m = i >> 9, c4 = i & 511;
    int kblk = c4 >> 3;
    int g0 = (c4 & 7) * 2;
    int r = m & 127, mblk = m >> 7;
    int phys = g0 ^ (((r >> 1) & 3) << 2);
    __half2* dst = (__half2*)(out + ((size_t)(mblk * 64 + kblk) * 4096 + r * 32 + phys * 2));
    dst[0] = __floats2half2_rn(v.x, v.y);
    dst[1] = __floats2half2_rn(v.z, v.w);
}

// ---------------- prep: W -> half TILED [n][k] ----------------
__global__ void transpose_half_kernel(const float* __restrict__ W, __half* __restrict__ WT) {
    __shared__ float t[32][33];
    int n0 = blockIdx.x * 32, k0 = blockIdx.y * 32;
    int tx = threadIdx.x, ty = threadIdx.y;
#pragma unroll
    for (int j = 0; j < 32; j += 8)
        t[ty + j][tx] = W[(size_t)(k0 + ty + j) * 2048 + n0 + tx];
    __syncthreads();
    int kblk = k0 >> 5;
#pragma unroll
    for (int j = 0; j < 32; j += 8) {
        int n = n0 + ty + j;
        int kcol = tx;
        int r = n & 127, nblk = n >> 7;
        int g = kcol >> 1, phys = g ^ (((r >> 1) & 3) << 2);
        WT[(size_t)(nblk * 64 + kblk) * 4096 + r * 32 + phys * 2 + (kcol & 1)] =
            __float2half_rn(t[tx][ty + j]);
    }
}

// ---------------- fp16 GEMM via cp.async.bulk + ldmatrix ----------------
#define GSTAGE_B 24576
#define GSTAGE_H 12288
#define GEMM_SMEM (4 * GSTAGE_B + 64)

__global__ __launch_bounds__(512, 1) void gemm256_kernel(
    const __half* __restrict__ A, const __half* __restrict__ BW, float* __restrict__ C)
{
    extern __shared__ __half shh[];
    uint32_t sb = smem_u32(shh);
    uint32_t mb = sb + 4 * GSTAGE_B;

    int tid = threadIdx.x;
    int wid = tid >> 5, lane = tid & 31;
    int wm = wid >> 2, wn = wid & 3;
    int gq = lane >> 2, kc = lane & 3;
    int n0 = blockIdx.x * 256, m0 = blockIdx.y * 128;

    if (tid == 0) {
#pragma unroll
        for (int s = 0; s < 4; s++) MBARRIER_INIT(mb + 8 * s, 1);
    }
    __syncthreads();

    const __half* Ab = A  + (size_t)(m0 >> 7) * 64 * 4096;
    const __half* B0 = BW + (size_t)(n0 >> 7) * 64 * 4096;
    const __half* B1 = BW + (size_t)((n0 >> 7) + 1) * 64 * 4096;

    if (tid == 0) {
#pragma unroll
        for (int s = 0; s < 3; s++) {
            MBARRIER_EXPECT_TX(mb + 8 * s, GSTAGE_B);
            CP_BULK(sb + s * GSTAGE_B,         Ab + (size_t)s * 4096, 8192, mb + 8 * s);
            CP_BULK(sb + s * GSTAGE_B + 8192,  B0 + (size_t)s * 4096, 8192, mb + 8 * s);
            CP_BULK(sb + s * GSTAGE_B + 16384, B1 + (size_t)s * 4096, 8192, mb + 8 * s);
        }
    }

    // ---- per-lane ldmatrix base addresses (within stage 0) ----
    // A fragments: rows wm*32 + mf*16 + {0..15}, 16B chunk (2t + cA) ^ swA
    int laneAr = wm * 32 + (lane & 7) + (((lane >> 3) & 1) << 3);
    int cA = lane >> 4;                     // 0/1 -> k chunk within fragment
    int swA = (laneAr >> 1) & 3;
    uint32_t aAddr0 = sb + (uint32_t)laneAr * 64 + (uint32_t)((cA     ^ swA) << 4);
    uint32_t aAddr1 = sb + (uint32_t)laneAr * 64 + (uint32_t)(((2|cA) ^ swA) << 4);
    // B fragments: rows wn*64 + nfp*16 + {nf-half: (lane>>4)*8} + lane&7, chunk (2t + cB) ^ swB
    int laneBr = wn * 64 + ((lane >> 4) << 3) + (lane & 7);
    int cB = (lane >> 3) & 1;
    int swB = (laneBr >> 1) & 3;
    uint32_t bAddr0 = sb + 8192 + (uint32_t)laneBr * 64 + (uint32_t)((cB     ^ swB) << 4);
    uint32_t bAddr1 = sb + 8192 + (uint32_t)laneBr * 64 + (uint32_t)(((2|cB) ^ swB) << 4);

    float acc[2][8][4];
#pragma unroll
    for (int i = 0; i < 2; i++)
#pragma unroll
        for (int j = 0; j < 8; j++)
#pragma unroll
            for (int r = 0; r < 4; r++) acc[i][j][r] = 0.f;

    for (int kt = 0; kt < 64; kt++) {
        int s = kt & 3;
        MBARRIER_WAIT_PARITY(mb + 8 * s, (kt >> 2) & 1);
        uint32_t so = (uint32_t)s * GSTAGE_B;
#pragma unroll
        for (int t = 0; t < 2; t++) {
            uint32_t aA = (t ? aAddr1 : aAddr0) + so;
            uint32_t bA = (t ? bAddr1 : bAddr0) + so;
            uint32_t af[2][4], bf[8][2];
            LDMX4(af[0][0], af[0][1], af[0][2], af[0][3], aA);
            LDMX4(af[1][0], af[1][1], af[1][2], af[1][3], aA + 1024);
#pragma unroll
            for (int nfp = 0; nfp < 4; nfp++)
                LDMX4(bf[2 * nfp][0], bf[2 * nfp][1], bf[2 * nfp + 1][0], bf[2 * nfp + 1][1],
                      bA + nfp * 1024);
#pragma unroll
            for (int mf = 0; mf < 2; mf++)
#pragma unroll
                for (int nf = 0; nf < 8; nf++)
                    mma_f16_16x8x16(acc[mf][nf][0], acc[mf][nf][1],
                                    acc[mf][nf][2], acc[mf][nf][3],
                                    af[mf][0], af[mf][1], af[mf][2], af[mf][3],
                                    bf[nf][0], bf[nf][1]);
        }
        __syncthreads();
        if (tid == 0 && kt + 3 < 64) {
            int s2 = (kt + 3) & 3;
            MBARRIER_EXPECT_TX(mb + 8 * s2, GSTAGE_B);
            CP_BULK(sb + s2 * GSTAGE_B,         Ab + (size_t)(kt + 3) * 4096, 8192, mb + 8 * s2);
            CP_BULK(sb + s2 * GSTAGE_B + 8192,  B0 + (size_t)(kt + 3) * 4096, 8192, mb + 8 * s2);
            CP_BULK(sb + s2 * GSTAGE_B + 16384, B1 + (size_t)(kt + 3) * 4096, 8192, mb + 8 * s2);
        }
    }

#pragma unroll
    for (int mf = 0; mf < 2; mf++) {
        int r0 = m0 + wm * 32 + mf * 16 + gq;
#pragma unroll
        for (int nf = 0; nf < 8; nf++) {
            int col = n0 + wn * 64 + nf * 8 + kc * 2;
            *(float2*)&C[(size_t)r0 * 2048 + col]       = make_float2(acc[mf][nf][0], acc[mf][nf][1]);
            *(float2*)&C[(size_t)(r0 + 8) * 2048 + col] = make_float2(acc[mf][nf][2], acc[mf][nf][3]);
        }
    }
}

// ---------------- sparse K/V projection (fp16 mma) ----------------
#define KVSTAGE_B 16384
#define KVSTAGE_H 8192
#define KV_SMEM (4 * KVSTAGE_B + 128 * 4)

__global__ __launch_bounds__(256, 1) void sparse_kv_mma_kernel(
    const int* __restrict__ anchors)
{
    extern __shared__ __half shh[];
    int* tok = (int*)(shh + 4 * KVSTAGE_H);

    int tid = threadIdx.x;
    int bh = blockIdx.x;
    int h = bh & 15, b = bh >> 4;
    const __half* Bb = (blockIdx.y ? g_wvt : g_wkt) + (size_t)h * 64 * 4096;
    float* out = (blockIdx.y ? g_vsp : g_ksp) + (size_t)bh * NKEYS * HDIM;

    if (tid < 128) {
        int ti = tid >> 4;
        int tile = (ti == 7) ? 255 : anchors[(bh << 3) + ti];
        tok[tid] = tile * 16 + (tid & 15);
    }
    __syncthreads();

    int wid = tid >> 5, lane = tid & 31;
    int wm = wid >> 2, wn = wid & 3;
    int gq = lane >> 2, kc = lane & 3;

    uint32_t sb = smem_u32(shh);

    float acc[4][4][4];
#pragma unroll
    for (int i = 0; i < 4; i++)
#pragma unroll
        for (int j = 0; j < 4; j++)
#pragma unroll
            for (int r = 0; r < 4; r++) acc[i][j][r] = 0.f;

#pragma unroll
    for (int s = 0; s < 3; s++) {
        uint32_t so = sb + s * KVSTAGE_B;
#pragma unroll
        for (int i = 0; i < 2; i++) {
            int cidx = i * 256 + tid;
            int rs = cidx >> 2, c = cidx & 3;
            int grow = b * SS + tok[rs];
            const __half* srcA = g_xh + (size_t)((grow >> 7) * 64 + s) * 4096
                               + (grow & 127) * 32 + ((c ^ ((grow >> 1) & 3)) * 8);
            CP_ASYNC16(so + (uint32_t)(rs * 64 + (c ^ ((rs >> 1) & 3)) * 16), srcA);
            const __half* srcB = Bb + (size_t)s * 4096 + rs * 32 + ((c ^ ((rs >> 1) & 3)) * 8);
            CP_ASYNC16(so + 8192 + (uint32_t)(rs * 64 + (c ^ ((rs >> 1) & 3)) * 16), srcB);
        }
        CP_COMMIT();
    }

    for (int kt = 0; kt < 64; kt++) {
        CP_WAIT(2);
        __syncthreads();
        if (kt + 3 < 64) {
            int sl = kt + 3;
            uint32_t so = sb + (uint32_t)(sl & 3) * KVSTAGE_B;
#pragma unroll
            for (int i = 0; i < 2; i++) {
                int cidx = i * 256 + tid;
                int rs = cidx >> 2, c = cidx & 3;
                int grow = b * SS + tok[rs];
                const __half* srcA = g_xh + (size_t)((grow >> 7) * 64 + sl) * 4096
                                   + (grow & 127) * 32 + ((c ^ ((grow >> 1) & 3)) * 8);
                CP_ASYNC16(so + (uint32_t)(rs * 64 + (c ^ ((rs >> 1) & 3)) * 16), srcA);
                const __half* srcB = Bb + (size_t)sl * 4096 + rs * 32 + ((c ^ ((rs >> 1) & 3)) * 8);
                CP_ASYNC16(so + 8192 + (uint32_t)(rs * 64 + (c ^ ((rs >> 1) & 3)) * 16), srcB);
            }
        }
        CP_COMMIT();

        const __half* As = shh + (size_t)(kt & 3) * KVSTAGE_H;
        const __half* Bs = As + 4096;
#pragma unroll
        for (int t = 0; t < 2; t++) {
            int gb = t * 8;
            uint32_t af[4][4], bf[4][2];
#pragma unroll
            for (int mf = 0; mf < 4; mf++) {
                int r = wm * 64 + mf * 16 + gq;
                af[mf][0] = ldh2(As, r,     gb + kc);
                af[mf][1] = ldh2(As, r + 8, gb + kc);
                af[mf][2] = ldh2(As, r,     gb + kc + 4);
                af[mf][3] = ldh2(As, r + 8, gb + kc + 4);
            }
#pragma unroll
            for (int nf = 0; nf < 4; nf++) {
                int nr = wn * 32 + nf * 8 + gq;
                bf[nf][0] = ldh2(Bs, nr, gb + kc);
                bf[nf][1] = ldh2(Bs, nr, gb + kc + 4);
            }
#pragma unroll
            for (int mf = 0; mf < 4; mf++)
#pragma unroll
                for (int nf = 0; nf < 4; nf++)
                    mma_f16_16x8x16(acc[mf][nf][0], acc[mf][nf][1],
                                    acc[mf][nf][2], acc[mf][nf][3],
                                    af[mf][0], af[mf][1], af[mf][2], af[mf][3],
                                    bf[nf][0], bf[nf][1]);
        }
    }

#pragma unroll
    for (int mf = 0; mf < 4; mf++) {
        int r0 = wm * 64 + mf * 16 + gq;
#pragma unroll
        for (int nf = 0; nf < 4; nf++) {
            int col = wn * 32 + nf * 8 + kc * 2;
            *(float2*)&out[(size_t)r0 * 128 + col]       = make_float2(acc[mf][nf][0], acc[mf][nf][1]);
            *(float2*)&out[(size_t)(r0 + 8) * 128 + col] = make_float2(acc[mf][nf][2], acc[mf][nf][3]);
        }
    }
}

// ---------------- attention: fp16 mma end-to-end ----------------
#define SAST 132
#define ATTN_SMEM (3 * 32768 + 128 * SAST * 4 + 512)

__global__ __launch_bounds__(256) void attn_mma_kernel(
    const int* __restrict__ anchors, __half* __restrict__ attout, int bhbase)
{
    extern __shared__ char smraw[];
    __half* Kh  = (__half*)smraw;
    __half* Vth = Kh + 16384;
    __half* QPh = Vth + 16384;
    float*  Sf  = (float*)(QPh + 16384);
    int*    tok = (int*)(Sf + 128 * SAST);

    int tid = threadIdx.x;
    int bh = bhbase + blockIdx.y;
    int b = bh >> 4, h = bh & 15;
    int q0 = blockIdx.x * 128;
    int wid = tid >> 5, lane = tid & 31;
    int gq = lane >> 2, kc = lane & 3;

    if (tid < 128) {
        int ti = tid >> 4;
        int tile = (ti == 7) ? 255 : anchors[(bh << 3) + ti];
        tok[tid] = tile * 16 + (tid & 15);
    }

    const float* kg = g_ksp + (size_t)bh * 16384;
    for (int idx = tid; idx < 4096; idx += 256) {
        int key = idx >> 5, d4 = idx & 31;
        float4 v = *(const float4*)(kg + key * 128 + d4 * 4);
        int p0 = (d4 * 2) ^ ((key & 7) << 2);
        *(__half2*)(Kh + key * 128 + p0 * 2)       = __floats2half2_rn(v.x, v.y);
        *(__half2*)(Kh + key * 128 + (p0 + 1) * 2) = __floats2half2_rn(v.z, v.w);
    }
    const float* vg = g_vsp + (size_t)bh * 16384;
    for (int idx = tid; idx < 16384; idx += 256) {
        int key = idx >> 7, d = idx & 127;
        int phys = (key >> 1) ^ ((d & 7) << 2);
        Vth[d * 128 + phys * 2 + (key & 1)] = __float2half_rn(vg[idx]);
    }
    const float* qg = g_q + ((size_t)b * SS + q0) * 2048 + h * 128;
    for (int idx = tid; idx < 4096; idx += 256) {
        int q = idx >> 5, d4 = idx & 31;
        float4 v = *(const float4*)(qg + (size_t)q * 2048 + d4 * 4);
        int p0 = (d4 * 2) ^ ((q & 7) << 2);
        *(__half2*)(QPh + q * 128 + p0 * 2)       = __floats2half2_rn(v.x, v.y);
        *(__half2*)(QPh + q * 128 + (p0 + 1) * 2) = __floats2half2_rn(v.z, v.w);
    }
    __syncthreads();

    int r = wid * 16 + gq;
    float acc[16][4];
#pragma unroll
    for (int nf = 0; nf < 16; nf++)
#pragma unroll
        for (int z = 0; z < 4; z++) acc[nf][z] = 0.f;
#pragma unroll
    for (int t = 0; t < 8; t++) {
        int gb = t * 8;
        uint32_t a0 = ldh2a(QPh, r,     gb + kc);
        uint32_t a1 = ldh2a(QPh, r + 8, gb + kc);
        uint32_t a2 = ldh2a(QPh, r,     gb + kc + 4);
        uint32_t a3 = ldh2a(QPh, r + 8, gb + kc + 4);
#pragma unroll
        for (int nf = 0; nf < 16; nf++) {
            int nr = nf * 8 + gq;
            uint32_t b0 = ldh2a(Kh, nr, gb + kc);
            uint32_t b1 = ldh2a(Kh, nr, gb + kc + 4);
            mma_f16_16x8x16(acc[nf][0], acc[nf][1], acc[nf][2], acc[nf][3],
                            a0, a1, a2, a3, b0, b1);
        }
    }
#pragma unroll
    for (int nf = 0; nf < 16; nf++) {
        int col = nf * 8 + kc * 2;
        Sf[r * SAST + col]           = acc[nf][0];
        Sf[r * SAST + col + 1]       = acc[nf][1];
        Sf[(r + 8) * SAST + col]     = acc[nf][2];
        Sf[(r + 8) * SAST + col + 1] = acc[nf][3];
    }
    __syncthreads();

    {
        const float scale = 0.0883883476483184f;
        int row = tid >> 1, hc = (tid & 1) * 64;
        int qpos = q0 + row;
        float* S = Sf + row * SAST + hc;
        float mx = -3.0e38f;
#pragma unroll 16
        for (int c = 0; c < 64; c++) {
            float v = S[c] * scale;
            if (tok[hc + c] > qpos) v = -1e10f;
            mx = fmaxf(mx, v);
        }
        mx = fmaxf(mx, __shfl_xor_sync(0xffffffffu, mx, 1));
        float sum = 0.f;
        float e[64];
#pragma unroll 16
        for (int c = 0; c < 64; c++) {
            float v = S[c] * scale;
            if (tok[hc + c] > qpos) v = -1e10f;
            e[c] = __expf(v - mx);
            sum += e[c];
        }
        sum += __shfl_xor_sync(0xffffffffu, sum, 1);
        float inv = 1.f / sum;
        int sw = (row & 7) << 2;
#pragma unroll 16
        for (int c = 0; c < 64; c += 2) {
            int g = (hc + c) >> 1, phys = g ^ sw;
            *(__half2*)(QPh + row * 128 + phys * 2) =
                __floats2half2_rn(e[c] * inv, e[c + 1] * inv);
        }
    }
    __syncthreads();

    float acc2[16][4];
#pragma unroll
    for (int nf = 0; nf < 16; nf++)
#pragma unroll
        for (int z = 0; z < 4; z++) acc2[nf][z] = 0.f;
#pragma unroll
    for (int t = 0; t < 8; t++) {
        int gb = t * 8;
        uint32_t a0 = ldh2a(QPh, r,     gb + kc);
        uint32_t a1 = ldh2a(QPh, r + 8, gb + kc);
        uint32_t a2 = ldh2a(QPh, r,     gb + kc + 4);
        uint32_t a3 = ldh2a(QPh, r + 8, gb + kc + 4);
#pragma unroll
        for (int nf = 0; nf < 16; nf++) {
            int nr = nf * 8 + gq;
            uint32_t b0 = ldh2a(Vth, nr, gb + kc);
            uint32_t b1 = ldh2a(Vth, nr, gb + kc + 4);
            mma_f16_16x8x16(acc2[nf][0], acc2[nf][1], acc2[nf][2], acc2[nf][3],
                            a0, a1, a2, a3, b0, b1);
        }
    }

    {
        int mblk = (b * SS + q0) >> 7;
        __half* abase = attout + (size_t)mblk * 64 * 4096;
        int sw = ((r >> 1) & 3) << 2;
#pragma unroll
        for (int nf = 0; nf < 16; nf++) {
            int col = h * HDIM + nf * 8 + kc * 2;
            int kblk = col >> 5, kcol = col & 31;
            int phys = (kcol >> 1) ^ sw;
            *(__half2*)(abase + (size_t)kblk * 4096 + r * 32 + phys * 2) =
                __floats2half2_rn(acc2[nf][0], acc2[nf][1]);
            *(__half2*)(abase + (size_t)kblk * 4096 + (r + 8) * 32 + phys * 2) =
                __floats2half2_rn(acc2[nf][2], acc2[nf][3]);
        }
    }
}

// ---------------- streams/events ----------------
static cudaStream_t g_s1, g_s2;
static cudaEvent_t g_e0, g_ekv, g_e1[4], g_e2[4];
static bool g_streams_ok = [](){
    cudaStreamCreateWithFlags(&g_s1, cudaStreamNonBlocking);
    cudaStreamCreateWithFlags(&g_s2, cudaStreamNonBlocking);
    cudaEventCreateWithFlags(&g_e0,  cudaEventDisableTiming);
    cudaEventCreateWithFlags(&g_ekv, cudaEventDisableTiming);
    for (int i = 0; i < 4; i++) {
        cudaEventCreateWithFlags(&g_e1[i], cudaEventDisableTiming);
        cudaEventCreateWithFlags(&g_e2[i], cudaEventDisableTiming);
    }
    return true;
}();

// ---------------- launch ----------------
extern "C" void kernel_launch(void* const* d_in, const int* in_sizes, int n_in,
                              void* d_out, int out_size)
{
    const float* x       = (const float*)d_in[0];
    const int*   anchors = (const int*)  d_in[1];
    const float* Wq      = (const float*)d_in[2];
    const float* Wk      = (const float*)d_in[3];
    const float* Wv      = (const float*)d_in[4];
    const float* Wo      = (const float*)d_in[5];
    float* out = (float*)d_out;

    float *qp;
    __half *attp, *xhp, *wqtp, *wotp, *wktp, *wvtp;
    cudaGetSymbolAddress((void**)&qp,   g_q);
    cudaGetSymbolAddress((void**)&attp, g_att);
    cudaGetSymbolAddress((void**)&xhp,  g_xh);
    cudaGetSymbolAddress((void**)&wqtp, g_wqt);
    cudaGetSymbolAddress((void**)&wotp, g_wot);
    cudaGetSymbolAddress((void**)&wktp, g_wkt);
    cudaGetSymbolAddress((void**)&wvtp, g_wvt);

    cudaFuncSetAttribute(attn_mma_kernel, cudaFuncAttributeMaxDynamicSharedMemorySize, ATTN_SMEM);
    cudaFuncSetAttribute(gemm256_kernel, cudaFuncAttributeMaxDynamicSharedMemorySize, GEMM_SMEM);
    cudaFuncSetAttribute(sparse_kv_mma_kernel, cudaFuncAttributeMaxDynamicSharedMemorySize, KV_SMEM);

    const size_t ABLK = (size_t)32 * 64 * 4096;
    const size_t CBLK = (size_t)SS * DD;

    round_half_kernel<<<(BB * SS * DD / 4) / 256, 256>>>((const float4*)x, xhp);
    transpose_half_kernel<<<dim3(64, 64), dim3(32, 8)>>>(Wq, wqtp);
    cudaEventRecord(g_e0, 0);
    transpose_half_kernel<<<dim3(64, 64), dim3(32, 8)>>>(Wk, wktp);
    transpose_half_kernel<<<dim3(64, 64), dim3(32, 8)>>>(Wv, wvtp);
    sparse_kv_mma_kernel<<<dim3(64, 2), 256, KV_SMEM>>>(anchors);
    cudaEventRecord(g_ekv, 0);
    transpose_half_kernel<<<dim3(64, 64), dim3(32, 8)>>>(Wo, wotp);

    cudaStreamWaitEvent(g_s1, g_e0, 0);
    for (int b = 0; b < 4; b++) {
        gemm256_kernel<<<dim3(8, 32), 512, GEMM_SMEM, g_s1>>>(
            xhp + b * ABLK, wqtp, qp + b * CBLK);
        cudaEventRecord(g_e1[b], g_s1);
    }
    cudaStreamWaitEvent(g_s2, g_ekv, 0);
    for (int b = 0; b < 4; b++) {
        cudaStreamWaitEvent(g_s2, g_e1[b], 0);
        attn_mma_kernel<<<dim3(32, 16), 256, ATTN_SMEM, g_s2>>>(anchors, attp, b * 16);
        cudaEventRecord(g_e2[b], g_s2);
    }
    for (int b = 0; b < 4; b++) {
        cudaStreamWaitEvent(0, g_e2[b], 0);
        gemm256_kernel<<<dim3(8, 32), 512, GEMM_SMEM>>>(
            attp + b * ABLK, wotp, out + b * CBLK);
    }
}

// round 11
// speedup vs baseline: 7.4166x; 1.1096x over previous
#include <cuda_runtime.h>
#include <cuda_fp16.h>
#include <cstdint>
#include <math.h>

#define BB 4
#define SS 4096
#define DD 2048
#define HH 16
#define HDIM 128
#define NKEYS 128

// ---------------- scratch ----------------
__device__ __half g_qh [(size_t)BB * SS * DD];   // Q, attn-smem image: [mblk][head][q][128d swz]
__device__ __half g_att[(size_t)BB * SS * DD];   // half TILED (GEMM2 A)
__device__ __half g_xh [(size_t)BB * SS * DD];   // half TILED (GEMM1 + kv A)
__device__ __half g_wqt[2048 * 2048];            // half TILED [n][k]
__device__ __half g_wot[2048 * 2048];
__device__ __half g_wkt[2048 * 2048];
__device__ __half g_wvt[2048 * 2048];
__device__ float  g_ksp[64 * NKEYS * HDIM];
__device__ float  g_vsp[64 * NKEYS * HDIM];

// ---------------- helpers ----------------
__device__ __forceinline__ uint32_t smem_u32(const void* p) {
    uint32_t a;
    asm("{ .reg .u64 t; cvta.to.shared.u64 t, %1; cvt.u32.u64 %0, t; }" : "=r"(a) : "l"(p));
    return a;
}
#define CP_ASYNC16(dst, src) \
    asm volatile("cp.async.cg.shared.global [%0], [%1], 16;" :: "r"(dst), "l"(src) : "memory")
#define CP_COMMIT() asm volatile("cp.async.commit_group;" ::: "memory")
#define CP_WAIT(n)  asm volatile("cp.async.wait_group %0;" :: "n"(n) : "memory")
#define CP_BULK(dst, src, bytes, mbar) \
    asm volatile("cp.async.bulk.shared::cluster.global.mbarrier::complete_tx::bytes [%0], [%1], %2, [%3];" \
        :: "r"(dst), "l"(src), "r"(bytes), "r"(mbar) : "memory")
#define MBARRIER_INIT(addr, cnt) \
    asm volatile("mbarrier.init.shared.b64 [%0], %1;" :: "r"(addr), "r"(cnt) : "memory")
#define MBARRIER_EXPECT_TX(addr, tx) \
    asm volatile("mbarrier.arrive.expect_tx.shared.b64 _, [%0], %1;" :: "r"(addr), "r"(tx) : "memory")
#define MBARRIER_WAIT_PARITY(addr, ph) do { \
    uint32_t _m = (addr), _p = (ph), _d; \
    asm volatile("{\n\t.reg .pred p;\n\t" \
        "mbarrier.try_wait.parity.acquire.cta.shared::cta.b64 p, [%1], %2;\n\t" \
        "selp.b32 %0, 1, 0, p;\n\t}" : "=r"(_d) : "r"(_m), "r"(_p) : "memory"); \
    if (!_d) { \
        asm volatile("{\n\t.reg .pred P1;\n\tWL_%=:\n\t" \
            "mbarrier.try_wait.parity.acquire.cta.shared::cta.b64 P1, [%0], %1, 0x989680;\n\t" \
            "@P1 bra.uni WD_%=;\n\tbra.uni WL_%=;\n\tWD_%=:\n\t}" \
            :: "r"(_m), "r"(_p) : "memory"); \
    } } while (0)
#define LDMX4(r0, r1, r2, r3, addr) \
    asm volatile("ldmatrix.sync.aligned.m8n8.x4.shared.b16 {%0,%1,%2,%3}, [%4];" \
        : "=r"(r0), "=r"(r1), "=r"(r2), "=r"(r3) : "r"(addr))

__device__ __forceinline__ void mma_f16_16x8x16(
    float& c0, float& c1, float& c2, float& c3,
    uint32_t a0, uint32_t a1, uint32_t a2, uint32_t a3,
    uint32_t b0, uint32_t b1)
{
    asm volatile(
        "mma.sync.aligned.m16n8k16.row.col.f32.f16.f16.f32 "
        "{%0,%1,%2,%3}, {%4,%5,%6,%7}, {%8,%9}, {%0,%1,%2,%3};"
        : "+f"(c0), "+f"(c1), "+f"(c2), "+f"(c3)
        : "r"(a0), "r"(a1), "r"(a2), "r"(a3), "r"(b0), "r"(b1));
}

// ---------------- prep: x -> half TILED ----------------
__global__ void round_half_kernel(const float4* __restrict__ in, __half* __restrict__ out) {
    int i = blockIdx.x * 256 + threadIdx.x;
    float4 v = in[i];
    int m = i >> 9, c4 = i & 511;
    int kblk = c4 >> 3;
    int g0 = (c4 & 7) * 2;
    int r = m & 127, mblk = m >> 7;
    int phys = g0 ^ (((r >> 1) & 3) << 2);
    __half2* dst = (__half2*)(out + ((size_t)(mblk * 64 + kblk) * 4096 + r * 32 + phys * 2));
    dst[0] = __floats2half2_rn(v.x, v.y);
    dst[1] = __floats2half2_rn(v.z, v.w);
}

// ---------------- prep: W -> half TILED [n][k] ----------------
__global__ void transpose_half_kernel(const float* __restrict__ W, __half* __restrict__ WT) {
    __shared__ float t[32][33];
    int n0 = blockIdx.x * 32, k0 = blockIdx.y * 32;
    int tx = threadIdx.x, ty = threadIdx.y;
#pragma unroll
    for (int j = 0; j < 32; j += 8)
        t[ty + j][tx] = W[(size_t)(k0 + ty + j) * 2048 + n0 + tx];
    __syncthreads();
    int kblk = k0 >> 5;
#pragma unroll
    for (int j = 0; j < 32; j += 8) {
        int n = n0 + ty + j;
        int kcol = tx;
        int r = n & 127, nblk = n >> 7;
        int g = kcol >> 1, phys = g ^ (((r >> 1) & 3) << 2);
        WT[(size_t)(nblk * 64 + kblk) * 4096 + r * 32 + phys * 2 + (kcol & 1)] =
            __float2half_rn(t[tx][ty + j]);
    }
}

// ---------------- fp16 GEMM (cp.async.bulk + ldmatrix); mode1 epilogue -> g_qh ----------------
#define GSTAGE_B 24576
#define GSTAGE_H 12288
#define GEMM_SMEM (4 * GSTAGE_B + 64)

__global__ __launch_bounds__(512, 1) void gemm256_kernel(
    const __half* __restrict__ A, const __half* __restrict__ BW,
    float* __restrict__ C, __half* __restrict__ Qh, int mode)
{
    extern __shared__ __half shh[];
    uint32_t sb = smem_u32(shh);
    uint32_t mb = sb + 4 * GSTAGE_B;

    int tid = threadIdx.x;
    int wid = tid >> 5, lane = tid & 31;
    int wm = wid >> 2, wn = wid & 3;
    int gq = lane >> 2, kc = lane & 3;
    int n0 = blockIdx.x * 256, m0 = blockIdx.y * 128;

    if (tid == 0) {
#pragma unroll
        for (int s = 0; s < 4; s++) MBARRIER_INIT(mb + 8 * s, 1);
    }
    __syncthreads();

    const __half* Ab = A  + (size_t)(m0 >> 7) * 64 * 4096;
    const __half* B0 = BW + (size_t)(n0 >> 7) * 64 * 4096;
    const __half* B1 = BW + (size_t)((n0 >> 7) + 1) * 64 * 4096;

    if (tid == 0) {
#pragma unroll
        for (int s = 0; s < 3; s++) {
            MBARRIER_EXPECT_TX(mb + 8 * s, GSTAGE_B);
            CP_BULK(sb + s * GSTAGE_B,         Ab + (size_t)s * 4096, 8192, mb + 8 * s);
            CP_BULK(sb + s * GSTAGE_B + 8192,  B0 + (size_t)s * 4096, 8192, mb + 8 * s);
            CP_BULK(sb + s * GSTAGE_B + 16384, B1 + (size_t)s * 4096, 8192, mb + 8 * s);
        }
    }

    int laneAr = wm * 32 + (lane & 7) + (((lane >> 3) & 1) << 3);
    int cA = lane >> 4;
    int swA = (laneAr >> 1) & 3;
    uint32_t aAddr0 = sb + (uint32_t)laneAr * 64 + (uint32_t)((cA     ^ swA) << 4);
    uint32_t aAddr1 = sb + (uint32_t)laneAr * 64 + (uint32_t)(((2|cA) ^ swA) << 4);
    int laneBr = wn * 64 + ((lane >> 4) << 3) + (lane & 7);
    int cB = (lane >> 3) & 1;
    int swB = (laneBr >> 1) & 3;
    uint32_t bAddr0 = sb + 8192 + (uint32_t)laneBr * 64 + (uint32_t)((cB     ^ swB) << 4);
    uint32_t bAddr1 = sb + 8192 + (uint32_t)laneBr * 64 + (uint32_t)(((2|cB) ^ swB) << 4);

    float acc[2][8][4];
#pragma unroll
    for (int i = 0; i < 2; i++)
#pragma unroll
        for (int j = 0; j < 8; j++)
#pragma unroll
            for (int r = 0; r < 4; r++) acc[i][j][r] = 0.f;

    for (int kt = 0; kt < 64; kt++) {
        int s = kt & 3;
        MBARRIER_WAIT_PARITY(mb + 8 * s, (kt >> 2) & 1);
        uint32_t so = (uint32_t)s * GSTAGE_B;
#pragma unroll
        for (int t = 0; t < 2; t++) {
            uint32_t aA = (t ? aAddr1 : aAddr0) + so;
            uint32_t bA = (t ? bAddr1 : bAddr0) + so;
            uint32_t af[2][4], bf[8][2];
            LDMX4(af[0][0], af[0][1], af[0][2], af[0][3], aA);
            LDMX4(af[1][0], af[1][1], af[1][2], af[1][3], aA + 1024);
#pragma unroll
            for (int nfp = 0; nfp < 4; nfp++)
                LDMX4(bf[2 * nfp][0], bf[2 * nfp][1], bf[2 * nfp + 1][0], bf[2 * nfp + 1][1],
                      bA + nfp * 1024);
#pragma unroll
            for (int mf = 0; mf < 2; mf++)
#pragma unroll
                for (int nf = 0; nf < 8; nf++)
                    mma_f16_16x8x16(acc[mf][nf][0], acc[mf][nf][1],
                                    acc[mf][nf][2], acc[mf][nf][3],
                                    af[mf][0], af[mf][1], af[mf][2], af[mf][3],
                                    bf[nf][0], bf[nf][1]);
        }
        __syncthreads();
        if (tid == 0 && kt + 3 < 64) {
            int s2 = (kt + 3) & 3;
            MBARRIER_EXPECT_TX(mb + 8 * s2, GSTAGE_B);
            CP_BULK(sb + s2 * GSTAGE_B,         Ab + (size_t)(kt + 3) * 4096, 8192, mb + 8 * s2);
            CP_BULK(sb + s2 * GSTAGE_B + 8192,  B0 + (size_t)(kt + 3) * 4096, 8192, mb + 8 * s2);
            CP_BULK(sb + s2 * GSTAGE_B + 16384, B1 + (size_t)(kt + 3) * 4096, 8192, mb + 8 * s2);
        }
    }

    if (mode == 0) {
#pragma unroll
        for (int mf = 0; mf < 2; mf++) {
            int r0 = m0 + wm * 32 + mf * 16 + gq;
#pragma unroll
            for (int nf = 0; nf < 8; nf++) {
                int col = n0 + wn * 64 + nf * 8 + kc * 2;
                *(float2*)&C[(size_t)r0 * 2048 + col]       = make_float2(acc[mf][nf][0], acc[mf][nf][1]);
                *(float2*)&C[(size_t)(r0 + 8) * 2048 + col] = make_float2(acc[mf][nf][2], acc[mf][nf][3]);
            }
        }
    } else {
        // write half into attn Q image: ((mblk*16 + head)*128 + q)*128 + swz(d)
#pragma unroll
        for (int mf = 0; mf < 2; mf++) {
            int r0 = m0 + wm * 32 + mf * 16 + gq;
            int q = r0 & 127, mblk = r0 >> 7;
            int sw = (q & 7) << 2;
#pragma unroll
            for (int nf = 0; nf < 8; nf++) {
                int col = n0 + wn * 64 + nf * 8 + kc * 2;
                int head = col >> 7, d = col & 127;
                int phys = (d >> 1) ^ sw;
                size_t base = ((size_t)(mblk * 16 + head) * 128 + q) * 128 + phys * 2;
                *(__half2*)(Qh + base)       = __floats2half2_rn(acc[mf][nf][0], acc[mf][nf][1]);
                *(__half2*)(Qh + base + 1024)= __floats2half2_rn(acc[mf][nf][2], acc[mf][nf][3]); // q+8: +8*128
            }
        }
    }
}

// ---------------- sparse K/V projection (fp16 mma + ldmatrix) ----------------
#define KVSTAGE_B 16384
#define KVSTAGE_H 8192
#define KV_SMEM (4 * KVSTAGE_B + 128 * 4)

__global__ __launch_bounds__(256, 1) void sparse_kv_mma_kernel(
    const int* __restrict__ anchors)
{
    extern __shared__ __half shh[];
    int* tok = (int*)(shh + 4 * KVSTAGE_H);

    int tid = threadIdx.x;
    int bh = blockIdx.x;
    int h = bh & 15, b = bh >> 4;
    const __half* Bb = (blockIdx.y ? g_wvt : g_wkt) + (size_t)h * 64 * 4096;
    float* out = (blockIdx.y ? g_vsp : g_ksp) + (size_t)bh * NKEYS * HDIM;

    if (tid < 128) {
        int ti = tid >> 4;
        int tile = (ti == 7) ? 255 : anchors[(bh << 3) + ti];
        tok[tid] = tile * 16 + (tid & 15);
    }
    __syncthreads();

    int wid = tid >> 5, lane = tid & 31;
    int wm = wid >> 2, wn = wid & 3;
    int gq = lane >> 2, kc = lane & 3;

    uint32_t sb = smem_u32(shh);

    int laneAr = wm * 64 + (lane & 7) + (((lane >> 3) & 1) << 3);
    int cA = lane >> 4;
    int swA = (laneAr >> 1) & 3;
    uint32_t aAddr0 = sb + (uint32_t)laneAr * 64 + (uint32_t)((cA     ^ swA) << 4);
    uint32_t aAddr1 = sb + (uint32_t)laneAr * 64 + (uint32_t)(((2|cA) ^ swA) << 4);
    int laneBr = wn * 32 + ((lane >> 4) << 3) + (lane & 7);
    int cB = (lane >> 3) & 1;
    int swB = (laneBr >> 1) & 3;
    uint32_t bAddr0 = sb + 8192 + (uint32_t)laneBr * 64 + (uint32_t)((cB     ^ swB) << 4);
    uint32_t bAddr1 = sb + 8192 + (uint32_t)laneBr * 64 + (uint32_t)(((2|cB) ^ swB) << 4);

    float acc[4][4][4];
#pragma unroll
    for (int i = 0; i < 4; i++)
#pragma unroll
        for (int j = 0; j < 4; j++)
#pragma unroll
            for (int r = 0; r < 4; r++) acc[i][j][r] = 0.f;

#pragma unroll
    for (int s = 0; s < 3; s++) {
        uint32_t so = sb + s * KVSTAGE_B;
#pragma unroll
        for (int i = 0; i < 2; i++) {
            int cidx = i * 256 + tid;
            int rs = cidx >> 2, c = cidx & 3;
            int grow = b * SS + tok[rs];
            const __half* srcA = g_xh + (size_t)((grow >> 7) * 64 + s) * 4096
                               + (grow & 127) * 32 + ((c ^ ((grow >> 1) & 3)) * 8);
            CP_ASYNC16(so + (uint32_t)(rs * 64 + (c ^ ((rs >> 1) & 3)) * 16), srcA);
            const __half* srcB = Bb + (size_t)s * 4096 + rs * 32 + ((c ^ ((rs >> 1) & 3)) * 8);
            CP_ASYNC16(so + 8192 + (uint32_t)(rs * 64 + (c ^ ((rs >> 1) & 3)) * 16), srcB);
        }
        CP_COMMIT();
    }

    for (int kt = 0; kt < 64; kt++) {
        CP_WAIT(2);
        __syncthreads();
        if (kt + 3 < 64) {
            int sl = kt + 3;
            uint32_t so = sb + (uint32_t)(sl & 3) * KVSTAGE_B;
#pragma unroll
            for (int i = 0; i < 2; i++) {
                int cidx = i * 256 + tid;
                int rs = cidx >> 2, c = cidx & 3;
                int grow = b * SS + tok[rs];
                const __half* srcA = g_xh + (size_t)((grow >> 7) * 64 + sl) * 4096
                                   + (grow & 127) * 32 + ((c ^ ((grow >> 1) & 3)) * 8);
                CP_ASYNC16(so + (uint32_t)(rs * 64 + (c ^ ((rs >> 1) & 3)) * 16), srcA);
                const __half* srcB = Bb + (size_t)sl * 4096 + rs * 32 + ((c ^ ((rs >> 1) & 3)) * 8);
                CP_ASYNC16(so + 8192 + (uint32_t)(rs * 64 + (c ^ ((rs >> 1) & 3)) * 16), srcB);
            }
        }
        CP_COMMIT();

        uint32_t so = (uint32_t)(kt & 3) * KVSTAGE_B;
#pragma unroll
        for (int t = 0; t < 2; t++) {
            uint32_t aA = (t ? aAddr1 : aAddr0) + so;
            uint32_t bA = (t ? bAddr1 : bAddr0) + so;
            uint32_t af[4][4], bf[4][2];
#pragma unroll
            for (int mf = 0; mf < 4; mf++)
                LDMX4(af[mf][0], af[mf][1], af[mf][2], af[mf][3], aA + mf * 1024);
#pragma unroll
            for (int nfp = 0; nfp < 2; nfp++)
                LDMX4(bf[2 * nfp][0], bf[2 * nfp][1], bf[2 * nfp + 1][0], bf[2 * nfp + 1][1],
                      bA + nfp * 1024);
#pragma unroll
            for (int mf = 0; mf < 4; mf++)
#pragma unroll
                for (int nf = 0; nf < 4; nf++)
                    mma_f16_16x8x16(acc[mf][nf][0], acc[mf][nf][1],
                                    acc[mf][nf][2], acc[mf][nf][3],
                                    af[mf][0], af[mf][1], af[mf][2], af[mf][3],
                                    bf[nf][0], bf[nf][1]);
        }
    }

#pragma unroll
    for (int mf = 0; mf < 4; mf++) {
        int r0 = wm * 64 + mf * 16 + gq;
#pragma unroll
        for (int nf = 0; nf < 4; nf++) {
            int col = wn * 32 + nf * 8 + kc * 2;
            *(float2*)&out[(size_t)r0 * 128 + col]       = make_float2(acc[mf][nf][0], acc[mf][nf][1]);
            *(float2*)&out[(size_t)(r0 + 8) * 128 + col] = make_float2(acc[mf][nf][2], acc[mf][nf][3]);
        }
    }
}

// ---------------- attention: fp16 mma + ldmatrix; Q via bulk copy ----------------
#define SAST 132
#define ATTN_TOK_OFF (3 * 32768 + 128 * SAST * 4)
#define ATTN_SMEM (ATTN_TOK_OFF + 512 + 16)

__global__ __launch_bounds__(256) void attn_mma_kernel(
    const int* __restrict__ anchors, __half* __restrict__ attout, int bhbase)
{
    extern __shared__ char smraw[];
    __half* Kh  = (__half*)smraw;              // [key][128d] swizzled 256B rows
    __half* Vth = Kh + 16384;                  // [d][128key]
    __half* QPh = Vth + 16384;                 // [q][128] Q then P
    float*  Sf  = (float*)(QPh + 16384);
    int*    tok = (int*)(smraw + ATTN_TOK_OFF);
    uint32_t sbb = smem_u32(smraw);
    uint32_t mb = sbb + ATTN_TOK_OFF + 512;

    int tid = threadIdx.x;
    int bh = bhbase + blockIdx.y;
    int b = bh >> 4, h = bh & 15;
    int q0 = blockIdx.x * 128;
    int wid = tid >> 5, lane = tid & 31;
    int gq = lane >> 2, kc = lane & 3;

    if (tid == 0) MBARRIER_INIT(mb, 1);
    if (tid < 128) {
        int ti = tid >> 4;
        int tile = (ti == 7) ? 255 : anchors[(bh << 3) + ti];
        tok[tid] = tile * 16 + (tid & 15);
    }
    __syncthreads();

    if (tid == 0) {
        const __half* qsrc = g_qh + ((size_t)((b * 32 + (q0 >> 7)) * 16 + h) * 16384);
        MBARRIER_EXPECT_TX(mb, 32768);
        CP_BULK(sbb + 2 * 32768, qsrc, 32768, mb);
    }

    const float* kg = g_ksp + (size_t)bh * 16384;
    for (int idx = tid; idx < 4096; idx += 256) {
        int key = idx >> 5, d4 = idx & 31;
        float4 v = *(const float4*)(kg + key * 128 + d4 * 4);
        int p0 = (d4 * 2) ^ ((key & 7) << 2);
        *(__half2*)(Kh + key * 128 + p0 * 2)       = __floats2half2_rn(v.x, v.y);
        *(__half2*)(Kh + key * 128 + (p0 + 1) * 2) = __floats2half2_rn(v.z, v.w);
    }
    const float* vg = g_vsp + (size_t)bh * 16384;
    for (int idx = tid; idx < 16384; idx += 256) {
        int key = idx >> 7, d = idx & 127;
        int phys = (key >> 1) ^ ((d & 7) << 2);
        Vth[d * 128 + phys * 2 + (key & 1)] = __float2half_rn(vg[idx]);
    }
    __syncthreads();
    MBARRIER_WAIT_PARITY(mb, 0);

    // ldmatrix lane addressing (256B rows, chunk swizzle c ^ (r&7))
    int laneAr = wid * 16 + (lane & 7) + (((lane >> 3) & 1) << 3);
    int cA = lane >> 4;
    int laneBr = ((lane >> 4) << 3) + (lane & 7);
    int cB = (lane >> 3) & 1;
    uint32_t qBase = sbb + 2 * 32768 + (uint32_t)laneAr * 256;
    uint32_t kBase = sbb + (uint32_t)laneBr * 256;
    uint32_t vBase = sbb + 32768 + (uint32_t)laneBr * 256;
    int swAa = laneAr & 7, swBa = laneBr & 7;

    int r = wid * 16 + gq;

    // ---- S = Q @ K^T ----
    float acc[16][4];
#pragma unroll
    for (int nf = 0; nf < 16; nf++)
#pragma unroll
        for (int z = 0; z < 4; z++) acc[nf][z] = 0.f;
#pragma unroll
    for (int t = 0; t < 8; t++) {
        uint32_t af[4], bf[16][2];
        LDMX4(af[0], af[1], af[2], af[3], qBase + (uint32_t)(((2 * t + cA) ^ swAa) << 4));
#pragma unroll
        for (int nfp = 0; nfp < 8; nfp++)
            LDMX4(bf[2 * nfp][0], bf[2 * nfp][1], bf[2 * nfp + 1][0], bf[2 * nfp + 1][1],
                  kBase + nfp * 4096 + (uint32_t)(((2 * t + cB) ^ swBa) << 4));
#pragma unroll
        for (int nf = 0; nf < 16; nf++)
            mma_f16_16x8x16(acc[nf][0], acc[nf][1], acc[nf][2], acc[nf][3],
                            af[0], af[1], af[2], af[3], bf[nf][0], bf[nf][1]);
    }
#pragma unroll
    for (int nf = 0; nf < 16; nf++) {
        int col = nf * 8 + kc * 2;
        Sf[r * SAST + col]           = acc[nf][0];
        Sf[r * SAST + col + 1]       = acc[nf][1];
        Sf[(r + 8) * SAST + col]     = acc[nf][2];
        Sf[(r + 8) * SAST + col + 1] = acc[nf][3];
    }
    __syncthreads();

    // ---- softmax (fp32), write P into QPh (same swizzle) ----
    {
        const float scale = 0.0883883476483184f;
        int row = tid >> 1, hc = (tid & 1) * 64;
        int qpos = q0 + row;
        float* S = Sf + row * SAST + hc;
        float mx = -3.0e38f;
#pragma unroll 16
        for (int c = 0; c < 64; c++) {
            float v = S[c] * scale;
            if (tok[hc + c] > qpos) v = -1e10f;
            mx = fmaxf(mx, v);
        }
        mx = fmaxf(mx, __shfl_xor_sync(0xffffffffu, mx, 1));
        float sum = 0.f;
        float e[64];
#pragma unroll 16
        for (int c = 0; c < 64; c++) {
            float v = S[c] * scale;
            if (tok[hc + c] > qpos) v = -1e10f;
            e[c] = __expf(v - mx);
            sum += e[c];
        }
        sum += __shfl_xor_sync(0xffffffffu, sum, 1);
        float inv = 1.f / sum;
        int sw = (row & 7) << 2;
#pragma unroll 16
        for (int c = 0; c < 64; c += 2) {
            int g = (hc + c) >> 1, phys = g ^ sw;
            *(__half2*)(QPh + row * 128 + phys * 2) =
                __floats2half2_rn(e[c] * inv, e[c + 1] * inv);
        }
    }
    __syncthreads();

    // ---- O = P @ V ----
    float acc2[16][4];
#pragma unroll
    for (int nf = 0; nf < 16; nf++)
#pragma unroll
        for (int z = 0; z < 4; z++) acc2[nf][z] = 0.f;
#pragma unroll
    for (int t = 0; t < 8; t++) {
        uint32_t af[4], bf[16][2];
        LDMX4(af[0], af[1], af[2], af[3], qBase + (uint32_t)(((2 * t + cA) ^ swAa) << 4));
#pragma unroll
        for (int nfp = 0; nfp < 8; nfp++)
            LDMX4(bf[2 * nfp][0], bf[2 * nfp][1], bf[2 * nfp + 1][0], bf[2 * nfp + 1][1],
                  vBase + nfp * 4096 + (uint32_t)(((2 * t + cB) ^ swBa) << 4));
#pragma unroll
        for (int nf = 0; nf < 16; nf++)
            mma_f16_16x8x16(acc2[nf][0], acc2[nf][1], acc2[nf][2], acc2[nf][3],
                            af[0], af[1], af[2], af[3], bf[nf][0], bf[nf][1]);
    }

    // ---- store O in half TILED layout (GEMM2 A operand) ----
    {
        int mblk = (b * SS + q0) >> 7;
        __half* abase = attout + (size_t)mblk * 64 * 4096;
        int sw = ((r >> 1) & 3) << 2;
#pragma unroll
        for (int nf = 0; nf < 16; nf++) {
            int col = h * HDIM + nf * 8 + kc * 2;
            int kblk = col >> 5, kcol = col & 31;
            int phys = (kcol >> 1) ^ sw;
            *(__half2*)(abase + (size_t)kblk * 4096 + r * 32 + phys * 2) =
                __floats2half2_rn(acc2[nf][0], acc2[nf][1]);
            *(__half2*)(abase + (size_t)kblk * 4096 + (r + 8) * 32 + phys * 2) =
                __floats2half2_rn(acc2[nf][2], acc2[nf][3]);
        }
    }
}

// ---------------- streams/events ----------------
static cudaStream_t g_s1, g_s2;
static cudaEvent_t g_e0, g_ekv, g_e1[4], g_e2[4];
static bool g_streams_ok = [](){
    cudaStreamCreateWithFlags(&g_s1, cudaStreamNonBlocking);
    cudaStreamCreateWithFlags(&g_s2, cudaStreamNonBlocking);
    cudaEventCreateWithFlags(&g_e0,  cudaEventDisableTiming);
    cudaEventCreateWithFlags(&g_ekv, cudaEventDisableTiming);
    for (int i = 0; i < 4; i++) {
        cudaEventCreateWithFlags(&g_e1[i], cudaEventDisableTiming);
        cudaEventCreateWithFlags(&g_e2[i], cudaEventDisableTiming);
    }
    return true;
}();

// ---------------- launch ----------------
extern "C" void kernel_launch(void* const* d_in, const int* in_sizes, int n_in,
                              void* d_out, int out_size)
{
    const float* x       = (const float*)d_in[0];
    const int*   anchors = (const int*)  d_in[1];
    const float* Wq      = (const float*)d_in[2];
    const float* Wk      = (const float*)d_in[3];
    const float* Wv      = (const float*)d_in[4];
    const float* Wo      = (const float*)d_in[5];
    float* out = (float*)d_out;

    __half *qhp, *attp, *xhp, *wqtp, *wotp, *wktp, *wvtp;
    cudaGetSymbolAddress((void**)&qhp,  g_qh);
    cudaGetSymbolAddress((void**)&attp, g_att);
    cudaGetSymbolAddress((void**)&xhp,  g_xh);
    cudaGetSymbolAddress((void**)&wqtp, g_wqt);
    cudaGetSymbolAddress((void**)&wotp, g_wot);
    cudaGetSymbolAddress((void**)&wktp, g_wkt);
    cudaGetSymbolAddress((void**)&wvtp, g_wvt);

    cudaFuncSetAttribute(attn_mma_kernel, cudaFuncAttributeMaxDynamicSharedMemorySize, ATTN_SMEM);
    cudaFuncSetAttribute(gemm256_kernel, cudaFuncAttributeMaxDynamicSharedMemorySize, GEMM_SMEM);
    cudaFuncSetAttribute(sparse_kv_mma_kernel, cudaFuncAttributeMaxDynamicSharedMemorySize, KV_SMEM);

    const size_t ABLK = (size_t)32 * 64 * 4096;   // half elems per batch (tiled)
    const size_t QBLK = (size_t)SS * DD;          // half elems per batch (q image)
    const size_t CBLK = (size_t)SS * DD;          // fp32 elems per batch

    round_half_kernel<<<(BB * SS * DD / 4) / 256, 256>>>((const float4*)x, xhp);
    transpose_half_kernel<<<dim3(64, 64), dim3(32, 8)>>>(Wq, wqtp);
    cudaEventRecord(g_e0, 0);
    transpose_half_kernel<<<dim3(64, 64), dim3(32, 8)>>>(Wk, wktp);
    transpose_half_kernel<<<dim3(64, 64), dim3(32, 8)>>>(Wv, wvtp);
    sparse_kv_mma_kernel<<<dim3(64, 2), 256, KV_SMEM>>>(anchors);
    cudaEventRecord(g_ekv, 0);
    transpose_half_kernel<<<dim3(64, 64), dim3(32, 8)>>>(Wo, wotp);

    cudaStreamWaitEvent(g_s1, g_e0, 0);
    for (int b = 0; b < 4; b++) {
        gemm256_kernel<<<dim3(8, 32), 512, GEMM_SMEM, g_s1>>>(
            xhp + b * ABLK, wqtp, nullptr, qhp + b * QBLK, 1);
        cudaEventRecord(g_e1[b], g_s1);
    }
    cudaStreamWaitEvent(g_s2, g_ekv, 0);
    for (int b = 0; b < 4; b++) {
        cudaStreamWaitEvent(g_s2, g_e1[b], 0);
        attn_mma_kernel<<<dim3(32, 16), 256, ATTN_SMEM, g_s2>>>(anchors, attp, b * 16);
        cudaEventRecord(g_e2[b], g_s2);
    }
    for (int b = 0; b < 4; b++) {
        cudaStreamWaitEvent(0, g_e2[b], 0);
        gemm256_kernel<<<dim3(8, 32), 512, GEMM_SMEM>>>(
            attp + b * ABLK, wotp, out + b * CBLK, nullptr, 0);
    }
}

// round 13
// speedup vs baseline: 8.4682x; 1.1418x over previous
#include <cuda_runtime.h>
#include <cuda_fp16.h>
#include <cstdint>
#include <math.h>

#define BB 4
#define SS 4096
#define DD 2048
#define HH 16
#define HDIM 128
#define NKEYS 128

// ---------------- scratch ----------------
__device__ __half g_qh [(size_t)BB * SS * DD];   // Q, attn-smem image
__device__ __half g_att[(size_t)BB * SS * DD];   // half TILED (GEMM2 A)
__device__ __half g_xh [(size_t)BB * SS * DD];   // half TILED
__device__ __half g_wqt[2048 * 2048];            // half TILED [n][k]
__device__ __half g_wot[2048 * 2048];
__device__ __half g_wkt[2048 * 2048];
__device__ __half g_wvt[2048 * 2048];
__device__ float  g_ksp[64 * NKEYS * HDIM];
__device__ float  g_vsp[64 * NKEYS * HDIM];

// ---------------- helpers ----------------
__device__ __forceinline__ uint32_t smem_u32(const void* p) {
    uint32_t a;
    asm("{ .reg .u64 t; cvta.to.shared.u64 t, %1; cvt.u32.u64 %0, t; }" : "=r"(a) : "l"(p));
    return a;
}
#define CP_ASYNC16(dst, src) \
    asm volatile("cp.async.cg.shared.global [%0], [%1], 16;" :: "r"(dst), "l"(src) : "memory")
#define CP_COMMIT() asm volatile("cp.async.commit_group;" ::: "memory")
#define CP_WAIT(n)  asm volatile("cp.async.wait_group %0;" :: "n"(n) : "memory")
#define CP_BULK(dst, src, bytes, mbar) \
    asm volatile("cp.async.bulk.shared::cluster.global.mbarrier::complete_tx::bytes [%0], [%1], %2, [%3];" \
        :: "r"(dst), "l"(src), "r"(bytes), "r"(mbar) : "memory")
#define MBARRIER_INIT(addr, cnt) \
    asm volatile("mbarrier.init.shared.b64 [%0], %1;" :: "r"(addr), "r"(cnt) : "memory")
#define MBARRIER_EXPECT_TX(addr, tx) \
    asm volatile("mbarrier.arrive.expect_tx.shared.b64 _, [%0], %1;" :: "r"(addr), "r"(tx) : "memory")
#define MBARRIER_WAIT_PARITY(addr, ph) do { \
    uint32_t _m = (addr), _p = (ph), _d; \
    asm volatile("{\n\t.reg .pred p;\n\t" \
        "mbarrier.try_wait.parity.acquire.cta.shared::cta.b64 p, [%1], %2;\n\t" \
        "selp.b32 %0, 1, 0, p;\n\t}" : "=r"(_d) : "r"(_m), "r"(_p) : "memory"); \
    if (!_d) { \
        asm volatile("{\n\t.reg .pred P1;\n\tWL_%=:\n\t" \
            "mbarrier.try_wait.parity.acquire.cta.shared::cta.b64 P1, [%0], %1, 0x989680;\n\t" \
            "@P1 bra.uni WD_%=;\n\tbra.uni WL_%=;\n\tWD_%=:\n\t}" \
            :: "r"(_m), "r"(_p) : "memory"); \
    } } while (0)
#define LDMX4(r0, r1, r2, r3, addr) \
    asm volatile("ldmatrix.sync.aligned.m8n8.x4.shared.b16 {%0,%1,%2,%3}, [%4];" \
        : "=r"(r0), "=r"(r1), "=r"(r2), "=r"(r3) : "r"(addr))

__device__ __forceinline__ void mma_f16_16x8x16(
    float& c0, float& c1, float& c2, float& c3,
    uint32_t a0, uint32_t a1, uint32_t a2, uint32_t a3,
    uint32_t b0, uint32_t b1)
{
    asm volatile(
        "mma.sync.aligned.m16n8k16.row.col.f32.f16.f16.f32 "
        "{%0,%1,%2,%3}, {%4,%5,%6,%7}, {%8,%9}, {%0,%1,%2,%3};"
        : "+f"(c0), "+f"(c1), "+f"(c2), "+f"(c3)
        : "r"(a0), "r"(a1), "r"(a2), "r"(a3), "r"(b0), "r"(b1));
}

// ---------------- prep: x -> half TILED ----------------
__global__ void round_half_kernel(const float4* __restrict__ in, __half* __restrict__ out) {
    int i = blockIdx.x * 256 + threadIdx.x;
    float4 v = in[i];
    int m = i >> 9, c4 = i & 511;
    int kblk = c4 >> 3;
    int g0 = (c4 & 7) * 2;
    int r = m & 127, mblk = m >> 7;
    int phys = g0 ^ (((r >> 1) & 3) << 2);
    __half2* dst = (__half2*)(out + ((size_t)(mblk * 64 + kblk) * 4096 + r * 32 + phys * 2));
    dst[0] = __floats2half2_rn(v.x, v.y);
    dst[1] = __floats2half2_rn(v.z, v.w);
}

// ---------------- prep: W -> half TILED [n][k], vectorized 16B stores ----------------
__global__ void transpose_half_kernel(const float* __restrict__ W, __half* __restrict__ WT) {
    __shared__ float t[32][132];
    int n0 = blockIdx.x * 128, kblk = blockIdx.y, k0 = kblk * 32;
    int tid = threadIdx.x;
#pragma unroll
    for (int i = 0; i < 16; i++) {
        int lin = i * 256 + tid;
        int k = lin >> 7, n = lin & 127;
        t[k][n] = W[(size_t)(k0 + k) * 2048 + n0 + n];
    }
    __syncthreads();
    int r = tid & 127;
    int cbase = (tid >> 7) * 2;
    int sw = (r >> 1) & 3;
    __half* obase = WT + (size_t)((n0 >> 7) * 64 + kblk) * 4096 + r * 32;
#pragma unroll
    for (int cc = 0; cc < 2; cc++) {
        int c = cbase + cc;
        __half h[8];
#pragma unroll
        for (int i = 0; i < 8; i++) h[i] = __float2half_rn(t[c * 8 + i][r]);
        *(uint4*)(obase + ((c ^ sw) * 8)) = *(uint4*)h;
    }
}

// ---------------- fp16 GEMM (cp.async.bulk + ldmatrix); mode1 epilogue -> g_qh ----------------
#define GSTAGE_B 24576
#define GSTAGE_H 12288
#define GEMM_SMEM (4 * GSTAGE_B + 64)

__global__ __launch_bounds__(512, 1) void gemm256_kernel(
    const __half* __restrict__ A, const __half* __restrict__ BW,
    float* __restrict__ C, __half* __restrict__ Qh, int mode)
{
    extern __shared__ __half shh[];
    uint32_t sb = smem_u32(shh);
    uint32_t mb = sb + 4 * GSTAGE_B;

    int tid = threadIdx.x;
    int wid = tid >> 5, lane = tid & 31;
    int wm = wid >> 2, wn = wid & 3;
    int gq = lane >> 2, kc = lane & 3;
    int n0 = blockIdx.x * 256, m0 = blockIdx.y * 128;

    if (tid == 0) {
#pragma unroll
        for (int s = 0; s < 4; s++) MBARRIER_INIT(mb + 8 * s, 1);
    }
    __syncthreads();

    const __half* Ab = A  + (size_t)(m0 >> 7) * 64 * 4096;
    const __half* B0 = BW + (size_t)(n0 >> 7) * 64 * 4096;
    const __half* B1 = BW + (size_t)((n0 >> 7) + 1) * 64 * 4096;

    if (tid == 0) {
#pragma unroll
        for (int s = 0; s < 3; s++) {
            MBARRIER_EXPECT_TX(mb + 8 * s, GSTAGE_B);
            CP_BULK(sb + s * GSTAGE_B,         Ab + (size_t)s * 4096, 8192, mb + 8 * s);
            CP_BULK(sb + s * GSTAGE_B + 8192,  B0 + (size_t)s * 4096, 8192, mb + 8 * s);
            CP_BULK(sb + s * GSTAGE_B + 16384, B1 + (size_t)s * 4096, 8192, mb + 8 * s);
        }
    }

    int laneAr = wm * 32 + (lane & 7) + (((lane >> 3) & 1) << 3);
    int cA = lane >> 4;
    int swA = (laneAr >> 1) & 3;
    uint32_t aAddr0 = sb + (uint32_t)laneAr * 64 + (uint32_t)((cA     ^ swA) << 4);
    uint32_t aAddr1 = sb + (uint32_t)laneAr * 64 + (uint32_t)(((2|cA) ^ swA) << 4);
    int laneBr = wn * 64 + ((lane >> 4) << 3) + (lane & 7);
    int cB = (lane >> 3) & 1;
    int swB = (laneBr >> 1) & 3;
    uint32_t bAddr0 = sb + 8192 + (uint32_t)laneBr * 64 + (uint32_t)((cB     ^ swB) << 4);
    uint32_t bAddr1 = sb + 8192 + (uint32_t)laneBr * 64 + (uint32_t)(((2|cB) ^ swB) << 4);

    float acc[2][8][4];
#pragma unroll
    for (int i = 0; i < 2; i++)
#pragma unroll
        for (int j = 0; j < 8; j++)
#pragma unroll
            for (int r = 0; r < 4; r++) acc[i][j][r] = 0.f;

    for (int kt = 0; kt < 64; kt++) {
        int s = kt & 3;
        MBARRIER_WAIT_PARITY(mb + 8 * s, (kt >> 2) & 1);
        uint32_t so = (uint32_t)s * GSTAGE_B;
#pragma unroll
        for (int t = 0; t < 2; t++) {
            uint32_t aA = (t ? aAddr1 : aAddr0) + so;
            uint32_t bA = (t ? bAddr1 : bAddr0) + so;
            uint32_t af[2][4], bf[8][2];
            LDMX4(af[0][0], af[0][1], af[0][2], af[0][3], aA);
            LDMX4(af[1][0], af[1][1], af[1][2], af[1][3], aA + 1024);
#pragma unroll
            for (int nfp = 0; nfp < 4; nfp++)
                LDMX4(bf[2 * nfp][0], bf[2 * nfp][1], bf[2 * nfp + 1][0], bf[2 * nfp + 1][1],
                      bA + nfp * 1024);
#pragma unroll
            for (int mf = 0; mf < 2; mf++)
#pragma unroll
                for (int nf = 0; nf < 8; nf++)
                    mma_f16_16x8x16(acc[mf][nf][0], acc[mf][nf][1],
                                    acc[mf][nf][2], acc[mf][nf][3],
                                    af[mf][0], af[mf][1], af[mf][2], af[mf][3],
                                    bf[nf][0], bf[nf][1]);
        }
        __syncthreads();
        if (tid == 0 && kt + 3 < 64) {
            int s2 = (kt + 3) & 3;
            MBARRIER_EXPECT_TX(mb + 8 * s2, GSTAGE_B);
            CP_BULK(sb + s2 * GSTAGE_B,         Ab + (size_t)(kt + 3) * 4096, 8192, mb + 8 * s2);
            CP_BULK(sb + s2 * GSTAGE_B + 8192,  B0 + (size_t)(kt + 3) * 4096, 8192, mb + 8 * s2);
            CP_BULK(sb + s2 * GSTAGE_B + 16384, B1 + (size_t)(kt + 3) * 4096, 8192, mb + 8 * s2);
        }
    }

    if (mode == 0) {
#pragma unroll
        for (int mf = 0; mf < 2; mf++) {
            int r0 = m0 + wm * 32 + mf * 16 + gq;
#pragma unroll
            for (int nf = 0; nf < 8; nf++) {
                int col = n0 + wn * 64 + nf * 8 + kc * 2;
                *(float2*)&C[(size_t)r0 * 2048 + col]       = make_float2(acc[mf][nf][0], acc[mf][nf][1]);
                *(float2*)&C[(size_t)(r0 + 8) * 2048 + col] = make_float2(acc[mf][nf][2], acc[mf][nf][3]);
            }
        }
    } else {
#pragma unroll
        for (int mf = 0; mf < 2; mf++) {
            int r0 = m0 + wm * 32 + mf * 16 + gq;
            int q = r0 & 127, mblk = r0 >> 7;
            int sw = (q & 7) << 2;
#pragma unroll
            for (int nf = 0; nf < 8; nf++) {
                int col = n0 + wn * 64 + nf * 8 + kc * 2;
                int head = col >> 7, d = col & 127;
                int phys = (d >> 1) ^ sw;
                size_t base = ((size_t)(mblk * 16 + head) * 128 + q) * 128 + phys * 2;
                *(__half2*)(Qh + base)        = __floats2half2_rn(acc[mf][nf][0], acc[mf][nf][1]);
                *(__half2*)(Qh + base + 1024) = __floats2half2_rn(acc[mf][nf][2], acc[mf][nf][3]);
            }
        }
    }
}

// ---------------- sparse K/V projection (fp16 mma + ldmatrix) ----------------
#define KVSTAGE_B 16384
#define KVSTAGE_H 8192
#define KV_SMEM (4 * KVSTAGE_B + 128 * 4)

__global__ __launch_bounds__(256, 1) void sparse_kv_mma_kernel(
    const int* __restrict__ anchors)
{
    extern __shared__ __half shh[];
    int* tok = (int*)(shh + 4 * KVSTAGE_H);

    int tid = threadIdx.x;
    int bh = blockIdx.x;
    int h = bh & 15, b = bh >> 4;
    const __half* Bb = (blockIdx.y ? g_wvt : g_wkt) + (size_t)h * 64 * 4096;
    float* out = (blockIdx.y ? g_vsp : g_ksp) + (size_t)bh * NKEYS * HDIM;

    if (tid < 128) {
        int ti = tid >> 4;
        int tile = (ti == 7) ? 255 : anchors[(bh << 3) + ti];
        tok[tid] = tile * 16 + (tid & 15);
    }
    __syncthreads();

    int wid = tid >> 5, lane = tid & 31;
    int wm = wid >> 2, wn = wid & 3;
    int gq = lane >> 2, kc = lane & 3;

    uint32_t sb = smem_u32(shh);

    int laneAr = wm * 64 + (lane & 7) + (((lane >> 3) & 1) << 3);
    int cA = lane >> 4;
    int swA = (laneAr >> 1) & 3;
    uint32_t aAddr0 = sb + (uint32_t)laneAr * 64 + (uint32_t)((cA     ^ swA) << 4);
    uint32_t aAddr1 = sb + (uint32_t)laneAr * 64 + (uint32_t)(((2|cA) ^ swA) << 4);
    int laneBr = wn * 32 + ((lane >> 4) << 3) + (lane & 7);
    int cB = (lane >> 3) & 1;
    int swB = (laneBr >> 1) & 3;
    uint32_t bAddr0 = sb + 8192 + (uint32_t)laneBr * 64 + (uint32_t)((cB     ^ swB) << 4);
    uint32_t bAddr1 = sb + 8192 + (uint32_t)laneBr * 64 + (uint32_t)(((2|cB) ^ swB) << 4);

    float acc[4][4][4];
#pragma unroll
    for (int i = 0; i < 4; i++)
#pragma unroll
        for (int j = 0; j < 4; j++)
#pragma unroll
            for (int r = 0; r < 4; r++) acc[i][j][r] = 0.f;

#pragma unroll
    for (int s = 0; s < 3; s++) {
        uint32_t so = sb + s * KVSTAGE_B;
#pragma unroll
        for (int i = 0; i < 2; i++) {
            int cidx = i * 256 + tid;
            int rs = cidx >> 2, c = cidx & 3;
            int grow = b * SS + tok[rs];
            const __half* srcA = g_xh + (size_t)((grow >> 7) * 64 + s) * 4096
                               + (grow & 127) * 32 + ((c ^ ((grow >> 1) & 3)) * 8);
            CP_ASYNC16(so + (uint32_t)(rs * 64 + (c ^ ((rs >> 1) & 3)) * 16), srcA);
            const __half* srcB = Bb + (size_t)s * 4096 + rs * 32 + ((c ^ ((rs >> 1) & 3)) * 8);
            CP_ASYNC16(so + 8192 + (uint32_t)(rs * 64 + (c ^ ((rs >> 1) & 3)) * 16), srcB);
        }
        CP_COMMIT();
    }

    for (int kt = 0; kt < 64; kt++) {
        CP_WAIT(2);
        __syncthreads();
        if (kt + 3 < 64) {
            int sl = kt + 3;
            uint32_t so = sb + (uint32_t)(sl & 3) * KVSTAGE_B;
#pragma unroll
            for (int i = 0; i < 2; i++) {
                int cidx = i * 256 + tid;
                int rs = cidx >> 2, c = cidx & 3;
                int grow = b * SS + tok[rs];
                const __half* srcA = g_xh + (size_t)((grow >> 7) * 64 + sl) * 4096
                                   + (grow & 127) * 32 + ((c ^ ((grow >> 1) & 3)) * 8);
                CP_ASYNC16(so + (uint32_t)(rs * 64 + (c ^ ((rs >> 1) & 3)) * 16), srcA);
                const __half* srcB = Bb + (size_t)sl * 4096 + rs * 32 + ((c ^ ((rs >> 1) & 3)) * 8);
                CP_ASYNC16(so + 8192 + (uint32_t)(rs * 64 + (c ^ ((rs >> 1) & 3)) * 16), srcB);
            }
        }
        CP_COMMIT();

        uint32_t so = (uint32_t)(kt & 3) * KVSTAGE_B;
#pragma unroll
        for (int t = 0; t < 2; t++) {
            uint32_t aA = (t ? aAddr1 : aAddr0) + so;
            uint32_t bA = (t ? bAddr1 : bAddr0) + so;
            uint32_t af[4][4], bf[4][2];
#pragma unroll
            for (int mf = 0; mf < 4; mf++)
                LDMX4(af[mf][0], af[mf][1], af[mf][2], af[mf][3], aA + mf * 1024);
#pragma unroll
            for (int nfp = 0; nfp < 2; nfp++)
                LDMX4(bf[2 * nfp][0], bf[2 * nfp][1], bf[2 * nfp + 1][0], bf[2 * nfp + 1][1],
                      bA + nfp * 1024);
#pragma unroll
            for (int mf = 0; mf < 4; mf++)
#pragma unroll
                for (int nf = 0; nf < 4; nf++)
                    mma_f16_16x8x16(acc[mf][nf][0], acc[mf][nf][1],
                                    acc[mf][nf][2], acc[mf][nf][3],
                                    af[mf][0], af[mf][1], af[mf][2], af[mf][3],
                                    bf[nf][0], bf[nf][1]);
        }
    }

#pragma unroll
    for (int mf = 0; mf < 4; mf++) {
        int r0 = wm * 64 + mf * 16 + gq;
#pragma unroll
        for (int nf = 0; nf < 4; nf++) {
            int col = wn * 32 + nf * 8 + kc * 2;
            *(float2*)&out[(size_t)r0 * 128 + col]       = make_float2(acc[mf][nf][0], acc[mf][nf][1]);
            *(float2*)&out[(size_t)(r0 + 8) * 128 + col] = make_float2(acc[mf][nf][2], acc[mf][nf][3]);
        }
    }
}

// ---------------- attention: fp16 mma + ldmatrix, register softmax ----------------
#define ATTN_TOK_OFF (3 * 32768)
#define ATTN_SMEM (ATTN_TOK_OFF + 512 + 16)

__global__ __launch_bounds__(256) void attn_mma_kernel(
    const int* __restrict__ anchors, __half* __restrict__ attout, int bhbase)
{
    extern __shared__ char smraw[];
    __half* Kh  = (__half*)smraw;
    __half* Vth = Kh + 16384;
    __half* QPh = Vth + 16384;
    int*    tok = (int*)(smraw + ATTN_TOK_OFF);
    uint32_t sbb = smem_u32(smraw);
    uint32_t mb = sbb + ATTN_TOK_OFF + 512;

    int tid = threadIdx.x;
    int bh = bhbase + blockIdx.y;
    int b = bh >> 4, h = bh & 15;
    int q0 = blockIdx.x * 128;
    int wid = tid >> 5, lane = tid & 31;
    int gq = lane >> 2, kc = lane & 3;

    if (tid == 0) MBARRIER_INIT(mb, 1);
    if (tid < 128) {
        int ti = tid >> 4;
        int tile = (ti == 7) ? 255 : anchors[(bh << 3) + ti];
        tok[tid] = tile * 16 + (tid & 15);
    }
    __syncthreads();

    if (tid == 0) {
        const __half* qsrc = g_qh + ((size_t)((b * 32 + (q0 >> 7)) * 16 + h) * 16384);
        MBARRIER_EXPECT_TX(mb, 32768);
        CP_BULK(sbb + 2 * 32768, qsrc, 32768, mb);
    }

    const float* kg = g_ksp + (size_t)bh * 16384;
    for (int idx = tid; idx < 4096; idx += 256) {
        int key = idx >> 5, d4 = idx & 31;
        float4 v = *(const float4*)(kg + key * 128 + d4 * 4);
        int p0 = (d4 * 2) ^ ((key & 7) << 2);
        *(__half2*)(Kh + key * 128 + p0 * 2)       = __floats2half2_rn(v.x, v.y);
        *(__half2*)(Kh + key * 128 + (p0 + 1) * 2) = __floats2half2_rn(v.z, v.w);
    }
    const float* vg = g_vsp + (size_t)bh * 16384;
    for (int idx = tid; idx < 16384; idx += 256) {
        int key = idx >> 7, d = idx & 127;
        int phys = (key >> 1) ^ ((d & 7) << 2);
        Vth[d * 128 + phys * 2 + (key & 1)] = __float2half_rn(vg[idx]);
    }
    __syncthreads();
    MBARRIER_WAIT_PARITY(mb, 0);

    int laneAr = wid * 16 + (lane & 7) + (((lane >> 3) & 1) << 3);
    int cA = lane >> 4;
    int laneBr = ((lane >> 4) << 3) + (lane & 7);
    int cB = (lane >> 3) & 1;
    uint32_t qBase = sbb + 2 * 32768 + (uint32_t)laneAr * 256;
    uint32_t kBase = sbb + (uint32_t)laneBr * 256;
    uint32_t vBase = sbb + 32768 + (uint32_t)laneBr * 256;
    int swAa = laneAr & 7, swBa = laneBr & 7;

    int r = wid * 16 + gq;

    // ---- S = Q @ K^T ----
    float acc[16][4];
#pragma unroll
    for (int nf = 0; nf < 16; nf++)
#pragma unroll
        for (int z = 0; z < 4; z++) acc[nf][z] = 0.f;
#pragma unroll
    for (int t = 0; t < 8; t++) {
        uint32_t af[4], bf[16][2];
        LDMX4(af[0], af[1], af[2], af[3], qBase + (uint32_t)(((2 * t + cA) ^ swAa) << 4));
#pragma unroll
        for (int nfp = 0; nfp < 8; nfp++)
            LDMX4(bf[2 * nfp][0], bf[2 * nfp][1], bf[2 * nfp + 1][0], bf[2 * nfp + 1][1],
                  kBase + nfp * 4096 + (uint32_t)(((2 * t + cB) ^ swBa) << 4));
#pragma unroll
        for (int nf = 0; nf < 16; nf++)
            mma_f16_16x8x16(acc[nf][0], acc[nf][1], acc[nf][2], acc[nf][3],
                            af[0], af[1], af[2], af[3], bf[nf][0], bf[nf][1]);
    }

    // ---- register softmax (rows r, r+8; quad lanes gq*4+kc) ----
    {
        const float scale = 0.0883883476483184f;
        int qpos0 = q0 + r, qpos1 = qpos0 + 8;
        float mx0 = -3.0e38f, mx1 = -3.0e38f;
#pragma unroll
        for (int nf = 0; nf < 16; nf++)
#pragma unroll
            for (int j = 0; j < 2; j++) {
                int tcol = tok[nf * 8 + kc * 2 + j];
                float v0 = acc[nf][j] * scale;
                float v1 = acc[nf][2 + j] * scale;
                if (tcol > qpos0) v0 = -1e10f;
                if (tcol > qpos1) v1 = -1e10f;
                acc[nf][j] = v0; acc[nf][2 + j] = v1;
                mx0 = fmaxf(mx0, v0); mx1 = fmaxf(mx1, v1);
            }
        mx0 = fmaxf(mx0, __shfl_xor_sync(0xffffffffu, mx0, 1));
        mx0 = fmaxf(mx0, __shfl_xor_sync(0xffffffffu, mx0, 2));
        mx1 = fmaxf(mx1, __shfl_xor_sync(0xffffffffu, mx1, 1));
        mx1 = fmaxf(mx1, __shfl_xor_sync(0xffffffffu, mx1, 2));
        float s0 = 0.f, s1 = 0.f;
#pragma unroll
        for (int nf = 0; nf < 16; nf++)
#pragma unroll
            for (int j = 0; j < 2; j++) {
                float e0 = __expf(acc[nf][j] - mx0);
                float e1 = __expf(acc[nf][2 + j] - mx1);
                acc[nf][j] = e0; acc[nf][2 + j] = e1;
                s0 += e0; s1 += e1;
            }
        s0 += __shfl_xor_sync(0xffffffffu, s0, 1);
        s0 += __shfl_xor_sync(0xffffffffu, s0, 2);
        s1 += __shfl_xor_sync(0xffffffffu, s1, 1);
        s1 += __shfl_xor_sync(0xffffffffu, s1, 2);
        float inv0 = 1.f / s0, inv1 = 1.f / s1;
        int sw = (r & 7) << 2;
#pragma unroll
        for (int nf = 0; nf < 16; nf++) {
            int g = nf * 4 + kc;
            int phys = g ^ sw;
            *(__half2*)(QPh + r * 128 + phys * 2) =
                __floats2half2_rn(acc[nf][0] * inv0, acc[nf][1] * inv0);
            *(__half2*)(QPh + (r + 8) * 128 + phys * 2) =
                __floats2half2_rn(acc[nf][2] * inv1, acc[nf][3] * inv1);
        }
        __syncwarp();
    }

    // ---- O = P @ V ----
    float acc2[16][4];
#pragma unroll
    for (int nf = 0; nf < 16; nf++)
#pragma unroll
        for (int z = 0; z < 4; z++) acc2[nf][z] = 0.f;
#pragma unroll
    for (int t = 0; t < 8; t++) {
        uint32_t af[4], bf[16][2];
        LDMX4(af[0], af[1], af[2], af[3], qBase + (uint32_t)(((2 * t + cA) ^ swAa) << 4));
#pragma unroll
        for (int nfp = 0; nfp < 8; nfp++)
            LDMX4(bf[2 * nfp][0], bf[2 * nfp][1], bf[2 * nfp + 1][0], bf[2 * nfp + 1][1],
                  vBase + nfp * 4096 + (uint32_t)(((2 * t + cB) ^ swBa) << 4));
#pragma unroll
        for (int nf = 0; nf < 16; nf++)
            mma_f16_16x8x16(acc2[nf][0], acc2[nf][1], acc2[nf][2], acc2[nf][3],
                            af[0], af[1], af[2], af[3], bf[nf][0], bf[nf][1]);
    }

    // ---- store O in half TILED layout ----
    {
        int mblk = (b * SS + q0) >> 7;
        __half* abase = attout + (size_t)mblk * 64 * 4096;
        int sw = ((r >> 1) & 3) << 2;
#pragma unroll
        for (int nf = 0; nf < 16; nf++) {
            int col = h * HDIM + nf * 8 + kc * 2;
            int kblk = col >> 5, kcol = col & 31;
            int phys = (kcol >> 1) ^ sw;
            *(__half2*)(abase + (size_t)kblk * 4096 + r * 32 + phys * 2) =
                __floats2half2_rn(acc2[nf][0], acc2[nf][1]);
            *(__half2*)(abase + (size_t)kblk * 4096 + (r + 8) * 32 + phys * 2) =
                __floats2half2_rn(acc2[nf][2], acc2[nf][3]);
        }
    }
}

// ---------------- streams/events ----------------
static cudaStream_t g_s1, g_s2;
static cudaEvent_t g_estart, g_erh, g_ewq, g_ewo, g_ekv, g_e1[4], g_e2[4];
static bool g_streams_ok = [](){
    cudaStreamCreateWithFlags(&g_s1, cudaStreamNonBlocking);
    cudaStreamCreateWithFlags(&g_s2, cudaStreamNonBlocking);
    cudaEventCreateWithFlags(&g_estart, cudaEventDisableTiming);
    cudaEventCreateWithFlags(&g_erh, cudaEventDisableTiming);
    cudaEventCreateWithFlags(&g_ewq, cudaEventDisableTiming);
    cudaEventCreateWithFlags(&g_ewo, cudaEventDisableTiming);
    cudaEventCreateWithFlags(&g_ekv, cudaEventDisableTiming);
    for (int i = 0; i < 4; i++) {
        cudaEventCreateWithFlags(&g_e1[i], cudaEventDisableTiming);
        cudaEventCreateWithFlags(&g_e2[i], cudaEventDisableTiming);
    }
    return true;
}();

// ---------------- launch ----------------
extern "C" void kernel_launch(void* const* d_in, const int* in_sizes, int n_in,
                              void* d_out, int out_size)
{
    const float* x       = (const float*)d_in[0];
    const int*   anchors = (const int*)  d_in[1];
    const float* Wq      = (const float*)d_in[2];
    const float* Wk      = (const float*)d_in[3];
    const float* Wv      = (const float*)d_in[4];
    const float* Wo      = (const float*)d_in[5];
    float* out = (float*)d_out;

    __half *qhp, *attp, *xhp, *wqtp, *wotp, *wktp, *wvtp;
    cudaGetSymbolAddress((void**)&qhp,  g_qh);
    cudaGetSymbolAddress((void**)&attp, g_att);
    cudaGetSymbolAddress((void**)&xhp,  g_xh);
    cudaGetSymbolAddress((void**)&wqtp, g_wqt);
    cudaGetSymbolAddress((void**)&wotp, g_wot);
    cudaGetSymbolAddress((void**)&wktp, g_wkt);
    cudaGetSymbolAddress((void**)&wvtp, g_wvt);

    cudaFuncSetAttribute(attn_mma_kernel, cudaFuncAttributeMaxDynamicSharedMemorySize, ATTN_SMEM);
    cudaFuncSetAttribute(gemm256_kernel, cudaFuncAttributeMaxDynamicSharedMemorySize, GEMM_SMEM);
    cudaFuncSetAttribute(sparse_kv_mma_kernel, cudaFuncAttributeMaxDynamicSharedMemorySize, KV_SMEM);

    const size_t ABLK = (size_t)32 * 64 * 4096;
    const size_t QBLK = (size_t)SS * DD;
    const size_t CBLK = (size_t)SS * DD;

    // FORK: all side streams must originate from the capture (origin) stream.
    cudaEventRecord(g_estart, 0);

    // stream 0: round x
    round_half_kernel<<<(BB * SS * DD / 4) / 256, 256>>>((const float4*)x, xhp);
    cudaEventRecord(g_erh, 0);

    // s2 forks from origin, runs weight transposes concurrently with round_half
    cudaStreamWaitEvent(g_s2, g_estart, 0);
    transpose_half_kernel<<<dim3(16, 64), 256, 0, g_s2>>>(Wq, wqtp);
    cudaEventRecord(g_ewq, g_s2);
    transpose_half_kernel<<<dim3(16, 64), 256, 0, g_s2>>>(Wk, wktp);
    transpose_half_kernel<<<dim3(16, 64), 256, 0, g_s2>>>(Wv, wvtp);
    transpose_half_kernel<<<dim3(16, 64), 256, 0, g_s2>>>(Wo, wotp);
    cudaEventRecord(g_ewo, g_s2);
    cudaStreamWaitEvent(g_s2, g_erh, 0);
    sparse_kv_mma_kernel<<<dim3(64, 2), 256, KV_SMEM, g_s2>>>(anchors);
    cudaEventRecord(g_ekv, g_s2);

    // s1: GEMM1 per batch (forks via events recorded on origin/s2)
    cudaStreamWaitEvent(g_s1, g_erh, 0);
    cudaStreamWaitEvent(g_s1, g_ewq, 0);
    for (int b = 0; b < 4; b++) {
        gemm256_kernel<<<dim3(8, 32), 512, GEMM_SMEM, g_s1>>>(
            xhp + b * ABLK, wqtp, nullptr, qhp + b * QBLK, 1);
        cudaEventRecord(g_e1[b], g_s1);
    }
    // s2: attention per batch (after kv on same stream)
    for (int b = 0; b < 4; b++) {
        cudaStreamWaitEvent(g_s2, g_e1[b], 0);
        attn_mma_kernel<<<dim3(32, 16), 256, ATTN_SMEM, g_s2>>>(anchors, attp, b * 16);
        cudaEventRecord(g_e2[b], g_s2);
    }
    // stream 0: GEMM2 per batch (joins all forks)
    cudaStreamWaitEvent(0, g_ewo, 0);
    for (int b = 0; b < 4; b++) {
        cudaStreamWaitEvent(0, g_e2[b], 0);
        gemm256_kernel<<<dim3(8, 32), 512, GEMM_SMEM>>>(
            attp + b * ABLK, wotp, out + b * CBLK, nullptr, 0);
    }
}

// round 14
// speedup vs baseline: 8.5050x; 1.0044x over previous
#include <cuda_runtime.h>
#include <cuda_fp16.h>
#include <cstdint>
#include <math.h>

#define BB 4
#define SS 4096
#define DD 2048
#define HH 16
#define HDIM 128
#define NKEYS 128

// ---------------- scratch ----------------
__device__ __half g_qh [(size_t)BB * SS * DD];   // Q, attn-smem image
__device__ __half g_att[(size_t)BB * SS * DD];   // half TILED (GEMM2 A)
__device__ __half g_xh [(size_t)BB * SS * DD];   // half TILED
__device__ __half g_wqt[2048 * 2048];            // half TILED [n][k]
__device__ __half g_wot[2048 * 2048];
__device__ __half g_wkt[2048 * 2048];
__device__ __half g_wvt[2048 * 2048];
__device__ float  g_ksp[64 * NKEYS * HDIM];
__device__ float  g_vsp[64 * NKEYS * HDIM];

// ---------------- helpers ----------------
__device__ __forceinline__ uint32_t smem_u32(const void* p) {
    uint32_t a;
    asm("{ .reg .u64 t; cvta.to.shared.u64 t, %1; cvt.u32.u64 %0, t; }" : "=r"(a) : "l"(p));
    return a;
}
#define CP_ASYNC16(dst, src) \
    asm volatile("cp.async.cg.shared.global [%0], [%1], 16;" :: "r"(dst), "l"(src) : "memory")
#define CP_COMMIT() asm volatile("cp.async.commit_group;" ::: "memory")
#define CP_WAIT(n)  asm volatile("cp.async.wait_group %0;" :: "n"(n) : "memory")
#define CP_BULK(dst, src, bytes, mbar) \
    asm volatile("cp.async.bulk.shared::cluster.global.mbarrier::complete_tx::bytes [%0], [%1], %2, [%3];" \
        :: "r"(dst), "l"(src), "r"(bytes), "r"(mbar) : "memory")
#define MBARRIER_INIT(addr, cnt) \
    asm volatile("mbarrier.init.shared.b64 [%0], %1;" :: "r"(addr), "r"(cnt) : "memory")
#define MBARRIER_EXPECT_TX(addr, tx) \
    asm volatile("mbarrier.arrive.expect_tx.shared.b64 _, [%0], %1;" :: "r"(addr), "r"(tx) : "memory")
#define MBARRIER_WAIT_PARITY(addr, ph) do { \
    uint32_t _m = (addr), _p = (ph), _d; \
    asm volatile("{\n\t.reg .pred p;\n\t" \
        "mbarrier.try_wait.parity.acquire.cta.shared::cta.b64 p, [%1], %2;\n\t" \
        "selp.b32 %0, 1, 0, p;\n\t}" : "=r"(_d) : "r"(_m), "r"(_p) : "memory"); \
    if (!_d) { \
        asm volatile("{\n\t.reg .pred P1;\n\tWL_%=:\n\t" \
            "mbarrier.try_wait.parity.acquire.cta.shared::cta.b64 P1, [%0], %1, 0x989680;\n\t" \
            "@P1 bra.uni WD_%=;\n\tbra.uni WL_%=;\n\tWD_%=:\n\t}" \
            :: "r"(_m), "r"(_p) : "memory"); \
    } } while (0)
#define LDMX4(r0, r1, r2, r3, addr) \
    asm volatile("ldmatrix.sync.aligned.m8n8.x4.shared.b16 {%0,%1,%2,%3}, [%4];" \
        : "=r"(r0), "=r"(r1), "=r"(r2), "=r"(r3) : "r"(addr))

__device__ __forceinline__ void mma_f16_16x8x16(
    float& c0, float& c1, float& c2, float& c3,
    uint32_t a0, uint32_t a1, uint32_t a2, uint32_t a3,
    uint32_t b0, uint32_t b1)
{
    asm volatile(
        "mma.sync.aligned.m16n8k16.row.col.f32.f16.f16.f32 "
        "{%0,%1,%2,%3}, {%4,%5,%6,%7}, {%8,%9}, {%0,%1,%2,%3};"
        : "+f"(c0), "+f"(c1), "+f"(c2), "+f"(c3)
        : "r"(a0), "r"(a1), "r"(a2), "r"(a3), "r"(b0), "r"(b1));
}

// ---------------- prep: x -> half TILED (one batch per launch) ----------------
__global__ void round_half_kernel(const float4* __restrict__ in, __half* __restrict__ out) {
    int i = blockIdx.x * 256 + threadIdx.x;
    float4 v = in[i];
    int m = i >> 9, c4 = i & 511;
    int kblk = c4 >> 3;
    int g0 = (c4 & 7) * 2;
    int r = m & 127, mblk = m >> 7;
    int phys = g0 ^ (((r >> 1) & 3) << 2);
    __half2* dst = (__half2*)(out + ((size_t)(mblk * 64 + kblk) * 4096 + r * 32 + phys * 2));
    dst[0] = __floats2half2_rn(v.x, v.y);
    dst[1] = __floats2half2_rn(v.z, v.w);
}

// ---------------- prep: W -> half TILED [n][k], vectorized 16B stores ----------------
__global__ void transpose_half_kernel(const float* __restrict__ W, __half* __restrict__ WT) {
    __shared__ float t[32][132];
    int n0 = blockIdx.x * 128, kblk = blockIdx.y, k0 = kblk * 32;
    int tid = threadIdx.x;
#pragma unroll
    for (int i = 0; i < 16; i++) {
        int lin = i * 256 + tid;
        int k = lin >> 7, n = lin & 127;
        t[k][n] = W[(size_t)(k0 + k) * 2048 + n0 + n];
    }
    __syncthreads();
    int r = tid & 127;
    int cbase = (tid >> 7) * 2;
    int sw = (r >> 1) & 3;
    __half* obase = WT + (size_t)((n0 >> 7) * 64 + kblk) * 4096 + r * 32;
#pragma unroll
    for (int cc = 0; cc < 2; cc++) {
        int c = cbase + cc;
        __half h[8];
#pragma unroll
        for (int i = 0; i < 8; i++) h[i] = __float2half_rn(t[c * 8 + i][r]);
        *(uint4*)(obase + ((c ^ sw) * 8)) = *(uint4*)h;
    }
}

// ---------------- fp16 GEMM (cp.async.bulk + ldmatrix); mode1 epilogue -> g_qh ----------------
#define GSTAGE_B 24576
#define GSTAGE_H 12288
#define GEMM_SMEM (4 * GSTAGE_B + 64)

__global__ __launch_bounds__(512, 1) void gemm256_kernel(
    const __half* __restrict__ A, const __half* __restrict__ BW,
    float* __restrict__ C, __half* __restrict__ Qh, int mode)
{
    extern __shared__ __half shh[];
    uint32_t sb = smem_u32(shh);
    uint32_t mb = sb + 4 * GSTAGE_B;

    int tid = threadIdx.x;
    int wid = tid >> 5, lane = tid & 31;
    int wm = wid >> 2, wn = wid & 3;
    int gq = lane >> 2, kc = lane & 3;
    int n0 = blockIdx.x * 256, m0 = blockIdx.y * 128;

    if (tid == 0) {
#pragma unroll
        for (int s = 0; s < 4; s++) MBARRIER_INIT(mb + 8 * s, 1);
    }
    __syncthreads();

    const __half* Ab = A  + (size_t)(m0 >> 7) * 64 * 4096;
    const __half* B0 = BW + (size_t)(n0 >> 7) * 64 * 4096;
    const __half* B1 = BW + (size_t)((n0 >> 7) + 1) * 64 * 4096;

    if (tid == 0) {
#pragma unroll
        for (int s = 0; s < 3; s++) {
            MBARRIER_EXPECT_TX(mb + 8 * s, GSTAGE_B);
            CP_BULK(sb + s * GSTAGE_B,         Ab + (size_t)s * 4096, 8192, mb + 8 * s);
            CP_BULK(sb + s * GSTAGE_B + 8192,  B0 + (size_t)s * 4096, 8192, mb + 8 * s);
            CP_BULK(sb + s * GSTAGE_B + 16384, B1 + (size_t)s * 4096, 8192, mb + 8 * s);
        }
    }

    int laneAr = wm * 32 + (lane & 7) + (((lane >> 3) & 1) << 3);
    int cA = lane >> 4;
    int swA = (laneAr >> 1) & 3;
    uint32_t aAddr0 = sb + (uint32_t)laneAr * 64 + (uint32_t)((cA     ^ swA) << 4);
    uint32_t aAddr1 = sb + (uint32_t)laneAr * 64 + (uint32_t)(((2|cA) ^ swA) << 4);
    int laneBr = wn * 64 + ((lane >> 4) << 3) + (lane & 7);
    int cB = (lane >> 3) & 1;
    int swB = (laneBr >> 1) & 3;
    uint32_t bAddr0 = sb + 8192 + (uint32_t)laneBr * 64 + (uint32_t)((cB     ^ swB) << 4);
    uint32_t bAddr1 = sb + 8192 + (uint32_t)laneBr * 64 + (uint32_t)(((2|cB) ^ swB) << 4);

    float acc[2][8][4];
#pragma unroll
    for (int i = 0; i < 2; i++)
#pragma unroll
        for (int j = 0; j < 8; j++)
#pragma unroll
            for (int r = 0; r < 4; r++) acc[i][j][r] = 0.f;

    for (int kt = 0; kt < 64; kt++) {
        int s = kt & 3;
        MBARRIER_WAIT_PARITY(mb + 8 * s, (kt >> 2) & 1);
        uint32_t so = (uint32_t)s * GSTAGE_B;
#pragma unroll
        for (int t = 0; t < 2; t++) {
            uint32_t aA = (t ? aAddr1 : aAddr0) + so;
            uint32_t bA = (t ? bAddr1 : bAddr0) + so;
            uint32_t af[2][4], bf[8][2];
            LDMX4(af[0][0], af[0][1], af[0][2], af[0][3], aA);
            LDMX4(af[1][0], af[1][1], af[1][2], af[1][3], aA + 1024);
#pragma unroll
            for (int nfp = 0; nfp < 4; nfp++)
                LDMX4(bf[2 * nfp][0], bf[2 * nfp][1], bf[2 * nfp + 1][0], bf[2 * nfp + 1][1],
                      bA + nfp * 1024);
#pragma unroll
            for (int mf = 0; mf < 2; mf++)
#pragma unroll
                for (int nf = 0; nf < 8; nf++)
                    mma_f16_16x8x16(acc[mf][nf][0], acc[mf][nf][1],
                                    acc[mf][nf][2], acc[mf][nf][3],
                                    af[mf][0], af[mf][1], af[mf][2], af[mf][3],
                                    bf[nf][0], bf[nf][1]);
        }
        __syncthreads();
        if (tid == 0 && kt + 3 < 64) {
            int s2 = (kt + 3) & 3;
            MBARRIER_EXPECT_TX(mb + 8 * s2, GSTAGE_B);
            CP_BULK(sb + s2 * GSTAGE_B,         Ab + (size_t)(kt + 3) * 4096, 8192, mb + 8 * s2);
            CP_BULK(sb + s2 * GSTAGE_B + 8192,  B0 + (size_t)(kt + 3) * 4096, 8192, mb + 8 * s2);
            CP_BULK(sb + s2 * GSTAGE_B + 16384, B1 + (size_t)(kt + 3) * 4096, 8192, mb + 8 * s2);
        }
    }

    if (mode == 0) {
#pragma unroll
        for (int mf = 0; mf < 2; mf++) {
            int r0 = m0 + wm * 32 + mf * 16 + gq;
#pragma unroll
            for (int nf = 0; nf < 8; nf++) {
                int col = n0 + wn * 64 + nf * 8 + kc * 2;
                *(float2*)&C[(size_t)r0 * 2048 + col]       = make_float2(acc[mf][nf][0], acc[mf][nf][1]);
                *(float2*)&C[(size_t)(r0 + 8) * 2048 + col] = make_float2(acc[mf][nf][2], acc[mf][nf][3]);
            }
        }
    } else {
#pragma unroll
        for (int mf = 0; mf < 2; mf++) {
            int r0 = m0 + wm * 32 + mf * 16 + gq;
            int q = r0 & 127, mblk = r0 >> 7;
            int sw = (q & 7) << 2;
#pragma unroll
            for (int nf = 0; nf < 8; nf++) {
                int col = n0 + wn * 64 + nf * 8 + kc * 2;
                int head = col >> 7, d = col & 127;
                int phys = (d >> 1) ^ sw;
                size_t base = ((size_t)(mblk * 16 + head) * 128 + q) * 128 + phys * 2;
                *(__half2*)(Qh + base)        = __floats2half2_rn(acc[mf][nf][0], acc[mf][nf][1]);
                *(__half2*)(Qh + base + 1024) = __floats2half2_rn(acc[mf][nf][2], acc[mf][nf][3]);
            }
        }
    }
}

// ---------------- sparse K/V projection (fp16 mma + ldmatrix) ----------------
#define KVSTAGE_B 16384
#define KVSTAGE_H 8192
#define KV_SMEM (4 * KVSTAGE_B + 128 * 4)

__global__ __launch_bounds__(256, 1) void sparse_kv_mma_kernel(
    const int* __restrict__ anchors)
{
    extern __shared__ __half shh[];
    int* tok = (int*)(shh + 4 * KVSTAGE_H);

    int tid = threadIdx.x;
    int bh = blockIdx.x;
    int h = bh & 15, b = bh >> 4;
    const __half* Bb = (blockIdx.y ? g_wvt : g_wkt) + (size_t)h * 64 * 4096;
    float* out = (blockIdx.y ? g_vsp : g_ksp) + (size_t)bh * NKEYS * HDIM;

    if (tid < 128) {
        int ti = tid >> 4;
        int tile = (ti == 7) ? 255 : anchors[(bh << 3) + ti];
        tok[tid] = tile * 16 + (tid & 15);
    }
    __syncthreads();

    int wid = tid >> 5, lane = tid & 31;
    int wm = wid >> 2, wn = wid & 3;
    int gq = lane >> 2, kc = lane & 3;

    uint32_t sb = smem_u32(shh);

    int laneAr = wm * 64 + (lane & 7) + (((lane >> 3) & 1) << 3);
    int cA = lane >> 4;
    int swA = (laneAr >> 1) & 3;
    uint32_t aAddr0 = sb + (uint32_t)laneAr * 64 + (uint32_t)((cA     ^ swA) << 4);
    uint32_t aAddr1 = sb + (uint32_t)laneAr * 64 + (uint32_t)(((2|cA) ^ swA) << 4);
    int laneBr = wn * 32 + ((lane >> 4) << 3) + (lane & 7);
    int cB = (lane >> 3) & 1;
    int swB = (laneBr >> 1) & 3;
    uint32_t bAddr0 = sb + 8192 + (uint32_t)laneBr * 64 + (uint32_t)((cB     ^ swB) << 4);
    uint32_t bAddr1 = sb + 8192 + (uint32_t)laneBr * 64 + (uint32_t)(((2|cB) ^ swB) << 4);

    float acc[4][4][4];
#pragma unroll
    for (int i = 0; i < 4; i++)
#pragma unroll
        for (int j = 0; j < 4; j++)
#pragma unroll
            for (int r = 0; r < 4; r++) acc[i][j][r] = 0.f;

#pragma unroll
    for (int s = 0; s < 3; s++) {
        uint32_t so = sb + s * KVSTAGE_B;
#pragma unroll
        for (int i = 0; i < 2; i++) {
            int cidx = i * 256 + tid;
            int rs = cidx >> 2, c = cidx & 3;
            int grow = b * SS + tok[rs];
            const __half* srcA = g_xh + (size_t)((grow >> 7) * 64 + s) * 4096
                               + (grow & 127) * 32 + ((c ^ ((grow >> 1) & 3)) * 8);
            CP_ASYNC16(so + (uint32_t)(rs * 64 + (c ^ ((rs >> 1) & 3)) * 16), srcA);
            const __half* srcB = Bb + (size_t)s * 4096 + rs * 32 + ((c ^ ((rs >> 1) & 3)) * 8);
            CP_ASYNC16(so + 8192 + (uint32_t)(rs * 64 + (c ^ ((rs >> 1) & 3)) * 16), srcB);
        }
        CP_COMMIT();
    }

    for (int kt = 0; kt < 64; kt++) {
        CP_WAIT(2);
        __syncthreads();
        if (kt + 3 < 64) {
            int sl = kt + 3;
            uint32_t so = sb + (uint32_t)(sl & 3) * KVSTAGE_B;
#pragma unroll
            for (int i = 0; i < 2; i++) {
                int cidx = i * 256 + tid;
                int rs = cidx >> 2, c = cidx & 3;
                int grow = b * SS + tok[rs];
                const __half* srcA = g_xh + (size_t)((grow >> 7) * 64 + sl) * 4096
                                   + (grow & 127) * 32 + ((c ^ ((grow >> 1) & 3)) * 8);
                CP_ASYNC16(so + (uint32_t)(rs * 64 + (c ^ ((rs >> 1) & 3)) * 16), srcA);
                const __half* srcB = Bb + (size_t)sl * 4096 + rs * 32 + ((c ^ ((rs >> 1) & 3)) * 8);
                CP_ASYNC16(so + 8192 + (uint32_t)(rs * 64 + (c ^ ((rs >> 1) & 3)) * 16), srcB);
            }
        }
        CP_COMMIT();

        uint32_t so = (uint32_t)(kt & 3) * KVSTAGE_B;
#pragma unroll
        for (int t = 0; t < 2; t++) {
            uint32_t aA = (t ? aAddr1 : aAddr0) + so;
            uint32_t bA = (t ? bAddr1 : bAddr0) + so;
            uint32_t af[4][4], bf[4][2];
#pragma unroll
            for (int mf = 0; mf < 4; mf++)
                LDMX4(af[mf][0], af[mf][1], af[mf][2], af[mf][3], aA + mf * 1024);
#pragma unroll
            for (int nfp = 0; nfp < 2; nfp++)
                LDMX4(bf[2 * nfp][0], bf[2 * nfp][1], bf[2 * nfp + 1][0], bf[2 * nfp + 1][1],
                      bA + nfp * 1024);
#pragma unroll
            for (int mf = 0; mf < 4; mf++)
#pragma unroll
                for (int nf = 0; nf < 4; nf++)
                    mma_f16_16x8x16(acc[mf][nf][0], acc[mf][nf][1],
                                    acc[mf][nf][2], acc[mf][nf][3],
                                    af[mf][0], af[mf][1], af[mf][2], af[mf][3],
                                    bf[nf][0], bf[nf][1]);
        }
    }

#pragma unroll
    for (int mf = 0; mf < 4; mf++) {
        int r0 = wm * 64 + mf * 16 + gq;
#pragma unroll
        for (int nf = 0; nf < 4; nf++) {
            int col = wn * 32 + nf * 8 + kc * 2;
            *(float2*)&out[(size_t)r0 * 128 + col]       = make_float2(acc[mf][nf][0], acc[mf][nf][1]);
            *(float2*)&out[(size_t)(r0 + 8) * 128 + col] = make_float2(acc[mf][nf][2], acc[mf][nf][3]);
        }
    }
}

// ---------------- attention: fp16 mma + ldmatrix, register softmax ----------------
#define ATTN_TOK_OFF (3 * 32768)
#define ATTN_SMEM (ATTN_TOK_OFF + 512 + 16)

__global__ __launch_bounds__(256) void attn_mma_kernel(
    const int* __restrict__ anchors, __half* __restrict__ attout, int bhbase)
{
    extern __shared__ char smraw[];
    __half* Kh  = (__half*)smraw;
    __half* Vth = Kh + 16384;
    __half* QPh = Vth + 16384;
    int*    tok = (int*)(smraw + ATTN_TOK_OFF);
    uint32_t sbb = smem_u32(smraw);
    uint32_t mb = sbb + ATTN_TOK_OFF + 512;

    int tid = threadIdx.x;
    int bh = bhbase + blockIdx.y;
    int b = bh >> 4, h = bh & 15;
    int q0 = blockIdx.x * 128;
    int wid = tid >> 5, lane = tid & 31;
    int gq = lane >> 2, kc = lane & 3;

    if (tid == 0) MBARRIER_INIT(mb, 1);
    if (tid < 128) {
        int ti = tid >> 4;
        int tile = (ti == 7) ? 255 : anchors[(bh << 3) + ti];
        tok[tid] = tile * 16 + (tid & 15);
    }
    __syncthreads();

    if (tid == 0) {
        const __half* qsrc = g_qh + ((size_t)((b * 32 + (q0 >> 7)) * 16 + h) * 16384);
        MBARRIER_EXPECT_TX(mb, 32768);
        CP_BULK(sbb + 2 * 32768, qsrc, 32768, mb);
    }

    const float* kg = g_ksp + (size_t)bh * 16384;
    for (int idx = tid; idx < 4096; idx += 256) {
        int key = idx >> 5, d4 = idx & 31;
        float4 v = *(const float4*)(kg + key * 128 + d4 * 4);
        int p0 = (d4 * 2) ^ ((key & 7) << 2);
        *(__half2*)(Kh + key * 128 + p0 * 2)       = __floats2half2_rn(v.x, v.y);
        *(__half2*)(Kh + key * 128 + (p0 + 1) * 2) = __floats2half2_rn(v.z, v.w);
    }
    const float* vg = g_vsp + (size_t)bh * 16384;
    for (int idx = tid; idx < 16384; idx += 256) {
        int key = idx >> 7, d = idx & 127;
        int phys = (key >> 1) ^ ((d & 7) << 2);
        Vth[d * 128 + phys * 2 + (key & 1)] = __float2half_rn(vg[idx]);
    }
    __syncthreads();
    MBARRIER_WAIT_PARITY(mb, 0);

    int laneAr = wid * 16 + (lane & 7) + (((lane >> 3) & 1) << 3);
    int cA = lane >> 4;
    int laneBr = ((lane >> 4) << 3) + (lane & 7);
    int cB = (lane >> 3) & 1;
    uint32_t qBase = sbb + 2 * 32768 + (uint32_t)laneAr * 256;
    uint32_t kBase = sbb + (uint32_t)laneBr * 256;
    uint32_t vBase = sbb + 32768 + (uint32_t)laneBr * 256;
    int swAa = laneAr & 7, swBa = laneBr & 7;

    int r = wid * 16 + gq;

    float acc[16][4];
#pragma unroll
    for (int nf = 0; nf < 16; nf++)
#pragma unroll
        for (int z = 0; z < 4; z++) acc[nf][z] = 0.f;
#pragma unroll
    for (int t = 0; t < 8; t++) {
        uint32_t af[4], bf[16][2];
        LDMX4(af[0], af[1], af[2], af[3], qBase + (uint32_t)(((2 * t + cA) ^ swAa) << 4));
#pragma unroll
        for (int nfp = 0; nfp < 8; nfp++)
            LDMX4(bf[2 * nfp][0], bf[2 * nfp][1], bf[2 * nfp + 1][0], bf[2 * nfp + 1][1],
                  kBase + nfp * 4096 + (uint32_t)(((2 * t + cB) ^ swBa) << 4));
#pragma unroll
        for (int nf = 0; nf < 16; nf++)
            mma_f16_16x8x16(acc[nf][0], acc[nf][1], acc[nf][2], acc[nf][3],
                            af[0], af[1], af[2], af[3], bf[nf][0], bf[nf][1]);
    }

    {
        const float scale = 0.0883883476483184f;
        int qpos0 = q0 + r, qpos1 = qpos0 + 8;
        float mx0 = -3.0e38f, mx1 = -3.0e38f;
#pragma unroll
        for (int nf = 0; nf < 16; nf++)
#pragma unroll
            for (int j = 0; j < 2; j++) {
                int tcol = tok[nf * 8 + kc * 2 + j];
                float v0 = acc[nf][j] * scale;
                float v1 = acc[nf][2 + j] * scale;
                if (tcol > qpos0) v0 = -1e10f;
                if (tcol > qpos1) v1 = -1e10f;
                acc[nf][j] = v0; acc[nf][2 + j] = v1;
                mx0 = fmaxf(mx0, v0); mx1 = fmaxf(mx1, v1);
            }
        mx0 = fmaxf(mx0, __shfl_xor_sync(0xffffffffu, mx0, 1));
        mx0 = fmaxf(mx0, __shfl_xor_sync(0xffffffffu, mx0, 2));
        mx1 = fmaxf(mx1, __shfl_xor_sync(0xffffffffu, mx1, 1));
        mx1 = fmaxf(mx1, __shfl_xor_sync(0xffffffffu, mx1, 2));
        float s0 = 0.f, s1 = 0.f;
#pragma unroll
        for (int nf = 0; nf < 16; nf++)
#pragma unroll
            for (int j = 0; j < 2; j++) {
                float e0 = __expf(acc[nf][j] - mx0);
                float e1 = __expf(acc[nf][2 + j] - mx1);
                acc[nf][j] = e0; acc[nf][2 + j] = e1;
                s0 += e0; s1 += e1;
            }
        s0 += __shfl_xor_sync(0xffffffffu, s0, 1);
        s0 += __shfl_xor_sync(0xffffffffu, s0, 2);
        s1 += __shfl_xor_sync(0xffffffffu, s1, 1);
        s1 += __shfl_xor_sync(0xffffffffu, s1, 2);
        float inv0 = 1.f / s0, inv1 = 1.f / s1;
        int sw = (r & 7) << 2;
#pragma unroll
        for (int nf = 0; nf < 16; nf++) {
            int g = nf * 4 + kc;
            int phys = g ^ sw;
            *(__half2*)(QPh + r * 128 + phys * 2) =
                __floats2half2_rn(acc[nf][0] * inv0, acc[nf][1] * inv0);
            *(__half2*)(QPh + (r + 8) * 128 + phys * 2) =
                __floats2half2_rn(acc[nf][2] * inv1, acc[nf][3] * inv1);
        }
        __syncwarp();
    }

    float acc2[16][4];
#pragma unroll
    for (int nf = 0; nf < 16; nf++)
#pragma unroll
        for (int z = 0; z < 4; z++) acc2[nf][z] = 0.f;
#pragma unroll
    for (int t = 0; t < 8; t++) {
        uint32_t af[4], bf[16][2];
        LDMX4(af[0], af[1], af[2], af[3], qBase + (uint32_t)(((2 * t + cA) ^ swAa) << 4));
#pragma unroll
        for (int nfp = 0; nfp < 8; nfp++)
            LDMX4(bf[2 * nfp][0], bf[2 * nfp][1], bf[2 * nfp + 1][0], bf[2 * nfp + 1][1],
                  vBase + nfp * 4096 + (uint32_t)(((2 * t + cB) ^ swBa) << 4));
#pragma unroll
        for (int nf = 0; nf < 16; nf++)
            mma_f16_16x8x16(acc2[nf][0], acc2[nf][1], acc2[nf][2], acc2[nf][3],
                            af[0], af[1], af[2], af[3], bf[nf][0], bf[nf][1]);
    }

    {
        int mblk = (b * SS + q0) >> 7;
        __half* abase = attout + (size_t)mblk * 64 * 4096;
        int sw = ((r >> 1) & 3) << 2;
#pragma unroll
        for (int nf = 0; nf < 16; nf++) {
            int col = h * HDIM + nf * 8 + kc * 2;
            int kblk = col >> 5, kcol = col & 31;
            int phys = (kcol >> 1) ^ sw;
            *(__half2*)(abase + (size_t)kblk * 4096 + r * 32 + phys * 2) =
                __floats2half2_rn(acc2[nf][0], acc2[nf][1]);
            *(__half2*)(abase + (size_t)kblk * 4096 + (r + 8) * 32 + phys * 2) =
                __floats2half2_rn(acc2[nf][2], acc2[nf][3]);
        }
    }
}

// ---------------- streams/events ----------------
static cudaStream_t g_s1a, g_s1b, g_s2, g_s3;
static cudaEvent_t g_estart, g_erhb[4], g_ewq, g_ewo, g_ekv, g_e1[4], g_e2[4], g_e3;
static bool g_streams_ok = [](){
    cudaStreamCreateWithFlags(&g_s1a, cudaStreamNonBlocking);
    cudaStreamCreateWithFlags(&g_s1b, cudaStreamNonBlocking);
    cudaStreamCreateWithFlags(&g_s2,  cudaStreamNonBlocking);
    cudaStreamCreateWithFlags(&g_s3,  cudaStreamNonBlocking);
    cudaEventCreateWithFlags(&g_estart, cudaEventDisableTiming);
    cudaEventCreateWithFlags(&g_ewq, cudaEventDisableTiming);
    cudaEventCreateWithFlags(&g_ewo, cudaEventDisableTiming);
    cudaEventCreateWithFlags(&g_ekv, cudaEventDisableTiming);
    cudaEventCreateWithFlags(&g_e3,  cudaEventDisableTiming);
    for (int i = 0; i < 4; i++) {
        cudaEventCreateWithFlags(&g_erhb[i], cudaEventDisableTiming);
        cudaEventCreateWithFlags(&g_e1[i], cudaEventDisableTiming);
        cudaEventCreateWithFlags(&g_e2[i], cudaEventDisableTiming);
    }
    return true;
}();

// ---------------- launch ----------------
extern "C" void kernel_launch(void* const* d_in, const int* in_sizes, int n_in,
                              void* d_out, int out_size)
{
    const float* x       = (const float*)d_in[0];
    const int*   anchors = (const int*)  d_in[1];
    const float* Wq      = (const float*)d_in[2];
    const float* Wk      = (const float*)d_in[3];
    const float* Wv      = (const float*)d_in[4];
    const float* Wo      = (const float*)d_in[5];
    float* out = (float*)d_out;

    __half *qhp, *attp, *xhp, *wqtp, *wotp, *wktp, *wvtp;
    cudaGetSymbolAddress((void**)&qhp,  g_qh);
    cudaGetSymbolAddress((void**)&attp, g_att);
    cudaGetSymbolAddress((void**)&xhp,  g_xh);
    cudaGetSymbolAddress((void**)&wqtp, g_wqt);
    cudaGetSymbolAddress((void**)&wotp, g_wot);
    cudaGetSymbolAddress((void**)&wktp, g_wkt);
    cudaGetSymbolAddress((void**)&wvtp, g_wvt);

    cudaFuncSetAttribute(attn_mma_kernel, cudaFuncAttributeMaxDynamicSharedMemorySize, ATTN_SMEM);
    cudaFuncSetAttribute(gemm256_kernel, cudaFuncAttributeMaxDynamicSharedMemorySize, GEMM_SMEM);
    cudaFuncSetAttribute(sparse_kv_mma_kernel, cudaFuncAttributeMaxDynamicSharedMemorySize, KV_SMEM);

    const size_t ABLK = (size_t)SS * DD;   // half elems per batch (tiled) == fp32 elems per batch
    const size_t X4BLK = (size_t)SS * DD / 4;

    // FORK root
    cudaEventRecord(g_estart, 0);

    // stream 0: per-batch rounding of x (GEMM1_0 can start after batch 0)
    for (int b = 0; b < 4; b++) {
        round_half_kernel<<<(SS * DD / 4) / 256, 256>>>(
            (const float4*)(x + b * 4 * X4BLK), xhp + b * ABLK);
        cudaEventRecord(g_erhb[b], 0);
    }

    // s2 forks from origin: weight transposes, then sparse KV
    cudaStreamWaitEvent(g_s2, g_estart, 0);
    transpose_half_kernel<<<dim3(16, 64), 256, 0, g_s2>>>(Wq, wqtp);
    cudaEventRecord(g_ewq, g_s2);
    transpose_half_kernel<<<dim3(16, 64), 256, 0, g_s2>>>(Wk, wktp);
    transpose_half_kernel<<<dim3(16, 64), 256, 0, g_s2>>>(Wv, wvtp);
    transpose_half_kernel<<<dim3(16, 64), 256, 0, g_s2>>>(Wo, wotp);
    cudaEventRecord(g_ewo, g_s2);
    cudaStreamWaitEvent(g_s2, g_erhb[3], 0);
    sparse_kv_mma_kernel<<<dim3(64, 2), 256, KV_SMEM, g_s2>>>(anchors);
    cudaEventRecord(g_ekv, g_s2);

    // GEMM1 per batch, alternating streams so ragged waves interleave
    for (int b = 0; b < 4; b++) {
        cudaStream_t st = (b & 1) ? g_s1b : g_s1a;
        cudaStreamWaitEvent(st, g_erhb[b], 0);
        cudaStreamWaitEvent(st, g_ewq, 0);
        gemm256_kernel<<<dim3(8, 32), 512, GEMM_SMEM, st>>>(
            xhp + b * ABLK, wqtp, nullptr, qhp + b * ABLK, 1);
        cudaEventRecord(g_e1[b], st);
    }
    // attention per batch on s2 (after kv; sequential, tiny)
    for (int b = 0; b < 4; b++) {
        cudaStreamWaitEvent(g_s2, g_e1[b], 0);
        attn_mma_kernel<<<dim3(32, 16), 256, ATTN_SMEM, g_s2>>>(anchors, attp, b * 16);
        cudaEventRecord(g_e2[b], g_s2);
    }
    // GEMM2 per batch, alternating stream 0 / s3
    cudaStreamWaitEvent(0, g_ewo, 0);
    cudaStreamWaitEvent(g_s3, g_ewo, 0);
    for (int b = 0; b < 4; b++) {
        cudaStream_t st = (b & 1) ? g_s3 : (cudaStream_t)0;
        cudaStreamWaitEvent(st, g_e2[b], 0);
        gemm256_kernel<<<dim3(8, 32), 512, GEMM_SMEM, st>>>(
            attp + b * ABLK, wotp, out + b * ABLK, nullptr, 0);
    }
    // JOIN: fold s3 back into origin stream
    cudaEventRecord(g_e3, g_s3);
    cudaStreamWaitEvent(0, g_e3, 0);
}

// round 15
// speedup vs baseline: 10.6248x; 1.2492x over previous
#include <cuda_runtime.h>
#include <cuda_fp16.h>
#include <cstdint>
#include <math.h>

#define BB 4
#define SS 4096
#define DD 2048
#define HH 16
#define HDIM 128
#define NKEYS 128

// ---------------- scratch ----------------
__device__ __half g_qh [(size_t)BB * SS * DD];   // Q, attn-smem image
__device__ __half g_att[(size_t)BB * SS * DD];   // half TILED (GEMM2 A)
__device__ __half g_xh [(size_t)BB * SS * DD];   // half TILED
__device__ __half g_wqt[2048 * 2048];            // half TILED [n][k]
__device__ __half g_wot[2048 * 2048];
__device__ __half g_wkt[2048 * 2048];
__device__ __half g_wvt[2048 * 2048];
__device__ __half g_kh [64 * NKEYS * HDIM];      // K attn image: [bh][key][128d swz]
__device__ __half g_vh [64 * NKEYS * HDIM];      // V attn image: [bh][d][128key swz]

// ---------------- helpers ----------------
__device__ __forceinline__ uint32_t smem_u32(const void* p) {
    uint32_t a;
    asm("{ .reg .u64 t; cvta.to.shared.u64 t, %1; cvt.u32.u64 %0, t; }" : "=r"(a) : "l"(p));
    return a;
}
#define CP_ASYNC16(dst, src) \
    asm volatile("cp.async.cg.shared.global [%0], [%1], 16;" :: "r"(dst), "l"(src) : "memory")
#define CP_COMMIT() asm volatile("cp.async.commit_group;" ::: "memory")
#define CP_WAIT(n)  asm volatile("cp.async.wait_group %0;" :: "n"(n) : "memory")
#define CP_BULK(dst, src, bytes, mbar) \
    asm volatile("cp.async.bulk.shared::cluster.global.mbarrier::complete_tx::bytes [%0], [%1], %2, [%3];" \
        :: "r"(dst), "l"(src), "r"(bytes), "r"(mbar) : "memory")
#define MBARRIER_INIT(addr, cnt) \
    asm volatile("mbarrier.init.shared.b64 [%0], %1;" :: "r"(addr), "r"(cnt) : "memory")
#define MBARRIER_EXPECT_TX(addr, tx) \
    asm volatile("mbarrier.arrive.expect_tx.shared.b64 _, [%0], %1;" :: "r"(addr), "r"(tx) : "memory")
#define MBARRIER_WAIT_PARITY(addr, ph) do { \
    uint32_t _m = (addr), _p = (ph), _d; \
    asm volatile("{\n\t.reg .pred p;\n\t" \
        "mbarrier.try_wait.parity.acquire.cta.shared::cta.b64 p, [%1], %2;\n\t" \
        "selp.b32 %0, 1, 0, p;\n\t}" : "=r"(_d) : "r"(_m), "r"(_p) : "memory"); \
    if (!_d) { \
        asm volatile("{\n\t.reg .pred P1;\n\tWL_%=:\n\t" \
            "mbarrier.try_wait.parity.acquire.cta.shared::cta.b64 P1, [%0], %1, 0x989680;\n\t" \
            "@P1 bra.uni WD_%=;\n\tbra.uni WL_%=;\n\tWD_%=:\n\t}" \
            :: "r"(_m), "r"(_p) : "memory"); \
    } } while (0)
#define LDMX4(r0, r1, r2, r3, addr) \
    asm volatile("ldmatrix.sync.aligned.m8n8.x4.shared.b16 {%0,%1,%2,%3}, [%4];" \
        : "=r"(r0), "=r"(r1), "=r"(r2), "=r"(r3) : "r"(addr))

__device__ __forceinline__ void mma_f16_16x8x16(
    float& c0, float& c1, float& c2, float& c3,
    uint32_t a0, uint32_t a1, uint32_t a2, uint32_t a3,
    uint32_t b0, uint32_t b1)
{
    asm volatile(
        "mma.sync.aligned.m16n8k16.row.col.f32.f16.f16.f32 "
        "{%0,%1,%2,%3}, {%4,%5,%6,%7}, {%8,%9}, {%0,%1,%2,%3};"
        : "+f"(c0), "+f"(c1), "+f"(c2), "+f"(c3)
        : "r"(a0), "r"(a1), "r"(a2), "r"(a3), "r"(b0), "r"(b1));
}

// ---------------- prep: x -> half TILED (one batch per launch) ----------------
__global__ void round_half_kernel(const float4* __restrict__ in, __half* __restrict__ out) {
    int i = blockIdx.x * 256 + threadIdx.x;
    float4 v = in[i];
    int m = i >> 9, c4 = i & 511;
    int kblk = c4 >> 3;
    int g0 = (c4 & 7) * 2;
    int r = m & 127, mblk = m >> 7;
    int phys = g0 ^ (((r >> 1) & 3) << 2);
    __half2* dst = (__half2*)(out + ((size_t)(mblk * 64 + kblk) * 4096 + r * 32 + phys * 2));
    dst[0] = __floats2half2_rn(v.x, v.y);
    dst[1] = __floats2half2_rn(v.z, v.w);
}

// ---------------- prep: W -> half TILED [n][k], vectorized 16B stores ----------------
__global__ void transpose_half_kernel(const float* __restrict__ W, __half* __restrict__ WT) {
    __shared__ float t[32][132];
    int n0 = blockIdx.x * 128, kblk = blockIdx.y, k0 = kblk * 32;
    int tid = threadIdx.x;
#pragma unroll
    for (int i = 0; i < 16; i++) {
        int lin = i * 256 + tid;
        int k = lin >> 7, n = lin & 127;
        t[k][n] = W[(size_t)(k0 + k) * 2048 + n0 + n];
    }
    __syncthreads();
    int r = tid & 127;
    int cbase = (tid >> 7) * 2;
    int sw = (r >> 1) & 3;
    __half* obase = WT + (size_t)((n0 >> 7) * 64 + kblk) * 4096 + r * 32;
#pragma unroll
    for (int cc = 0; cc < 2; cc++) {
        int c = cbase + cc;
        __half h[8];
#pragma unroll
        for (int i = 0; i < 8; i++) h[i] = __float2half_rn(t[c * 8 + i][r]);
        *(uint4*)(obase + ((c ^ sw) * 8)) = *(uint4*)h;
    }
}

// ---------------- fp16 GEMM (bulk + ldmatrix); barrier every 2 kts ----------------
#define GSTAGE_B 24576
#define GSTAGE_H 12288
#define GEMM_SMEM (4 * GSTAGE_B + 64)

__global__ __launch_bounds__(512, 1) void gemm256_kernel(
    const __half* __restrict__ A, const __half* __restrict__ BW,
    float* __restrict__ C, __half* __restrict__ Qh, int mode)
{
    extern __shared__ __half shh[];
    uint32_t sb = smem_u32(shh);
    uint32_t mb = sb + 4 * GSTAGE_B;

    int tid = threadIdx.x;
    int wid = tid >> 5, lane = tid & 31;
    int wm = wid >> 2, wn = wid & 3;
    int gq = lane >> 2, kc = lane & 3;
    int n0 = blockIdx.x * 256, m0 = blockIdx.y * 128;

    if (tid == 0) {
#pragma unroll
        for (int s = 0; s < 4; s++) MBARRIER_INIT(mb + 8 * s, 1);
    }
    __syncthreads();

    const __half* Ab = A  + (size_t)(m0 >> 7) * 64 * 4096;
    const __half* B0 = BW + (size_t)(n0 >> 7) * 64 * 4096;
    const __half* B1 = BW + (size_t)((n0 >> 7) + 1) * 64 * 4096;

    if (tid == 0) {
#pragma unroll
        for (int s = 0; s < 4; s++) {                    // prefill ALL 4 stages
            MBARRIER_EXPECT_TX(mb + 8 * s, GSTAGE_B);
            CP_BULK(sb + s * GSTAGE_B,         Ab + (size_t)s * 4096, 8192, mb + 8 * s);
            CP_BULK(sb + s * GSTAGE_B + 8192,  B0 + (size_t)s * 4096, 8192, mb + 8 * s);
            CP_BULK(sb + s * GSTAGE_B + 16384, B1 + (size_t)s * 4096, 8192, mb + 8 * s);
        }
    }

    int laneAr = wm * 32 + (lane & 7) + (((lane >> 3) & 1) << 3);
    int cA = lane >> 4;
    int swA = (laneAr >> 1) & 3;
    uint32_t aAddr0 = sb + (uint32_t)laneAr * 64 + (uint32_t)((cA     ^ swA) << 4);
    uint32_t aAddr1 = sb + (uint32_t)laneAr * 64 + (uint32_t)(((2|cA) ^ swA) << 4);
    int laneBr = wn * 64 + ((lane >> 4) << 3) + (lane & 7);
    int cB = (lane >> 3) & 1;
    int swB = (laneBr >> 1) & 3;
    uint32_t bAddr0 = sb + 8192 + (uint32_t)laneBr * 64 + (uint32_t)((cB     ^ swB) << 4);
    uint32_t bAddr1 = sb + 8192 + (uint32_t)laneBr * 64 + (uint32_t)(((2|cB) ^ swB) << 4);

    float acc[2][8][4];
#pragma unroll
    for (int i = 0; i < 2; i++)
#pragma unroll
        for (int j = 0; j < 8; j++)
#pragma unroll
            for (int r = 0; r < 4; r++) acc[i][j][r] = 0.f;

    for (int kt = 0; kt < 64; kt += 2) {
#pragma unroll
        for (int u = 0; u < 2; u++) {
            int k = kt + u, s = k & 3;
            MBARRIER_WAIT_PARITY(mb + 8 * s, (k >> 2) & 1);
            uint32_t so = (uint32_t)s * GSTAGE_B;
#pragma unroll
            for (int t = 0; t < 2; t++) {
                uint32_t aA = (t ? aAddr1 : aAddr0) + so;
                uint32_t bA = (t ? bAddr1 : bAddr0) + so;
                uint32_t af[2][4], bf[8][2];
                LDMX4(af[0][0], af[0][1], af[0][2], af[0][3], aA);
                LDMX4(af[1][0], af[1][1], af[1][2], af[1][3], aA + 1024);
#pragma unroll
                for (int nfp = 0; nfp < 4; nfp++)
                    LDMX4(bf[2 * nfp][0], bf[2 * nfp][1], bf[2 * nfp + 1][0], bf[2 * nfp + 1][1],
                          bA + nfp * 1024);
#pragma unroll
                for (int mf = 0; mf < 2; mf++)
#pragma unroll
                    for (int nf = 0; nf < 8; nf++)
                        mma_f16_16x8x16(acc[mf][nf][0], acc[mf][nf][1],
                                        acc[mf][nf][2], acc[mf][nf][3],
                                        af[mf][0], af[mf][1], af[mf][2], af[mf][3],
                                        bf[nf][0], bf[nf][1]);
            }
        }
        __syncthreads();
        if (tid == 0 && kt + 4 < 64) {
#pragma unroll
            for (int u = 0; u < 2; u++) {
                int kl = kt + 4 + u, s2 = kl & 3;
                MBARRIER_EXPECT_TX(mb + 8 * s2, GSTAGE_B);
                CP_BULK(sb + s2 * GSTAGE_B,         Ab + (size_t)kl * 4096, 8192, mb + 8 * s2);
                CP_BULK(sb + s2 * GSTAGE_B + 8192,  B0 + (size_t)kl * 4096, 8192, mb + 8 * s2);
                CP_BULK(sb + s2 * GSTAGE_B + 16384, B1 + (size_t)kl * 4096, 8192, mb + 8 * s2);
            }
        }
    }

    if (mode == 0) {
#pragma unroll
        for (int mf = 0; mf < 2; mf++) {
            int r0 = m0 + wm * 32 + mf * 16 + gq;
#pragma unroll
            for (int nf = 0; nf < 8; nf++) {
                int col = n0 + wn * 64 + nf * 8 + kc * 2;
                *(float2*)&C[(size_t)r0 * 2048 + col]       = make_float2(acc[mf][nf][0], acc[mf][nf][1]);
                *(float2*)&C[(size_t)(r0 + 8) * 2048 + col] = make_float2(acc[mf][nf][2], acc[mf][nf][3]);
            }
        }
    } else {
#pragma unroll
        for (int mf = 0; mf < 2; mf++) {
            int r0 = m0 + wm * 32 + mf * 16 + gq;
            int q = r0 & 127, mblk = r0 >> 7;
            int sw = (q & 7) << 2;
#pragma unroll
            for (int nf = 0; nf < 8; nf++) {
                int col = n0 + wn * 64 + nf * 8 + kc * 2;
                int head = col >> 7, d = col & 127;
                int phys = (d >> 1) ^ sw;
                size_t base = ((size_t)(mblk * 16 + head) * 128 + q) * 128 + phys * 2;
                *(__half2*)(Qh + base)        = __floats2half2_rn(acc[mf][nf][0], acc[mf][nf][1]);
                *(__half2*)(Qh + base + 1024) = __floats2half2_rn(acc[mf][nf][2], acc[mf][nf][3]);
            }
        }
    }
}

// ---------------- sparse K/V projection -> half attn images ----------------
// blockIdx.y==0: K = gathered_x @ WkT  (rows=token). ==1: V^T = WvT @ gathered_x (rows=d).
#define KVSTAGE_B 16384
#define KVSTAGE_H 8192
#define KV_SMEM (4 * KVSTAGE_B + 128 * 4)

__global__ __launch_bounds__(256, 1) void sparse_kv_mma_kernel(
    const int* __restrict__ anchors)
{
    extern __shared__ __half shh[];
    int* tok = (int*)(shh + 4 * KVSTAGE_H);

    int tid = threadIdx.x;
    int bh = blockIdx.x;
    int h = bh & 15, b = bh >> 4;
    int vsel = blockIdx.y;
    const __half* Bb = (vsel ? g_wvt : g_wkt) + (size_t)h * 64 * 4096;
    __half* img = (vsel ? g_vh : g_kh) + (size_t)bh * 16384;

    if (tid < 128) {
        int ti = tid >> 4;
        int tile = (ti == 7) ? 255 : anchors[(bh << 3) + ti];
        tok[tid] = tile * 16 + (tid & 15);
    }
    __syncthreads();

    int wid = tid >> 5, lane = tid & 31;
    int wm = wid >> 2, wn = wid & 3;
    int gq = lane >> 2, kc = lane & 3;

    uint32_t sb = smem_u32(shh);

    // fragment regions: x tile at +0, W tile at +8192 (bytes). For V, swap A/B roles.
    uint32_t aReg = vsel ? 8192u : 0u;
    uint32_t bReg = vsel ? 0u : 8192u;

    int laneAr = wm * 64 + (lane & 7) + (((lane >> 3) & 1) << 3);
    int cA = lane >> 4;
    int swA = (laneAr >> 1) & 3;
    uint32_t aAddr0 = sb + aReg + (uint32_t)laneAr * 64 + (uint32_t)((cA     ^ swA) << 4);
    uint32_t aAddr1 = sb + aReg + (uint32_t)laneAr * 64 + (uint32_t)(((2|cA) ^ swA) << 4);
    int laneBr = wn * 32 + ((lane >> 4) << 3) + (lane & 7);
    int cB = (lane >> 3) & 1;
    int swB = (laneBr >> 1) & 3;
    uint32_t bAddr0 = sb + bReg + (uint32_t)laneBr * 64 + (uint32_t)((cB     ^ swB) << 4);
    uint32_t bAddr1 = sb + bReg + (uint32_t)laneBr * 64 + (uint32_t)(((2|cB) ^ swB) << 4);

    float acc[4][4][4];
#pragma unroll
    for (int i = 0; i < 4; i++)
#pragma unroll
        for (int j = 0; j < 4; j++)
#pragma unroll
            for (int r = 0; r < 4; r++) acc[i][j][r] = 0.f;

#pragma unroll
    for (int s = 0; s < 3; s++) {
        uint32_t so = sb + s * KVSTAGE_B;
#pragma unroll
        for (int i = 0; i < 2; i++) {
            int cidx = i * 256 + tid;
            int rs = cidx >> 2, c = cidx & 3;
            int grow = b * SS + tok[rs];
            const __half* srcA = g_xh + (size_t)((grow >> 7) * 64 + s) * 4096
                               + (grow & 127) * 32 + ((c ^ ((grow >> 1) & 3)) * 8);
            CP_ASYNC16(so + (uint32_t)(rs * 64 + (c ^ ((rs >> 1) & 3)) * 16), srcA);
            const __half* srcB = Bb + (size_t)s * 4096 + rs * 32 + ((c ^ ((rs >> 1) & 3)) * 8);
            CP_ASYNC16(so + 8192 + (uint32_t)(rs * 64 + (c ^ ((rs >> 1) & 3)) * 16), srcB);
        }
        CP_COMMIT();
    }

    for (int kt = 0; kt < 64; kt++) {
        CP_WAIT(2);
        __syncthreads();
        if (kt + 3 < 64) {
            int sl = kt + 3;
            uint32_t so = sb + (uint32_t)(sl & 3) * KVSTAGE_B;
#pragma unroll
            for (int i = 0; i < 2; i++) {
                int cidx = i * 256 + tid;
                int rs = cidx >> 2, c = cidx & 3;
                int grow = b * SS + tok[rs];
                const __half* srcA = g_xh + (size_t)((grow >> 7) * 64 + sl) * 4096
                                   + (grow & 127) * 32 + ((c ^ ((grow >> 1) & 3)) * 8);
                CP_ASYNC16(so + (uint32_t)(rs * 64 + (c ^ ((rs >> 1) & 3)) * 16), srcA);
                const __half* srcB = Bb + (size_t)sl * 4096 + rs * 32 + ((c ^ ((rs >> 1) & 3)) * 8);
                CP_ASYNC16(so + 8192 + (uint32_t)(rs * 64 + (c ^ ((rs >> 1) & 3)) * 16), srcB);
            }
        }
        CP_COMMIT();

        uint32_t so = (uint32_t)(kt & 3) * KVSTAGE_B;
#pragma unroll
        for (int t = 0; t < 2; t++) {
            uint32_t aA = (t ? aAddr1 : aAddr0) + so;
            uint32_t bA = (t ? bAddr1 : bAddr0) + so;
            uint32_t af[4][4], bf[4][2];
#pragma unroll
            for (int mf = 0; mf < 4; mf++)
                LDMX4(af[mf][0], af[mf][1], af[mf][2], af[mf][3], aA + mf * 1024);
#pragma unroll
            for (int nfp = 0; nfp < 2; nfp++)
                LDMX4(bf[2 * nfp][0], bf[2 * nfp][1], bf[2 * nfp + 1][0], bf[2 * nfp + 1][1],
                      bA + nfp * 1024);
#pragma unroll
            for (int mf = 0; mf < 4; mf++)
#pragma unroll
                for (int nf = 0; nf < 4; nf++)
                    mma_f16_16x8x16(acc[mf][nf][0], acc[mf][nf][1],
                                    acc[mf][nf][2], acc[mf][nf][3],
                                    af[mf][0], af[mf][1], af[mf][2], af[mf][3],
                                    bf[nf][0], bf[nf][1]);
        }
    }

    // epilogue: rows = (K: token | V: d), cols paired along the image's granule dim.
    {
        int sw = gq << 2;                      // (row & 7) << 2
#pragma unroll
        for (int mf = 0; mf < 4; mf++) {
            int r0 = wm * 64 + mf * 16 + gq;
            __half* row0 = img + r0 * 128;
            __half* row1 = img + (r0 + 8) * 128;
#pragma unroll
            for (int nf = 0; nf < 4; nf++) {
                int g = wn * 16 + nf * 4 + kc;
                int phys = g ^ sw;
                *(__half2*)(row0 + phys * 2) = __floats2half2_rn(acc[mf][nf][0], acc[mf][nf][1]);
                *(__half2*)(row1 + phys * 2) = __floats2half2_rn(acc[mf][nf][2], acc[mf][nf][3]);
            }
        }
    }
}

// ---------------- attention: all operands via cp.async.bulk ----------------
#define ATTN_TOK_OFF (3 * 32768)
#define ATTN_SMEM (ATTN_TOK_OFF + 512 + 16)

__global__ __launch_bounds__(256) void attn_mma_kernel(
    const int* __restrict__ anchors, __half* __restrict__ attout, int bhbase)
{
    extern __shared__ char smraw[];
    __half* QPh = ((__half*)smraw) + 2 * 16384;   // [q][128] Q then P
    int*    tok = (int*)(smraw + ATTN_TOK_OFF);
    uint32_t sbb = smem_u32(smraw);
    uint32_t mb = sbb + ATTN_TOK_OFF + 512;

    int tid = threadIdx.x;
    int bh = bhbase + blockIdx.y;
    int b = bh >> 4, h = bh & 15;
    int q0 = blockIdx.x * 128;
    int wid = tid >> 5, lane = tid & 31;
    int gq = lane >> 2, kc = lane & 3;

    if (tid == 0) MBARRIER_INIT(mb, 1);
    if (tid < 128) {
        int ti = tid >> 4;
        int tile = (ti == 7) ? 255 : anchors[(bh << 3) + ti];
        tok[tid] = tile * 16 + (tid & 15);
    }
    __syncthreads();

    if (tid == 0) {
        const __half* qsrc = g_qh + ((size_t)((b * 32 + (q0 >> 7)) * 16 + h) * 16384);
        MBARRIER_EXPECT_TX(mb, 3 * 32768);
        CP_BULK(sbb,             g_kh + (size_t)bh * 16384, 32768, mb);
        CP_BULK(sbb + 32768,     g_vh + (size_t)bh * 16384, 32768, mb);
        CP_BULK(sbb + 2 * 32768, qsrc,                      32768, mb);
    }
    MBARRIER_WAIT_PARITY(mb, 0);

    int laneAr = wid * 16 + (lane & 7) + (((lane >> 3) & 1) << 3);
    int cA = lane >> 4;
    int laneBr = ((lane >> 4) << 3) + (lane & 7);
    int cB = (lane >> 3) & 1;
    uint32_t qBase = sbb + 2 * 32768 + (uint32_t)laneAr * 256;
    uint32_t kBase = sbb + (uint32_t)laneBr * 256;
    uint32_t vBase = sbb + 32768 + (uint32_t)laneBr * 256;
    int swAa = laneAr & 7, swBa = laneBr & 7;

    int r = wid * 16 + gq;

    // ---- S = Q @ K^T ----
    float acc[16][4];
#pragma unroll
    for (int nf = 0; nf < 16; nf++)
#pragma unroll
        for (int z = 0; z < 4; z++) acc[nf][z] = 0.f;
#pragma unroll
    for (int t = 0; t < 8; t++) {
        uint32_t af[4], bf[16][2];
        LDMX4(af[0], af[1], af[2], af[3], qBase + (uint32_t)(((2 * t + cA) ^ swAa) << 4));
#pragma unroll
        for (int nfp = 0; nfp < 8; nfp++)
            LDMX4(bf[2 * nfp][0], bf[2 * nfp][1], bf[2 * nfp + 1][0], bf[2 * nfp + 1][1],
                  kBase + nfp * 4096 + (uint32_t)(((2 * t + cB) ^ swBa) << 4));
#pragma unroll
        for (int nf = 0; nf < 16; nf++)
            mma_f16_16x8x16(acc[nf][0], acc[nf][1], acc[nf][2], acc[nf][3],
                            af[0], af[1], af[2], af[3], bf[nf][0], bf[nf][1]);
    }

    // ---- register softmax ----
    {
        const float scale = 0.0883883476483184f;
        int qpos0 = q0 + r, qpos1 = qpos0 + 8;
        float mx0 = -3.0e38f, mx1 = -3.0e38f;
#pragma unroll
        for (int nf = 0; nf < 16; nf++)
#pragma unroll
            for (int j = 0; j < 2; j++) {
                int tcol = tok[nf * 8 + kc * 2 + j];
                float v0 = acc[nf][j] * scale;
                float v1 = acc[nf][2 + j] * scale;
                if (tcol > qpos0) v0 = -1e10f;
                if (tcol > qpos1) v1 = -1e10f;
                acc[nf][j] = v0; acc[nf][2 + j] = v1;
                mx0 = fmaxf(mx0, v0); mx1 = fmaxf(mx1, v1);
            }
        mx0 = fmaxf(mx0, __shfl_xor_sync(0xffffffffu, mx0, 1));
        mx0 = fmaxf(mx0, __shfl_xor_sync(0xffffffffu, mx0, 2));
        mx1 = fmaxf(mx1, __shfl_xor_sync(0xffffffffu, mx1, 1));
        mx1 = fmaxf(mx1, __shfl_xor_sync(0xffffffffu, mx1, 2));
        float s0 = 0.f, s1 = 0.f;
#pragma unroll
        for (int nf = 0; nf < 16; nf++)
#pragma unroll
            for (int j = 0; j < 2; j++) {
                float e0 = __expf(acc[nf][j] - mx0);
                float e1 = __expf(acc[nf][2 + j] - mx1);
                acc[nf][j] = e0; acc[nf][2 + j] = e1;
                s0 += e0; s1 += e1;
            }
        s0 += __shfl_xor_sync(0xffffffffu, s0, 1);
        s0 += __shfl_xor_sync(0xffffffffu, s0, 2);
        s1 += __shfl_xor_sync(0xffffffffu, s1, 1);
        s1 += __shfl_xor_sync(0xffffffffu, s1, 2);
        float inv0 = 1.f / s0, inv1 = 1.f / s1;
        int sw = (r & 7) << 2;
#pragma unroll
        for (int nf = 0; nf < 16; nf++) {
            int g = nf * 4 + kc;
            int phys = g ^ sw;
            *(__half2*)(QPh + r * 128 + phys * 2) =
                __floats2half2_rn(acc[nf][0] * inv0, acc[nf][1] * inv0);
            *(__half2*)(QPh + (r + 8) * 128 + phys * 2) =
                __floats2half2_rn(acc[nf][2] * inv1, acc[nf][3] * inv1);
        }
        __syncwarp();
    }

    // ---- O = P @ V ----
    float acc2[16][4];
#pragma unroll
    for (int nf = 0; nf < 16; nf++)
#pragma unroll
        for (int z = 0; z < 4; z++) acc2[nf][z] = 0.f;
#pragma unroll
    for (int t = 0; t < 8; t++) {
        uint32_t af[4], bf[16][2];
        LDMX4(af[0], af[1], af[2], af[3], qBase + (uint32_t)(((2 * t + cA) ^ swAa) << 4));
#pragma unroll
        for (int nfp = 0; nfp < 8; nfp++)
            LDMX4(bf[2 * nfp][0], bf[2 * nfp][1], bf[2 * nfp + 1][0], bf[2 * nfp + 1][1],
                  vBase + nfp * 4096 + (uint32_t)(((2 * t + cB) ^ swBa) << 4));
#pragma unroll
        for (int nf = 0; nf < 16; nf++)
            mma_f16_16x8x16(acc2[nf][0], acc2[nf][1], acc2[nf][2], acc2[nf][3],
                            af[0], af[1], af[2], af[3], bf[nf][0], bf[nf][1]);
    }

    // ---- store O in half TILED layout ----
    {
        int mblk = (b * SS + q0) >> 7;
        __half* abase = attout + (size_t)mblk * 64 * 4096;
        int sw = ((r >> 1) & 3) << 2;
#pragma unroll
        for (int nf = 0; nf < 16; nf++) {
            int col = h * HDIM + nf * 8 + kc * 2;
            int kblk = col >> 5, kcol = col & 31;
            int phys = (kcol >> 1) ^ sw;
            *(__half2*)(abase + (size_t)kblk * 4096 + r * 32 + phys * 2) =
                __floats2half2_rn(acc2[nf][0], acc2[nf][1]);
            *(__half2*)(abase + (size_t)kblk * 4096 + (r + 8) * 32 + phys * 2) =
                __floats2half2_rn(acc2[nf][2], acc2[nf][3]);
        }
    }
}

// ---------------- streams/events ----------------
static cudaStream_t g_s1a, g_s1b, g_s2, g_s3;
static cudaEvent_t g_estart, g_erhb[4], g_ewq, g_ewo, g_ekv, g_e1[4], g_e2[4], g_e3;
static bool g_streams_ok = [](){
    cudaStreamCreateWithFlags(&g_s1a, cudaStreamNonBlocking);
    cudaStreamCreateWithFlags(&g_s1b, cudaStreamNonBlocking);
    cudaStreamCreateWithFlags(&g_s2,  cudaStreamNonBlocking);
    cudaStreamCreateWithFlags(&g_s3,  cudaStreamNonBlocking);
    cudaEventCreateWithFlags(&g_estart, cudaEventDisableTiming);
    cudaEventCreateWithFlags(&g_ewq, cudaEventDisableTiming);
    cudaEventCreateWithFlags(&g_ewo, cudaEventDisableTiming);
    cudaEventCreateWithFlags(&g_ekv, cudaEventDisableTiming);
    cudaEventCreateWithFlags(&g_e3,  cudaEventDisableTiming);
    for (int i = 0; i < 4; i++) {
        cudaEventCreateWithFlags(&g_erhb[i], cudaEventDisableTiming);
        cudaEventCreateWithFlags(&g_e1[i], cudaEventDisableTiming);
        cudaEventCreateWithFlags(&g_e2[i], cudaEventDisableTiming);
    }
    return true;
}();

// ---------------- launch ----------------
extern "C" void kernel_launch(void* const* d_in, const int* in_sizes, int n_in,
                              void* d_out, int out_size)
{
    const float* x       = (const float*)d_in[0];
    const int*   anchors = (const int*)  d_in[1];
    const float* Wq      = (const float*)d_in[2];
    const float* Wk      = (const float*)d_in[3];
    const float* Wv      = (const float*)d_in[4];
    const float* Wo      = (const float*)d_in[5];
    float* out = (float*)d_out;

    __half *qhp, *attp, *xhp, *wqtp, *wotp, *wktp, *wvtp;
    cudaGetSymbolAddress((void**)&qhp,  g_qh);
    cudaGetSymbolAddress((void**)&attp, g_att);
    cudaGetSymbolAddress((void**)&xhp,  g_xh);
    cudaGetSymbolAddress((void**)&wqtp, g_wqt);
    cudaGetSymbolAddress((void**)&wotp, g_wot);
    cudaGetSymbolAddress((void**)&wktp, g_wkt);
    cudaGetSymbolAddress((void**)&wvtp, g_wvt);

    cudaFuncSetAttribute(attn_mma_kernel, cudaFuncAttributeMaxDynamicSharedMemorySize, ATTN_SMEM);
    cudaFuncSetAttribute(gemm256_kernel, cudaFuncAttributeMaxDynamicSharedMemorySize, GEMM_SMEM);
    cudaFuncSetAttribute(sparse_kv_mma_kernel, cudaFuncAttributeMaxDynamicSharedMemorySize, KV_SMEM);

    const size_t ABLK = (size_t)SS * DD;
    const size_t X4BLK = (size_t)SS * DD / 4;

    // FORK root
    cudaEventRecord(g_estart, 0);

    // stream 0: per-batch rounding of x
    for (int b = 0; b < 4; b++) {
        round_half_kernel<<<(SS * DD / 4) / 256, 256>>>(
            (const float4*)(x + b * 4 * X4BLK), xhp + b * ABLK);
        cudaEventRecord(g_erhb[b], 0);
    }

    // s2 forks from origin: weight transposes, then sparse KV
    cudaStreamWaitEvent(g_s2, g_estart, 0);
    transpose_half_kernel<<<dim3(16, 64), 256, 0, g_s2>>>(Wq, wqtp);
    cudaEventRecord(g_ewq, g_s2);
    transpose_half_kernel<<<dim3(16, 64), 256, 0, g_s2>>>(Wk, wktp);
    transpose_half_kernel<<<dim3(16, 64), 256, 0, g_s2>>>(Wv, wvtp);
    transpose_half_kernel<<<dim3(16, 64), 256, 0, g_s2>>>(Wo, wotp);
    cudaEventRecord(g_ewo, g_s2);
    cudaStreamWaitEvent(g_s2, g_erhb[3], 0);
    sparse_kv_mma_kernel<<<dim3(64, 2), 256, KV_SMEM, g_s2>>>(anchors);
    cudaEventRecord(g_ekv, g_s2);

    // GEMM1 per batch, alternating streams
    for (int b = 0; b < 4; b++) {
        cudaStream_t st = (b & 1) ? g_s1b : g_s1a;
        cudaStreamWaitEvent(st, g_erhb[b], 0);
        cudaStreamWaitEvent(st, g_ewq, 0);
        gemm256_kernel<<<dim3(8, 32), 512, GEMM_SMEM, st>>>(
            xhp + b * ABLK, wqtp, nullptr, qhp + b * ABLK, 1);
        cudaEventRecord(g_e1[b], st);
    }
    // attention per batch on s2 (after kv)
    for (int b = 0; b < 4; b++) {
        cudaStreamWaitEvent(g_s2, g_e1[b], 0);
        attn_mma_kernel<<<dim3(32, 16), 256, ATTN_SMEM, g_s2>>>(anchors, attp, b * 16);
        cudaEventRecord(g_e2[b], g_s2);
    }
    // GEMM2 per batch, alternating stream 0 / s3
    cudaStreamWaitEvent(0, g_ewo, 0);
    cudaStreamWaitEvent(g_s3, g_ewo, 0);
    for (int b = 0; b < 4; b++) {
        cudaStream_t st = (b & 1) ? g_s3 : (cudaStream_t)0;
        cudaStreamWaitEvent(st, g_e2[b], 0);
        gemm256_kernel<<<dim3(8, 32), 512, GEMM_SMEM, st>>>(
            attp + b * ABLK, wotp, out + b * ABLK, nullptr, 0);
    }
    // JOIN
    cudaEventRecord(g_e3, g_s3);
    cudaStreamWaitEvent(0, g_e3, 0);
}

// round 16
// speedup vs baseline: 10.9207x; 1.0278x over previous
#include <cuda_runtime.h>
#include <cuda_fp16.h>
#include <cstdint>
#include <math.h>

#define BB 4
#define SS 4096
#define DD 2048
#define HH 16
#define HDIM 128
#define NKEYS 128

// ---------------- scratch ----------------
__device__ __half g_qh [(size_t)BB * SS * DD];   // Q, attn-smem image
__device__ __half g_att[(size_t)BB * SS * DD];   // half TILED (GEMM2 A)
__device__ __half g_xh [(size_t)BB * SS * DD];   // half TILED
__device__ __half g_wqt[2048 * 2048];            // half TILED [n][k]
__device__ __half g_wot[2048 * 2048];
__device__ __half g_wkt[2048 * 2048];
__device__ __half g_wvt[2048 * 2048];
__device__ __half g_kh [64 * NKEYS * HDIM];      // K attn image
__device__ __half g_vh [64 * NKEYS * HDIM];      // V attn image (transposed)

// ---------------- helpers ----------------
__device__ __forceinline__ uint32_t smem_u32(const void* p) {
    uint32_t a;
    asm("{ .reg .u64 t; cvta.to.shared.u64 t, %1; cvt.u32.u64 %0, t; }" : "=r"(a) : "l"(p));
    return a;
}
#define CP_ASYNC16(dst, src) \
    asm volatile("cp.async.cg.shared.global [%0], [%1], 16;" :: "r"(dst), "l"(src) : "memory")
#define CP_COMMIT() asm volatile("cp.async.commit_group;" ::: "memory")
#define CP_WAIT(n)  asm volatile("cp.async.wait_group %0;" :: "n"(n) : "memory")
#define CP_BULK(dst, src, bytes, mbar) \
    asm volatile("cp.async.bulk.shared::cluster.global.mbarrier::complete_tx::bytes [%0], [%1], %2, [%3];" \
        :: "r"(dst), "l"(src), "r"(bytes), "r"(mbar) : "memory")
#define MBARRIER_INIT(addr, cnt) \
    asm volatile("mbarrier.init.shared.b64 [%0], %1;" :: "r"(addr), "r"(cnt) : "memory")
#define MBARRIER_EXPECT_TX(addr, tx) \
    asm volatile("mbarrier.arrive.expect_tx.shared.b64 _, [%0], %1;" :: "r"(addr), "r"(tx) : "memory")
#define MBARRIER_WAIT_PARITY(addr, ph) do { \
    uint32_t _m = (addr), _p = (ph), _d; \
    asm volatile("{\n\t.reg .pred p;\n\t" \
        "mbarrier.try_wait.parity.acquire.cta.shared::cta.b64 p, [%1], %2;\n\t" \
        "selp.b32 %0, 1, 0, p;\n\t}" : "=r"(_d) : "r"(_m), "r"(_p) : "memory"); \
    if (!_d) { \
        asm volatile("{\n\t.reg .pred P1;\n\tWL_%=:\n\t" \
            "mbarrier.try_wait.parity.acquire.cta.shared::cta.b64 P1, [%0], %1, 0x989680;\n\t" \
            "@P1 bra.uni WD_%=;\n\tbra.uni WL_%=;\n\tWD_%=:\n\t}" \
            :: "r"(_m), "r"(_p) : "memory"); \
    } } while (0)
#define LDMX4(r0, r1, r2, r3, addr) \
    asm volatile("ldmatrix.sync.aligned.m8n8.x4.shared.b16 {%0,%1,%2,%3}, [%4];" \
        : "=r"(r0), "=r"(r1), "=r"(r2), "=r"(r3) : "r"(addr))

__device__ __forceinline__ void mma_f16_16x8x16(
    float& c0, float& c1, float& c2, float& c3,
    uint32_t a0, uint32_t a1, uint32_t a2, uint32_t a3,
    uint32_t b0, uint32_t b1)
{
    asm volatile(
        "mma.sync.aligned.m16n8k16.row.col.f32.f16.f16.f32 "
        "{%0,%1,%2,%3}, {%4,%5,%6,%7}, {%8,%9}, {%0,%1,%2,%3};"
        : "+f"(c0), "+f"(c1), "+f"(c2), "+f"(c3)
        : "r"(a0), "r"(a1), "r"(a2), "r"(a3), "r"(b0), "r"(b1));
}

// ---------------- prep: x -> half TILED (one batch per launch) ----------------
__global__ void round_half_kernel(const float4* __restrict__ in, __half* __restrict__ out) {
    int i = blockIdx.x * 256 + threadIdx.x;
    float4 v = in[i];
    int m = i >> 9, c4 = i & 511;
    int kblk = c4 >> 3;
    int g0 = (c4 & 7) * 2;
    int r = m & 127, mblk = m >> 7;
    int phys = g0 ^ (((r >> 1) & 3) << 2);
    __half2* dst = (__half2*)(out + ((size_t)(mblk * 64 + kblk) * 4096 + r * 32 + phys * 2));
    dst[0] = __floats2half2_rn(v.x, v.y);
    dst[1] = __floats2half2_rn(v.z, v.w);
}

// ---------------- prep: W -> half TILED [n][k] ----------------
__global__ void transpose_half_kernel(const float* __restrict__ W, __half* __restrict__ WT) {
    __shared__ float t[32][132];
    int n0 = blockIdx.x * 128, kblk = blockIdx.y, k0 = kblk * 32;
    int tid = threadIdx.x;
#pragma unroll
    for (int i = 0; i < 16; i++) {
        int lin = i * 256 + tid;
        int k = lin >> 7, n = lin & 127;
        t[k][n] = W[(size_t)(k0 + k) * 2048 + n0 + n];
    }
    __syncthreads();
    int r = tid & 127;
    int cbase = (tid >> 7) * 2;
    int sw = (r >> 1) & 3;
    __half* obase = WT + (size_t)((n0 >> 7) * 64 + kblk) * 4096 + r * 32;
#pragma unroll
    for (int cc = 0; cc < 2; cc++) {
        int c = cbase + cc;
        __half h[8];
#pragma unroll
        for (int i = 0; i < 8; i++) h[i] = __float2half_rn(t[c * 8 + i][r]);
        *(uint4*)(obase + ((c ^ sw) * 8)) = *(uint4*)h;
    }
}

// ---------------- fp16 GEMM: 8-stage bulk pipeline, barrier every 4 kts ----------------
#define GSTAGE_B 24576
#define GSTAGE_H 12288
#define NSTAGE 8
#define GEMM_SMEM (NSTAGE * GSTAGE_B + 64)

__global__ __launch_bounds__(512, 1) void gemm256_kernel(
    const __half* __restrict__ A, const __half* __restrict__ BW,
    float* __restrict__ C, __half* __restrict__ Qh, int mode)
{
    extern __shared__ __half shh[];
    uint32_t sb = smem_u32(shh);
    uint32_t mb = sb + NSTAGE * GSTAGE_B;

    int tid = threadIdx.x;
    int wid = tid >> 5, lane = tid & 31;
    int wm = wid >> 2, wn = wid & 3;
    int gq = lane >> 2, kc = lane & 3;
    int n0 = blockIdx.x * 256, m0 = blockIdx.y * 128;

    if (tid == 0) {
#pragma unroll
        for (int s = 0; s < NSTAGE; s++) MBARRIER_INIT(mb + 8 * s, 1);
    }
    __syncthreads();

    const __half* Ab = A  + (size_t)(m0 >> 7) * 64 * 4096;
    const __half* B0 = BW + (size_t)(n0 >> 7) * 64 * 4096;
    const __half* B1 = BW + (size_t)((n0 >> 7) + 1) * 64 * 4096;

    if (tid == 0) {
#pragma unroll
        for (int s = 0; s < NSTAGE; s++) {               // prefill all 8 stages
            MBARRIER_EXPECT_TX(mb + 8 * s, GSTAGE_B);
            CP_BULK(sb + s * GSTAGE_B,         Ab + (size_t)s * 4096, 8192, mb + 8 * s);
            CP_BULK(sb + s * GSTAGE_B + 8192,  B0 + (size_t)s * 4096, 8192, mb + 8 * s);
            CP_BULK(sb + s * GSTAGE_B + 16384, B1 + (size_t)s * 4096, 8192, mb + 8 * s);
        }
    }

    int laneAr = wm * 32 + (lane & 7) + (((lane >> 3) & 1) << 3);
    int cA = lane >> 4;
    int swA = (laneAr >> 1) & 3;
    uint32_t aAddr0 = sb + (uint32_t)laneAr * 64 + (uint32_t)((cA     ^ swA) << 4);
    uint32_t aAddr1 = sb + (uint32_t)laneAr * 64 + (uint32_t)(((2|cA) ^ swA) << 4);
    int laneBr = wn * 64 + ((lane >> 4) << 3) + (lane & 7);
    int cB = (lane >> 3) & 1;
    int swB = (laneBr >> 1) & 3;
    uint32_t bAddr0 = sb + 8192 + (uint32_t)laneBr * 64 + (uint32_t)((cB     ^ swB) << 4);
    uint32_t bAddr1 = sb + 8192 + (uint32_t)laneBr * 64 + (uint32_t)(((2|cB) ^ swB) << 4);

    float acc[2][8][4];
#pragma unroll
    for (int i = 0; i < 2; i++)
#pragma unroll
        for (int j = 0; j < 8; j++)
#pragma unroll
            for (int r = 0; r < 4; r++) acc[i][j][r] = 0.f;

    for (int kt = 0; kt < 64; kt += 4) {
#pragma unroll
        for (int u = 0; u < 4; u++) {
            int k = kt + u, s = k & (NSTAGE - 1);
            MBARRIER_WAIT_PARITY(mb + 8 * s, (k >> 3) & 1);
            uint32_t so = (uint32_t)s * GSTAGE_B;
#pragma unroll
            for (int t = 0; t < 2; t++) {
                uint32_t aA = (t ? aAddr1 : aAddr0) + so;
                uint32_t bA = (t ? bAddr1 : bAddr0) + so;
                uint32_t af[2][4], bf[8][2];
                LDMX4(af[0][0], af[0][1], af[0][2], af[0][3], aA);
                LDMX4(af[1][0], af[1][1], af[1][2], af[1][3], aA + 1024);
#pragma unroll
                for (int nfp = 0; nfp < 4; nfp++)
                    LDMX4(bf[2 * nfp][0], bf[2 * nfp][1], bf[2 * nfp + 1][0], bf[2 * nfp + 1][1],
                          bA + nfp * 1024);
#pragma unroll
                for (int mf = 0; mf < 2; mf++)
#pragma unroll
                    for (int nf = 0; nf < 8; nf++)
                        mma_f16_16x8x16(acc[mf][nf][0], acc[mf][nf][1],
                                        acc[mf][nf][2], acc[mf][nf][3],
                                        af[mf][0], af[mf][1], af[mf][2], af[mf][3],
                                        bf[nf][0], bf[nf][1]);
            }
        }
        __syncthreads();
        if (tid == 0 && kt + NSTAGE < 64) {
#pragma unroll
            for (int u = 0; u < 4; u++) {
                int kl = kt + NSTAGE + u, s2 = kl & (NSTAGE - 1);
                MBARRIER_EXPECT_TX(mb + 8 * s2, GSTAGE_B);
                CP_BULK(sb + s2 * GSTAGE_B,         Ab + (size_t)kl * 4096, 8192, mb + 8 * s2);
                CP_BULK(sb + s2 * GSTAGE_B + 8192,  B0 + (size_t)kl * 4096, 8192, mb + 8 * s2);
                CP_BULK(sb + s2 * GSTAGE_B + 16384, B1 + (size_t)kl * 4096, 8192, mb + 8 * s2);
            }
        }
    }

    if (mode == 0) {
#pragma unroll
        for (int mf = 0; mf < 2; mf++) {
            int r0 = m0 + wm * 32 + mf * 16 + gq;
#pragma unroll
            for (int nf = 0; nf < 8; nf++) {
                int col = n0 + wn * 64 + nf * 8 + kc * 2;
                *(float2*)&C[(size_t)r0 * 2048 + col]       = make_float2(acc[mf][nf][0], acc[mf][nf][1]);
                *(float2*)&C[(size_t)(r0 + 8) * 2048 + col] = make_float2(acc[mf][nf][2], acc[mf][nf][3]);
            }
        }
    } else {
#pragma unroll
        for (int mf = 0; mf < 2; mf++) {
            int r0 = m0 + wm * 32 + mf * 16 + gq;
            int q = r0 & 127, mblk = r0 >> 7;
            int sw = (q & 7) << 2;
#pragma unroll
            for (int nf = 0; nf < 8; nf++) {
                int col = n0 + wn * 64 + nf * 8 + kc * 2;
                int head = col >> 7, d = col & 127;
                int phys = (d >> 1) ^ sw;
                size_t base = ((size_t)(mblk * 16 + head) * 128 + q) * 128 + phys * 2;
                *(__half2*)(Qh + base)        = __floats2half2_rn(acc[mf][nf][0], acc[mf][nf][1]);
                *(__half2*)(Qh + base + 1024) = __floats2half2_rn(acc[mf][nf][2], acc[mf][nf][3]);
            }
        }
    }
}

// ---------------- sparse K/V projection -> half attn images ----------------
#define KVSTAGE_B 16384
#define KVSTAGE_H 8192
#define KV_SMEM (4 * KVSTAGE_B + 128 * 4)

__global__ __launch_bounds__(256, 1) void sparse_kv_mma_kernel(
    const int* __restrict__ anchors)
{
    extern __shared__ __half shh[];
    int* tok = (int*)(shh + 4 * KVSTAGE_H);

    int tid = threadIdx.x;
    int bh = blockIdx.x;
    int h = bh & 15, b = bh >> 4;
    int vsel = blockIdx.y;
    const __half* Bb = (vsel ? g_wvt : g_wkt) + (size_t)h * 64 * 4096;
    __half* img = (vsel ? g_vh : g_kh) + (size_t)bh * 16384;

    if (tid < 128) {
        int ti = tid >> 4;
        int tile = (ti == 7) ? 255 : anchors[(bh << 3) + ti];
        tok[tid] = tile * 16 + (tid & 15);
    }
    __syncthreads();

    int wid = tid >> 5, lane = tid & 31;
    int wm = wid >> 2, wn = wid & 3;
    int gq = lane >> 2, kc = lane & 3;

    uint32_t sb = smem_u32(shh);

    uint32_t aReg = vsel ? 8192u : 0u;
    uint32_t bReg = vsel ? 0u : 8192u;

    int laneAr = wm * 64 + (lane & 7) + (((lane >> 3) & 1) << 3);
    int cA = lane >> 4;
    int swA = (laneAr >> 1) & 3;
    uint32_t aAddr0 = sb + aReg + (uint32_t)laneAr * 64 + (uint32_t)((cA     ^ swA) << 4);
    uint32_t aAddr1 = sb + aReg + (uint32_t)laneAr * 64 + (uint32_t)(((2|cA) ^ swA) << 4);
    int laneBr = wn * 32 + ((lane >> 4) << 3) + (lane & 7);
    int cB = (lane >> 3) & 1;
    int swB = (laneBr >> 1) & 3;
    uint32_t bAddr0 = sb + bReg + (uint32_t)laneBr * 64 + (uint32_t)((cB     ^ swB) << 4);
    uint32_t bAddr1 = sb + bReg + (uint32_t)laneBr * 64 + (uint32_t)(((2|cB) ^ swB) << 4);

    float acc[4][4][4];
#pragma unroll
    for (int i = 0; i < 4; i++)
#pragma unroll
        for (int j = 0; j < 4; j++)
#pragma unroll
            for (int r = 0; r < 4; r++) acc[i][j][r] = 0.f;

#pragma unroll
    for (int s = 0; s < 3; s++) {
        uint32_t so = sb + s * KVSTAGE_B;
#pragma unroll
        for (int i = 0; i < 2; i++) {
            int cidx = i * 256 + tid;
            int rs = cidx >> 2, c = cidx & 3;
            int grow = b * SS + tok[rs];
            const __half* srcA = g_xh + (size_t)((grow >> 7) * 64 + s) * 4096
                               + (grow & 127) * 32 + ((c ^ ((grow >> 1) & 3)) * 8);
            CP_ASYNC16(so + (uint32_t)(rs * 64 + (c ^ ((rs >> 1) & 3)) * 16), srcA);
            const __half* srcB = Bb + (size_t)s * 4096 + rs * 32 + ((c ^ ((rs >> 1) & 3)) * 8);
            CP_ASYNC16(so + 8192 + (uint32_t)(rs * 64 + (c ^ ((rs >> 1) & 3)) * 16), srcB);
        }
        CP_COMMIT();
    }

    for (int kt = 0; kt < 64; kt++) {
        CP_WAIT(2);
        __syncthreads();
        if (kt + 3 < 64) {
            int sl = kt + 3;
            uint32_t so = sb + (uint32_t)(sl & 3) * KVSTAGE_B;
#pragma unroll
            for (int i = 0; i < 2; i++) {
                int cidx = i * 256 + tid;
                int rs = cidx >> 2, c = cidx & 3;
                int grow = b * SS + tok[rs];
                const __half* srcA = g_xh + (size_t)((grow >> 7) * 64 + sl) * 4096
                                   + (grow & 127) * 32 + ((c ^ ((grow >> 1) & 3)) * 8);
                CP_ASYNC16(so + (uint32_t)(rs * 64 + (c ^ ((rs >> 1) & 3)) * 16), srcA);
                const __half* srcB = Bb + (size_t)sl * 4096 + rs * 32 + ((c ^ ((rs >> 1) & 3)) * 8);
                CP_ASYNC16(so + 8192 + (uint32_t)(rs * 64 + (c ^ ((rs >> 1) & 3)) * 16), srcB);
            }
        }
        CP_COMMIT();

        uint32_t so = (uint32_t)(kt & 3) * KVSTAGE_B;
#pragma unroll
        for (int t = 0; t < 2; t++) {
            uint32_t aA = (t ? aAddr1 : aAddr0) + so;
            uint32_t bA = (t ? bAddr1 : bAddr0) + so;
            uint32_t af[4][4], bf[4][2];
#pragma unroll
            for (int mf = 0; mf < 4; mf++)
                LDMX4(af[mf][0], af[mf][1], af[mf][2], af[mf][3], aA + mf * 1024);
#pragma unroll
            for (int nfp = 0; nfp < 2; nfp++)
                LDMX4(bf[2 * nfp][0], bf[2 * nfp][1], bf[2 * nfp + 1][0], bf[2 * nfp + 1][1],
                      bA + nfp * 1024);
#pragma unroll
            for (int mf = 0; mf < 4; mf++)
#pragma unroll
                for (int nf = 0; nf < 4; nf++)
                    mma_f16_16x8x16(acc[mf][nf][0], acc[mf][nf][1],
                                    acc[mf][nf][2], acc[mf][nf][3],
                                    af[mf][0], af[mf][1], af[mf][2], af[mf][3],
                                    bf[nf][0], bf[nf][1]);
        }
    }

    {
        int sw = gq << 2;
#pragma unroll
        for (int mf = 0; mf < 4; mf++) {
            int r0 = wm * 64 + mf * 16 + gq;
            __half* row0 = img + r0 * 128;
            __half* row1 = img + (r0 + 8) * 128;
#pragma unroll
            for (int nf = 0; nf < 4; nf++) {
                int g = wn * 16 + nf * 4 + kc;
                int phys = g ^ sw;
                *(__half2*)(row0 + phys * 2) = __floats2half2_rn(acc[mf][nf][0], acc[mf][nf][1]);
                *(__half2*)(row1 + phys * 2) = __floats2half2_rn(acc[mf][nf][2], acc[mf][nf][3]);
            }
        }
    }
}

// ---------------- attention: all operands via cp.async.bulk ----------------
#define ATTN_TOK_OFF (3 * 32768)
#define ATTN_SMEM (ATTN_TOK_OFF + 512 + 16)

__global__ __launch_bounds__(256) void attn_mma_kernel(
    const int* __restrict__ anchors, __half* __restrict__ attout, int bhbase)
{
    extern __shared__ char smraw[];
    __half* QPh = ((__half*)smraw) + 2 * 16384;
    int*    tok = (int*)(smraw + ATTN_TOK_OFF);
    uint32_t sbb = smem_u32(smraw);
    uint32_t mb = sbb + ATTN_TOK_OFF + 512;

    int tid = threadIdx.x;
    int bh = bhbase + blockIdx.y;
    int b = bh >> 4, h = bh & 15;
    int q0 = blockIdx.x * 128;
    int wid = tid >> 5, lane = tid & 31;
    int gq = lane >> 2, kc = lane & 3;

    if (tid == 0) MBARRIER_INIT(mb, 1);
    if (tid < 128) {
        int ti = tid >> 4;
        int tile = (ti == 7) ? 255 : anchors[(bh << 3) + ti];
        tok[tid] = tile * 16 + (tid & 15);
    }
    __syncthreads();

    if (tid == 0) {
        const __half* qsrc = g_qh + ((size_t)((b * 32 + (q0 >> 7)) * 16 + h) * 16384);
        MBARRIER_EXPECT_TX(mb, 3 * 32768);
        CP_BULK(sbb,             g_kh + (size_t)bh * 16384, 32768, mb);
        CP_BULK(sbb + 32768,     g_vh + (size_t)bh * 16384, 32768, mb);
        CP_BULK(sbb + 2 * 32768, qsrc,                      32768, mb);
    }
    MBARRIER_WAIT_PARITY(mb, 0);

    int laneAr = wid * 16 + (lane & 7) + (((lane >> 3) & 1) << 3);
    int cA = lane >> 4;
    int laneBr = ((lane >> 4) << 3) + (lane & 7);
    int cB = (lane >> 3) & 1;
    uint32_t qBase = sbb + 2 * 32768 + (uint32_t)laneAr * 256;
    uint32_t kBase = sbb + (uint32_t)laneBr * 256;
    uint32_t vBase = sbb + 32768 + (uint32_t)laneBr * 256;
    int swAa = laneAr & 7, swBa = laneBr & 7;

    int r = wid * 16 + gq;

    float acc[16][4];
#pragma unroll
    for (int nf = 0; nf < 16; nf++)
#pragma unroll
        for (int z = 0; z < 4; z++) acc[nf][z] = 0.f;
#pragma unroll
    for (int t = 0; t < 8; t++) {
        uint32_t af[4], bf[16][2];
        LDMX4(af[0], af[1], af[2], af[3], qBase + (uint32_t)(((2 * t + cA) ^ swAa) << 4));
#pragma unroll
        for (int nfp = 0; nfp < 8; nfp++)
            LDMX4(bf[2 * nfp][0], bf[2 * nfp][1], bf[2 * nfp + 1][0], bf[2 * nfp + 1][1],
                  kBase + nfp * 4096 + (uint32_t)(((2 * t + cB) ^ swBa) << 4));
#pragma unroll
        for (int nf = 0; nf < 16; nf++)
            mma_f16_16x8x16(acc[nf][0], acc[nf][1], acc[nf][2], acc[nf][3],
                            af[0], af[1], af[2], af[3], bf[nf][0], bf[nf][1]);
    }

    {
        const float scale = 0.0883883476483184f;
        int qpos0 = q0 + r, qpos1 = qpos0 + 8;
        float mx0 = -3.0e38f, mx1 = -3.0e38f;
#pragma unroll
        for (int nf = 0; nf < 16; nf++)
#pragma unroll
            for (int j = 0; j < 2; j++) {
                int tcol = tok[nf * 8 + kc * 2 + j];
                float v0 = acc[nf][j] * scale;
                float v1 = acc[nf][2 + j] * scale;
                if (tcol > qpos0) v0 = -1e10f;
                if (tcol > qpos1) v1 = -1e10f;
                acc[nf][j] = v0; acc[nf][2 + j] = v1;
                mx0 = fmaxf(mx0, v0); mx1 = fmaxf(mx1, v1);
            }
        mx0 = fmaxf(mx0, __shfl_xor_sync(0xffffffffu, mx0, 1));
        mx0 = fmaxf(mx0, __shfl_xor_sync(0xffffffffu, mx0, 2));
        mx1 = fmaxf(mx1, __shfl_xor_sync(0xffffffffu, mx1, 1));
        mx1 = fmaxf(mx1, __shfl_xor_sync(0xffffffffu, mx1, 2));
        float s0 = 0.f, s1 = 0.f;
#pragma unroll
        for (int nf = 0; nf < 16; nf++)
#pragma unroll
            for (int j = 0; j < 2; j++) {
                float e0 = __expf(acc[nf][j] - mx0);
                float e1 = __expf(acc[nf][2 + j] - mx1);
                acc[nf][j] = e0; acc[nf][2 + j] = e1;
                s0 += e0; s1 += e1;
            }
        s0 += __shfl_xor_sync(0xffffffffu, s0, 1);
        s0 += __shfl_xor_sync(0xffffffffu, s0, 2);
        s1 += __shfl_xor_sync(0xffffffffu, s1, 1);
        s1 += __shfl_xor_sync(0xffffffffu, s1, 2);
        float inv0 = 1.f / s0, inv1 = 1.f / s1;
        int sw = (r & 7) << 2;
#pragma unroll
        for (int nf = 0; nf < 16; nf++) {
            int g = nf * 4 + kc;
            int phys = g ^ sw;
            *(__half2*)(QPh + r * 128 + phys * 2) =
                __floats2half2_rn(acc[nf][0] * inv0, acc[nf][1] * inv0);
            *(__half2*)(QPh + (r + 8) * 128 + phys * 2) =
                __floats2half2_rn(acc[nf][2] * inv1, acc[nf][3] * inv1);
        }
        __syncwarp();
    }

    float acc2[16][4];
#pragma unroll
    for (int nf = 0; nf < 16; nf++)
#pragma unroll
        for (int z = 0; z < 4; z++) acc2[nf][z] = 0.f;
#pragma unroll
    for (int t = 0; t < 8; t++) {
        uint32_t af[4], bf[16][2];
        LDMX4(af[0], af[1], af[2], af[3], qBase + (uint32_t)(((2 * t + cA) ^ swAa) << 4));
#pragma unroll
        for (int nfp = 0; nfp < 8; nfp++)
            LDMX4(bf[2 * nfp][0], bf[2 * nfp][1], bf[2 * nfp + 1][0], bf[2 * nfp + 1][1],
                  vBase + nfp * 4096 + (uint32_t)(((2 * t + cB) ^ swBa) << 4));
#pragma unroll
        for (int nf = 0; nf < 16; nf++)
            mma_f16_16x8x16(acc2[nf][0], acc2[nf][1], acc2[nf][2], acc2[nf][3],
                            af[0], af[1], af[2], af[3], bf[nf][0], bf[nf][1]);
    }

    {
        int mblk = (b * SS + q0) >> 7;
        __half* abase = attout + (size_t)mblk * 64 * 4096;
        int sw = ((r >> 1) & 3) << 2;
#pragma unroll
        for (int nf = 0; nf < 16; nf++) {
            int col = h * HDIM + nf * 8 + kc * 2;
            int kblk = col >> 5, kcol = col & 31;
            int phys = (kcol >> 1) ^ sw;
            *(__half2*)(abase + (size_t)kblk * 4096 + r * 32 + phys * 2) =
                __floats2half2_rn(acc2[nf][0], acc2[nf][1]);
            *(__half2*)(abase + (size_t)kblk * 4096 + (r + 8) * 32 + phys * 2) =
                __floats2half2_rn(acc2[nf][2], acc2[nf][3]);
        }
    }
}

// ---------------- streams/events ----------------
static cudaStream_t g_s1a, g_s1b, g_s2, g_s3;
static cudaEvent_t g_estart, g_erhb[4], g_ewq, g_ewo, g_ekv, g_e1[4], g_e2[4], g_e3;
static bool g_streams_ok = [](){
    cudaStreamCreateWithFlags(&g_s1a, cudaStreamNonBlocking);
    cudaStreamCreateWithFlags(&g_s1b, cudaStreamNonBlocking);
    cudaStreamCreateWithFlags(&g_s2,  cudaStreamNonBlocking);
    cudaStreamCreateWithFlags(&g_s3,  cudaStreamNonBlocking);
    cudaEventCreateWithFlags(&g_estart, cudaEventDisableTiming);
    cudaEventCreateWithFlags(&g_ewq, cudaEventDisableTiming);
    cudaEventCreateWithFlags(&g_ewo, cudaEventDisableTiming);
    cudaEventCreateWithFlags(&g_ekv, cudaEventDisableTiming);
    cudaEventCreateWithFlags(&g_e3,  cudaEventDisableTiming);
    for (int i = 0; i < 4; i++) {
        cudaEventCreateWithFlags(&g_erhb[i], cudaEventDisableTiming);
        cudaEventCreateWithFlags(&g_e1[i], cudaEventDisableTiming);
        cudaEventCreateWithFlags(&g_e2[i], cudaEventDisableTiming);
    }
    return true;
}();

// ---------------- launch ----------------
extern "C" void kernel_launch(void* const* d_in, const int* in_sizes, int n_in,
                              void* d_out, int out_size)
{
    const float* x       = (const float*)d_in[0];
    const int*   anchors = (const int*)  d_in[1];
    const float* Wq      = (const float*)d_in[2];
    const float* Wk      = (const float*)d_in[3];
    const float* Wv      = (const float*)d_in[4];
    const float* Wo      = (const float*)d_in[5];
    float* out = (float*)d_out;

    __half *qhp, *attp, *xhp, *wqtp, *wotp, *wktp, *wvtp;
    cudaGetSymbolAddress((void**)&qhp,  g_qh);
    cudaGetSymbolAddress((void**)&attp, g_att);
    cudaGetSymbolAddress((void**)&xhp,  g_xh);
    cudaGetSymbolAddress((void**)&wqtp, g_wqt);
    cudaGetSymbolAddress((void**)&wotp, g_wot);
    cudaGetSymbolAddress((void**)&wktp, g_wkt);
    cudaGetSymbolAddress((void**)&wvtp, g_wvt);

    cudaFuncSetAttribute(attn_mma_kernel, cudaFuncAttributeMaxDynamicSharedMemorySize, ATTN_SMEM);
    cudaFuncSetAttribute(gemm256_kernel, cudaFuncAttributeMaxDynamicSharedMemorySize, GEMM_SMEM);
    cudaFuncSetAttribute(sparse_kv_mma_kernel, cudaFuncAttributeMaxDynamicSharedMemorySize, KV_SMEM);

    const size_t ABLK = (size_t)SS * DD;
    const size_t X4BLK = (size_t)SS * DD / 4;

    // FORK root
    cudaEventRecord(g_estart, 0);

    for (int b = 0; b < 4; b++) {
        round_half_kernel<<<(SS * DD / 4) / 256, 256>>>(
            (const float4*)(x + b * 4 * X4BLK), xhp + b * ABLK);
        cudaEventRecord(g_erhb[b], 0);
    }

    cudaStreamWaitEvent(g_s2, g_estart, 0);
    transpose_half_kernel<<<dim3(16, 64), 256, 0, g_s2>>>(Wq, wqtp);
    cudaEventRecord(g_ewq, g_s2);
    transpose_half_kernel<<<dim3(16, 64), 256, 0, g_s2>>>(Wk, wktp);
    transpose_half_kernel<<<dim3(16, 64), 256, 0, g_s2>>>(Wv, wvtp);
    transpose_half_kernel<<<dim3(16, 64), 256, 0, g_s2>>>(Wo, wotp);
    cudaEventRecord(g_ewo, g_s2);
    cudaStreamWaitEvent(g_s2, g_erhb[3], 0);
    sparse_kv_mma_kernel<<<dim3(64, 2), 256, KV_SMEM, g_s2>>>(anchors);
    cudaEventRecord(g_ekv, g_s2);

    for (int b = 0; b < 4; b++) {
        cudaStream_t st = (b & 1) ? g_s1b : g_s1a;
        cudaStreamWaitEvent(st, g_erhb[b], 0);
        cudaStreamWaitEvent(st, g_ewq, 0);
        gemm256_kernel<<<dim3(8, 32), 512, GEMM_SMEM, st>>>(
            xhp + b * ABLK, wqtp, nullptr, qhp + b * ABLK, 1);
        cudaEventRecord(g_e1[b], st);
    }
    for (int b = 0; b < 4; b++) {
        cudaStreamWaitEvent(g_s2, g_e1[b], 0);
        attn_mma_kernel<<<dim3(32, 16), 256, ATTN_SMEM, g_s2>>>(anchors, attp, b * 16);
        cudaEventRecord(g_e2[b], g_s2);
    }
    cudaStreamWaitEvent(0, g_ewo, 0);
    cudaStreamWaitEvent(g_s3, g_ewo, 0);
    for (int b = 0; b < 4; b++) {
        cudaStream_t st = (b & 1) ? g_s3 : (cudaStream_t)0;
        cudaStreamWaitEvent(st, g_e2[b], 0);
        gemm256_kernel<<<dim3(8, 32), 512, GEMM_SMEM, st>>>(
            attp + b * ABLK, wotp, out + b * ABLK, nullptr, 0);
    }
    cudaEventRecord(g_e3, g_s3);
    cudaStreamWaitEvent(0, g_e3, 0);
}